// round 1
// baseline (speedup 1.0000x reference)
#include <cuda_runtime.h>
#include <math.h>

// ---------------- problem constants ----------------
#define DD   512          // dynamic dim
#define BB   512          // batch
#define TT   256          // time steps
#define UDIM 32
#define NOBS 50
#define NTAYLOR 8
#define NSQUARE 7         // Y = A*dt / 2^7

// ---------------- device scratch (no allocs allowed) ----------------
__device__ float g_Y [DD*DD];
__device__ float g_E [DD*DD];
__device__ float g_P [DD*DD];
__device__ float g_T [DD*DD];
__device__ float g_T2[DD*DD];
__device__ float g_Bb[DD*UDIM];
__device__ float g_Ds[NOBS*UDIM];

// ---------------- setup kernels ----------------

// Y = (skew(params) - diag(softplus(gamma))) * dt / 2^NSQUARE
__global__ void build_Y_kernel(const float* __restrict__ skew,
                               const float* __restrict__ gamma,
                               const float* __restrict__ dtp,
                               float* __restrict__ Y)
{
    int idx = blockIdx.x * 256 + threadIdx.x;
    if (idx >= DD*DD) return;
    int i = idx >> 9;
    int j = idx & (DD-1);
    float v;
    if (i < j) {
        v =  skew[i*(DD-1) - (i*(i-1))/2 + (j - i - 1)];
    } else if (i > j) {
        v = -skew[j*(DD-1) - (j*(j-1))/2 + (i - j - 1)];
    } else {
        float g = gamma[i];
        v = -(fmaxf(g, 0.f) + log1pf(expf(-fabsf(g))));   // -softplus(g)
    }
    Y[idx] = v * (dtp[0] * (1.0f / (float)(1 << NSQUARE)));
}

__global__ void init_EPT(float* __restrict__ E, float* __restrict__ P, float* __restrict__ Tm)
{
    int idx = blockIdx.x * 256 + threadIdx.x;
    if (idx >= DD*DD) return;
    int i = idx >> 9, j = idx & (DD-1);
    float v = (i == j) ? 1.f : 0.f;
    E[idx] = v; P[idx] = v; Tm[idx] = v;
}

// after T2 = (T @ Y) / k :  T = T2 ; E += T2 ; P += T2/(k+1)
__global__ void taylor_accum(float* __restrict__ E, float* __restrict__ P,
                             float* __restrict__ Tm, const float* __restrict__ T2,
                             float invk1)
{
    int idx = blockIdx.x * 256 + threadIdx.x;
    if (idx >= DD*DD) return;
    float t = T2[idx];
    Tm[idx] = t;
    E[idx] += t;
    P[idx] += t * invk1;
}

// P = T2 + 0.5*P   (T2 already holds 0.5*E@P)
__global__ void phi_update(float* __restrict__ P, const float* __restrict__ T2)
{
    int idx = blockIdx.x * 256 + threadIdx.x;
    if (idx >= DD*DD) return;
    P[idx] = T2[idx] + 0.5f * P[idx];
}

__global__ void copy_kernel(float* __restrict__ dst, const float* __restrict__ src, int n)
{
    int idx = blockIdx.x * 256 + threadIdx.x;
    if (idx < n) dst[idx] = src[idx];
}

__global__ void scale_by_dt(float* __restrict__ x, const float* __restrict__ dtp, int n)
{
    int idx = blockIdx.x * 256 + threadIdx.x;
    if (idx < n) x[idx] *= dtp[0];
}

__global__ void build_Ds(float* __restrict__ Ds, const float* __restrict__ Dm,
                         const float* __restrict__ dtp)
{
    int idx = blockIdx.x * 256 + threadIdx.x;
    if (idx < NOBS*UDIM) Ds[idx] = Dm[idx] * dtp[0];
}

// Generic row-major NN GEMM: C = alpha * A(MxK) @ B(KxN).  M,N,K multiples of 32.
__global__ void gemm_nn(float* __restrict__ C, const float* __restrict__ A,
                        const float* __restrict__ Bm, int M, int N, int K, float alpha)
{
    __shared__ float As[32][33];
    __shared__ float Bs[32][33];
    int tx = threadIdx.x & 15;
    int ty = threadIdx.x >> 4;
    int j0 = blockIdx.x * 32;
    int i0 = blockIdx.y * 32;
    float acc00 = 0.f, acc01 = 0.f, acc10 = 0.f, acc11 = 0.f;
    for (int k0 = 0; k0 < K; k0 += 32) {
        for (int u = threadIdx.x; u < 32*32; u += 256) {
            int r = u >> 5, c = u & 31;
            As[r][c] = A[(size_t)(i0 + r)*K + k0 + c];
            Bs[r][c] = Bm[(size_t)(k0 + r)*N + j0 + c];
        }
        __syncthreads();
        #pragma unroll
        for (int k = 0; k < 32; k++) {
            float a0 = As[ty*2+0][k];
            float a1 = As[ty*2+1][k];
            float b0 = Bs[k][tx*2+0];
            float b1 = Bs[k][tx*2+1];
            acc00 += a0*b0; acc01 += a0*b1;
            acc10 += a1*b0; acc11 += a1*b1;
        }
        __syncthreads();
    }
    C[(size_t)(i0+ty*2+0)*N + j0+tx*2+0] = alpha*acc00;
    C[(size_t)(i0+ty*2+0)*N + j0+tx*2+1] = alpha*acc01;
    C[(size_t)(i0+ty*2+1)*N + j0+tx*2+0] = alpha*acc10;
    C[(size_t)(i0+ty*2+1)*N + j0+tx*2+1] = alpha*acc11;
}

// ---------------- scan step kernel ----------------
// Z-blocks (blk < nZblocks): Zout[b,j] = sum_k Zprev[b,k]*Abar[j,k] + sum_m Ut[b,m]*Bbar[j,m]
// Y-blocks               : Yout[b,o] = sum_k Zprev[b,k]*C[o,k]    + sum_m Utm1[b,m]*Ds[o,m]
// (Ds = dt*D precomputed; Bbar pre-scaled by dt)
// BM=64 (batch) x BN=32 (out col), BK=16, 128 threads, 4x4 microtiles, double-buffered smem.

#define BM 64
#define BN 32
#define BK 16

__device__ __forceinline__ void load_tile_regs(
    const float* __restrict__ Aop, int ldA,
    const float* __restrict__ Bop, int ldB,
    int row0, int col0, int nB, int k0, int tid,
    float4& a0, float4& a1, float4& b0)
{
    {
        int b  = tid >> 2;
        int kg = tid & 3;
        a0 = *reinterpret_cast<const float4*>(Aop + (size_t)(row0 + b)*ldA + k0 + kg*4);
        int unit = tid + 128;
        b  = unit >> 2;
        kg = unit & 3;
        a1 = *reinterpret_cast<const float4*>(Aop + (size_t)(row0 + b)*ldA + k0 + kg*4);
    }
    {
        int j  = tid >> 2;
        int kg = tid & 3;
        if (col0 + j < nB)
            b0 = *reinterpret_cast<const float4*>(Bop + (size_t)(col0 + j)*ldB + k0 + kg*4);
        else
            b0 = make_float4(0.f, 0.f, 0.f, 0.f);
    }
}

__device__ __forceinline__ void store_tile_smem(
    float As[BK][BM+4], float Bs[BK][BN], int tid,
    float4 a0, float4 a1, float4 b0)
{
    int b  = tid >> 2;
    int kg = tid & 3;
    As[kg*4+0][b] = a0.x; As[kg*4+1][b] = a0.y;
    As[kg*4+2][b] = a0.z; As[kg*4+3][b] = a0.w;
    int unit = tid + 128;
    b  = unit >> 2;
    kg = unit & 3;
    As[kg*4+0][b] = a1.x; As[kg*4+1][b] = a1.y;
    As[kg*4+2][b] = a1.z; As[kg*4+3][b] = a1.w;
    int j = tid >> 2;
    kg = tid & 3;
    Bs[kg*4+0][j] = b0.x; Bs[kg*4+1][j] = b0.y;
    Bs[kg*4+2][j] = b0.z; Bs[kg*4+3][j] = b0.w;
}

__global__ void __launch_bounds__(128) step_kernel(
    const float* __restrict__ Zprev, const float* __restrict__ Ut,
    const float* __restrict__ Utm1,  float* __restrict__ Zout,
    float* __restrict__ Yout,        const float* __restrict__ Abar,
    const float* __restrict__ Bbar,  const float* __restrict__ Cm,
    const float* __restrict__ Ds,    int nZblocks, int writeY)
{
    __shared__ float As[2][BK][BM+4];
    __shared__ float Bs[2][BK][BN];

    int blk = blockIdx.x;
    const float *aop1, *bop1, *aop2, *bop2;
    int lda1, ldb1, lda2, ldb2;
    int row0, col0, nB, ncols, ldo;
    float* outp;

    if (blk < nZblocks) {
        int rb = blk & 7, cb = blk >> 3;           // 8 x 16
        row0 = rb*BM; col0 = cb*BN;
        aop1 = Zprev; lda1 = DD;   bop1 = Abar; ldb1 = DD;
        aop2 = Ut;    lda2 = UDIM; bop2 = Bbar; ldb2 = UDIM;
        nB = DD; ncols = DD; outp = Zout; ldo = DD;
    } else {
        if (!writeY) return;
        int local = blk - nZblocks;
        int rb = local & 7, cb = local >> 3;       // 8 x 2
        row0 = rb*BM; col0 = cb*BN;
        aop1 = Zprev; lda1 = DD;   bop1 = Cm; ldb1 = DD;
        aop2 = Utm1;  lda2 = UDIM; bop2 = Ds; ldb2 = UDIM;
        nB = NOBS; ncols = NOBS; outp = Yout; ldo = NOBS;
    }

    const int NT1 = DD / BK;        // 32 tiles over K=512
    const int NT2 = UDIM / BK;      // 2 tiles over K=32
    const int ntiles = NT1 + NT2;   // 34

    int tid = threadIdx.x;
    int bx = tid & 7;    // col group (4 cols each)
    int by = tid >> 3;   // row group (4 rows each)

    float acc[4][4];
    #pragma unroll
    for (int i = 0; i < 4; i++)
        #pragma unroll
        for (int j = 0; j < 4; j++) acc[i][j] = 0.f;

    float4 pa0, pa1, pb0;
    load_tile_regs(aop1, lda1, bop1, ldb1, row0, col0, nB, 0, tid, pa0, pa1, pb0);
    store_tile_smem(As[0], Bs[0], tid, pa0, pa1, pb0);
    __syncthreads();

    for (int tt = 0; tt < ntiles; tt++) {
        int cur = tt & 1;
        if (tt + 1 < ntiles) {
            int nt = tt + 1;
            int phase = (nt >= NT1) ? 1 : 0;
            int k0 = phase ? (nt - NT1)*BK : nt*BK;
            const float* Aop = phase ? aop2 : aop1;
            const float* Bop = phase ? bop2 : bop1;
            int ldA = phase ? lda2 : lda1;
            int ldB = phase ? ldb2 : ldb1;
            load_tile_regs(Aop, ldA, Bop, ldB, row0, col0, nB, k0, tid, pa0, pa1, pb0);
        }
        #pragma unroll
        for (int k = 0; k < BK; k++) {
            float4 a = *reinterpret_cast<const float4*>(&As[cur][k][by*4]);
            float4 b = *reinterpret_cast<const float4*>(&Bs[cur][k][bx*4]);
            acc[0][0] += a.x*b.x; acc[0][1] += a.x*b.y; acc[0][2] += a.x*b.z; acc[0][3] += a.x*b.w;
            acc[1][0] += a.y*b.x; acc[1][1] += a.y*b.y; acc[1][2] += a.y*b.z; acc[1][3] += a.y*b.w;
            acc[2][0] += a.z*b.x; acc[2][1] += a.z*b.y; acc[2][2] += a.z*b.z; acc[2][3] += a.z*b.w;
            acc[3][0] += a.w*b.x; acc[3][1] += a.w*b.y; acc[3][2] += a.w*b.z; acc[3][3] += a.w*b.w;
        }
        if (tt + 1 < ntiles)
            store_tile_smem(As[(tt+1)&1], Bs[(tt+1)&1], tid, pa0, pa1, pb0);
        __syncthreads();
    }

    #pragma unroll
    for (int i = 0; i < 4; i++) {
        int r = row0 + by*4 + i;
        #pragma unroll
        for (int j = 0; j < 4; j++) {
            int c = col0 + bx*4 + j;
            if (c < ncols) outp[(size_t)r*ldo + c] = acc[i][j];
        }
    }
}

// ---------------- host orchestration (graph-capturable) ----------------
extern "C" void kernel_launch(void* const* d_in, const int* in_sizes, int n_in,
                              void* d_out, int out_size)
{
    const float* z_dyn = (const float*)d_in[0];
    // d_in[1] = z_static (unused by reference)
    const float* dtp   = (const float*)d_in[2];
    const float* U     = (const float*)d_in[3];
    const float* skew  = (const float*)d_in[4];
    const float* gamma = (const float*)d_in[5];
    const float* B_ct  = (const float*)d_in[6];
    const float* Cm    = (const float*)d_in[7];
    const float* Dm    = (const float*)d_in[8];

    float *Y_, *E_, *P_, *T_, *T2_, *Bb_, *Ds_;
    cudaGetSymbolAddress((void**)&Y_,  g_Y);
    cudaGetSymbolAddress((void**)&E_,  g_E);
    cudaGetSymbolAddress((void**)&P_,  g_P);
    cudaGetSymbolAddress((void**)&T_,  g_T);
    cudaGetSymbolAddress((void**)&T2_, g_T2);
    cudaGetSymbolAddress((void**)&Bb_, g_Bb);
    cudaGetSymbolAddress((void**)&Ds_, g_Ds);

    const int n2 = DD*DD;
    const int g2 = (n2 + 255) / 256;
    dim3 ggemm(DD/32, DD/32);

    // --- setup: Y = A*dt/2^s ; E = exp(Y), P = phi1(Y) via Taylor deg 8 ---
    build_Y_kernel<<<g2, 256>>>(skew, gamma, dtp, Y_);
    init_EPT<<<g2, 256>>>(E_, P_, T_);
    for (int k = 1; k <= NTAYLOR; k++) {
        gemm_nn<<<ggemm, 256>>>(T2_, T_, Y_, DD, DD, DD, 1.0f/(float)k);
        taylor_accum<<<g2, 256>>>(E_, P_, T_, T2_, 1.0f/(float)(k+1));
    }
    // --- doubling: phi1(2Y) = 0.5*(E+I)*P ; E <- E^2 ---
    for (int s = 0; s < NSQUARE; s++) {
        gemm_nn<<<ggemm, 256>>>(T2_, E_, P_, DD, DD, DD, 0.5f);
        phi_update<<<g2, 256>>>(P_, T2_);
        gemm_nn<<<ggemm, 256>>>(T_, E_, E_, DD, DD, DD, 1.0f);
        copy_kernel<<<g2, 256>>>(E_, T_, n2);
    }
    // --- B_bar = dt * P @ B_ct ;  Ds = dt * D ---
    gemm_nn<<<dim3(UDIM/32, DD/32), 256>>>(Bb_, P_, B_ct, DD, UDIM, DD, 1.0f);
    scale_by_dt<<<(DD*UDIM + 255)/256, 256>>>(Bb_, dtp, DD*UDIM);
    build_Ds<<<(NOBS*UDIM + 255)/256, 256>>>(Ds_, Dm, dtp);

    // --- scan ---
    float* Zo = (float*)d_out;
    float* Yo = (float*)d_out + (size_t)TT*BB*DD;
    const int ZB = (BB/BM) * (DD/BN);   // 8*16 = 128 Z-blocks
    const int YB = (BB/BM) * 2;         // 8*2  = 16 Y-blocks

    for (int t = 0; t < TT; t++) {
        const float* Zp   = (t == 0) ? z_dyn : Zo + (size_t)(t-1)*BB*DD;
        const float* ut   = U + (size_t)t*BB*UDIM;
        const float* utm1 = (t == 0) ? ut : U + (size_t)(t-1)*BB*UDIM;
        float* yout       = (t == 0) ? Yo : Yo + (size_t)(t-1)*BB*NOBS;
        step_kernel<<<ZB + YB, 128>>>(Zp, ut, utm1,
                                      Zo + (size_t)t*BB*DD, yout,
                                      E_, Bb_, Cm, Ds_, ZB, (t > 0) ? 1 : 0);
    }
    // final Y[T-1]
    step_kernel<<<YB, 128>>>(Zo + (size_t)(TT-1)*BB*DD, U,
                             U + (size_t)(TT-1)*BB*UDIM,
                             Zo, Yo + (size_t)(TT-1)*BB*NOBS,
                             E_, Bb_, Cm, Ds_, 0, 1);
}

// round 2
// speedup vs baseline: 1.0010x; 1.0010x over previous
#include <cuda_runtime.h>
#include <math.h>

// ---------------- problem constants ----------------
#define DD   512          // dynamic dim
#define BB   512          // batch
#define TT   256          // time steps
#define UDIM 32
#define NOBS 50
#define NTAYLOR 8
#define NSQUARE 7         // Y = A*dt / 2^7

// ---------------- device scratch (no allocs allowed) ----------------
__device__ float g_Y [DD*DD];
__device__ float g_E [DD*DD];
__device__ float g_P [DD*DD];
__device__ float g_T [DD*DD];
__device__ float g_T2[DD*DD];
__device__ float g_Bb[DD*UDIM];
__device__ float g_Ds[NOBS*UDIM];

// ---------------- setup kernels ----------------

// Y = (skew(params) - diag(softplus(gamma))) * dt / 2^NSQUARE
__global__ void build_Y_kernel(const float* __restrict__ skew,
                               const float* __restrict__ gamma,
                               const float* __restrict__ dtp,
                               float* __restrict__ Y)
{
    int idx = blockIdx.x * 256 + threadIdx.x;
    if (idx >= DD*DD) return;
    int i = idx >> 9;
    int j = idx & (DD-1);
    float v;
    if (i < j) {
        v =  skew[i*(DD-1) - (i*(i-1))/2 + (j - i - 1)];
    } else if (i > j) {
        v = -skew[j*(DD-1) - (j*(j-1))/2 + (i - j - 1)];
    } else {
        float g = gamma[i];
        v = -(fmaxf(g, 0.f) + log1pf(expf(-fabsf(g))));   // -softplus(g)
    }
    Y[idx] = v * (dtp[0] * (1.0f / (float)(1 << NSQUARE)));
}

__global__ void init_EPT(float* __restrict__ E, float* __restrict__ P, float* __restrict__ Tm)
{
    int idx = blockIdx.x * 256 + threadIdx.x;
    if (idx >= DD*DD) return;
    int i = idx >> 9, j = idx & (DD-1);
    float v = (i == j) ? 1.f : 0.f;
    E[idx] = v; P[idx] = v; Tm[idx] = v;
}

// after T2 = (T @ Y) / k :  T = T2 ; E += T2 ; P += T2/(k+1)
__global__ void taylor_accum(float* __restrict__ E, float* __restrict__ P,
                             float* __restrict__ Tm, const float* __restrict__ T2,
                             float invk1)
{
    int idx = blockIdx.x * 256 + threadIdx.x;
    if (idx >= DD*DD) return;
    float t = T2[idx];
    Tm[idx] = t;
    E[idx] += t;
    P[idx] += t * invk1;
}

// P = T2 + 0.5*P   (T2 already holds 0.5*E@P)
__global__ void phi_update(float* __restrict__ P, const float* __restrict__ T2)
{
    int idx = blockIdx.x * 256 + threadIdx.x;
    if (idx >= DD*DD) return;
    P[idx] = T2[idx] + 0.5f * P[idx];
}

__global__ void copy_kernel(float* __restrict__ dst, const float* __restrict__ src, int n)
{
    int idx = blockIdx.x * 256 + threadIdx.x;
    if (idx < n) dst[idx] = src[idx];
}

__global__ void scale_by_dt(float* __restrict__ x, const float* __restrict__ dtp, int n)
{
    int idx = blockIdx.x * 256 + threadIdx.x;
    if (idx < n) x[idx] *= dtp[0];
}

__global__ void build_Ds(float* __restrict__ Ds, const float* __restrict__ Dm,
                         const float* __restrict__ dtp)
{
    int idx = blockIdx.x * 256 + threadIdx.x;
    if (idx < NOBS*UDIM) Ds[idx] = Dm[idx] * dtp[0];
}

// Generic row-major NN GEMM: C = alpha * A(MxK) @ B(KxN).  M,N,K multiples of 32.
__global__ void gemm_nn(float* __restrict__ C, const float* __restrict__ A,
                        const float* __restrict__ Bm, int M, int N, int K, float alpha)
{
    __shared__ float As[32][33];
    __shared__ float Bs[32][33];
    int tx = threadIdx.x & 15;
    int ty = threadIdx.x >> 4;
    int j0 = blockIdx.x * 32;
    int i0 = blockIdx.y * 32;
    float acc00 = 0.f, acc01 = 0.f, acc10 = 0.f, acc11 = 0.f;
    for (int k0 = 0; k0 < K; k0 += 32) {
        for (int u = threadIdx.x; u < 32*32; u += 256) {
            int r = u >> 5, c = u & 31;
            As[r][c] = A[(size_t)(i0 + r)*K + k0 + c];
            Bs[r][c] = Bm[(size_t)(k0 + r)*N + j0 + c];
        }
        __syncthreads();
        #pragma unroll
        for (int k = 0; k < 32; k++) {
            float a0 = As[ty*2+0][k];
            float a1 = As[ty*2+1][k];
            float b0 = Bs[k][tx*2+0];
            float b1 = Bs[k][tx*2+1];
            acc00 += a0*b0; acc01 += a0*b1;
            acc10 += a1*b0; acc11 += a1*b1;
        }
        __syncthreads();
    }
    C[(size_t)(i0+ty*2+0)*N + j0+tx*2+0] = alpha*acc00;
    C[(size_t)(i0+ty*2+0)*N + j0+tx*2+1] = alpha*acc01;
    C[(size_t)(i0+ty*2+1)*N + j0+tx*2+0] = alpha*acc10;
    C[(size_t)(i0+ty*2+1)*N + j0+tx*2+1] = alpha*acc11;
}

// ---------------- scan step kernel ----------------
// Z-blocks (blk < nZblocks): Zout[b,j] = sum_k Zprev[b,k]*Abar[j,k] + sum_m Ut[b,m]*Bbar[j,m]
// Y-blocks               : Yout[b,o] = sum_k Zprev[b,k]*C[o,k]    + sum_m Utm1[b,m]*Ds[o,m]
// (Ds = dt*D precomputed; Bbar pre-scaled by dt)
// BM=64 (batch) x BN=32 (out col), BK=16, 128 threads, 4x4 microtiles, double-buffered smem.

#define BM 64
#define BN 32
#define BK 16

__device__ __forceinline__ void load_tile_regs(
    const float* __restrict__ Aop, int ldA,
    const float* __restrict__ Bop, int ldB,
    int row0, int col0, int nB, int k0, int tid,
    float4& a0, float4& a1, float4& b0)
{
    {
        int b  = tid >> 2;
        int kg = tid & 3;
        a0 = *reinterpret_cast<const float4*>(Aop + (size_t)(row0 + b)*ldA + k0 + kg*4);
        int unit = tid + 128;
        b  = unit >> 2;
        kg = unit & 3;
        a1 = *reinterpret_cast<const float4*>(Aop + (size_t)(row0 + b)*ldA + k0 + kg*4);
    }
    {
        int j  = tid >> 2;
        int kg = tid & 3;
        if (col0 + j < nB)
            b0 = *reinterpret_cast<const float4*>(Bop + (size_t)(col0 + j)*ldB + k0 + kg*4);
        else
            b0 = make_float4(0.f, 0.f, 0.f, 0.f);
    }
}

__device__ __forceinline__ void store_tile_smem(
    float As[BK][BM+4], float Bs[BK][BN], int tid,
    float4 a0, float4 a1, float4 b0)
{
    int b  = tid >> 2;
    int kg = tid & 3;
    As[kg*4+0][b] = a0.x; As[kg*4+1][b] = a0.y;
    As[kg*4+2][b] = a0.z; As[kg*4+3][b] = a0.w;
    int unit = tid + 128;
    b  = unit >> 2;
    kg = unit & 3;
    As[kg*4+0][b] = a1.x; As[kg*4+1][b] = a1.y;
    As[kg*4+2][b] = a1.z; As[kg*4+3][b] = a1.w;
    int j = tid >> 2;
    kg = tid & 3;
    Bs[kg*4+0][j] = b0.x; Bs[kg*4+1][j] = b0.y;
    Bs[kg*4+2][j] = b0.z; Bs[kg*4+3][j] = b0.w;
}

__global__ void __launch_bounds__(128) step_kernel(
    const float* __restrict__ Zprev, const float* __restrict__ Ut,
    const float* __restrict__ Utm1,  float* __restrict__ Zout,
    float* __restrict__ Yout,        const float* __restrict__ Abar,
    const float* __restrict__ Bbar,  const float* __restrict__ Cm,
    const float* __restrict__ Ds,    int nZblocks, int writeY)
{
    __shared__ float As[2][BK][BM+4];
    __shared__ float Bs[2][BK][BN];

    int blk = blockIdx.x;
    const float *aop1, *bop1, *aop2, *bop2;
    int lda1, ldb1, lda2, ldb2;
    int row0, col0, nB, ncols, ldo;
    float* outp;

    if (blk < nZblocks) {
        int rb = blk & 7, cb = blk >> 3;           // 8 x 16
        row0 = rb*BM; col0 = cb*BN;
        aop1 = Zprev; lda1 = DD;   bop1 = Abar; ldb1 = DD;
        aop2 = Ut;    lda2 = UDIM; bop2 = Bbar; ldb2 = UDIM;
        nB = DD; ncols = DD; outp = Zout; ldo = DD;
    } else {
        if (!writeY) return;
        int local = blk - nZblocks;
        int rb = local & 7, cb = local >> 3;       // 8 x 2
        row0 = rb*BM; col0 = cb*BN;
        aop1 = Zprev; lda1 = DD;   bop1 = Cm; ldb1 = DD;
        aop2 = Utm1;  lda2 = UDIM; bop2 = Ds; ldb2 = UDIM;
        nB = NOBS; ncols = NOBS; outp = Yout; ldo = NOBS;
    }

    const int NT1 = DD / BK;        // 32 tiles over K=512
    const int NT2 = UDIM / BK;      // 2 tiles over K=32
    const int ntiles = NT1 + NT2;   // 34

    int tid = threadIdx.x;
    int bx = tid & 7;    // col group (4 cols each)
    int by = tid >> 3;   // row group (4 rows each)

    float acc[4][4];
    #pragma unroll
    for (int i = 0; i < 4; i++)
        #pragma unroll
        for (int j = 0; j < 4; j++) acc[i][j] = 0.f;

    float4 pa0, pa1, pb0;
    load_tile_regs(aop1, lda1, bop1, ldb1, row0, col0, nB, 0, tid, pa0, pa1, pb0);
    store_tile_smem(As[0], Bs[0], tid, pa0, pa1, pb0);
    __syncthreads();

    for (int tt = 0; tt < ntiles; tt++) {
        int cur = tt & 1;
        if (tt + 1 < ntiles) {
            int nt = tt + 1;
            int phase = (nt >= NT1) ? 1 : 0;
            int k0 = phase ? (nt - NT1)*BK : nt*BK;
            const float* Aop = phase ? aop2 : aop1;
            const float* Bop = phase ? bop2 : bop1;
            int ldA = phase ? lda2 : lda1;
            int ldB = phase ? ldb2 : ldb1;
            load_tile_regs(Aop, ldA, Bop, ldB, row0, col0, nB, k0, tid, pa0, pa1, pb0);
        }
        #pragma unroll
        for (int k = 0; k < BK; k++) {
            float4 a = *reinterpret_cast<const float4*>(&As[cur][k][by*4]);
            float4 b = *reinterpret_cast<const float4*>(&Bs[cur][k][bx*4]);
            acc[0][0] += a.x*b.x; acc[0][1] += a.x*b.y; acc[0][2] += a.x*b.z; acc[0][3] += a.x*b.w;
            acc[1][0] += a.y*b.x; acc[1][1] += a.y*b.y; acc[1][2] += a.y*b.z; acc[1][3] += a.y*b.w;
            acc[2][0] += a.z*b.x; acc[2][1] += a.z*b.y; acc[2][2] += a.z*b.z; acc[2][3] += a.z*b.w;
            acc[3][0] += a.w*b.x; acc[3][1] += a.w*b.y; acc[3][2] += a.w*b.z; acc[3][3] += a.w*b.w;
        }
        if (tt + 1 < ntiles)
            store_tile_smem(As[(tt+1)&1], Bs[(tt+1)&1], tid, pa0, pa1, pb0);
        __syncthreads();
    }

    #pragma unroll
    for (int i = 0; i < 4; i++) {
        int r = row0 + by*4 + i;
        #pragma unroll
        for (int j = 0; j < 4; j++) {
            int c = col0 + bx*4 + j;
            if (c < ncols) outp[(size_t)r*ldo + c] = acc[i][j];
        }
    }
}

// ---------------- host orchestration (graph-capturable) ----------------
extern "C" void kernel_launch(void* const* d_in, const int* in_sizes, int n_in,
                              void* d_out, int out_size)
{
    const float* z_dyn = (const float*)d_in[0];
    // d_in[1] = z_static (unused by reference)
    const float* dtp   = (const float*)d_in[2];
    const float* U     = (const float*)d_in[3];
    const float* skew  = (const float*)d_in[4];
    const float* gamma = (const float*)d_in[5];
    const float* B_ct  = (const float*)d_in[6];
    const float* Cm    = (const float*)d_in[7];
    const float* Dm    = (const float*)d_in[8];

    float *Y_, *E_, *P_, *T_, *T2_, *Bb_, *Ds_;
    cudaGetSymbolAddress((void**)&Y_,  g_Y);
    cudaGetSymbolAddress((void**)&E_,  g_E);
    cudaGetSymbolAddress((void**)&P_,  g_P);
    cudaGetSymbolAddress((void**)&T_,  g_T);
    cudaGetSymbolAddress((void**)&T2_, g_T2);
    cudaGetSymbolAddress((void**)&Bb_, g_Bb);
    cudaGetSymbolAddress((void**)&Ds_, g_Ds);

    const int n2 = DD*DD;
    const int g2 = (n2 + 255) / 256;
    dim3 ggemm(DD/32, DD/32);

    // --- setup: Y = A*dt/2^s ; E = exp(Y), P = phi1(Y) via Taylor deg 8 ---
    build_Y_kernel<<<g2, 256>>>(skew, gamma, dtp, Y_);
    init_EPT<<<g2, 256>>>(E_, P_, T_);
    for (int k = 1; k <= NTAYLOR; k++) {
        gemm_nn<<<ggemm, 256>>>(T2_, T_, Y_, DD, DD, DD, 1.0f/(float)k);
        taylor_accum<<<g2, 256>>>(E_, P_, T_, T2_, 1.0f/(float)(k+1));
    }
    // --- doubling: phi1(2Y) = 0.5*(E+I)*P ; E <- E^2 ---
    for (int s = 0; s < NSQUARE; s++) {
        gemm_nn<<<ggemm, 256>>>(T2_, E_, P_, DD, DD, DD, 0.5f);
        phi_update<<<g2, 256>>>(P_, T2_);
        gemm_nn<<<ggemm, 256>>>(T_, E_, E_, DD, DD, DD, 1.0f);
        copy_kernel<<<g2, 256>>>(E_, T_, n2);
    }
    // --- B_bar = dt * P @ B_ct ;  Ds = dt * D ---
    gemm_nn<<<dim3(UDIM/32, DD/32), 256>>>(Bb_, P_, B_ct, DD, UDIM, DD, 1.0f);
    scale_by_dt<<<(DD*UDIM + 255)/256, 256>>>(Bb_, dtp, DD*UDIM);
    build_Ds<<<(NOBS*UDIM + 255)/256, 256>>>(Ds_, Dm, dtp);

    // --- scan ---
    float* Zo = (float*)d_out;
    float* Yo = (float*)d_out + (size_t)TT*BB*DD;
    const int ZB = (BB/BM) * (DD/BN);   // 8*16 = 128 Z-blocks
    const int YB = (BB/BM) * 2;         // 8*2  = 16 Y-blocks

    for (int t = 0; t < TT; t++) {
        const float* Zp   = (t == 0) ? z_dyn : Zo + (size_t)(t-1)*BB*DD;
        const float* ut   = U + (size_t)t*BB*UDIM;
        const float* utm1 = (t == 0) ? ut : U + (size_t)(t-1)*BB*UDIM;
        float* yout       = (t == 0) ? Yo : Yo + (size_t)(t-1)*BB*NOBS;
        step_kernel<<<ZB + YB, 128>>>(Zp, ut, utm1,
                                      Zo + (size_t)t*BB*DD, yout,
                                      E_, Bb_, Cm, Ds_, ZB, (t > 0) ? 1 : 0);
    }
    // final Y[T-1]
    step_kernel<<<YB, 128>>>(Zo + (size_t)(TT-1)*BB*DD, U,
                             U + (size_t)(TT-1)*BB*UDIM,
                             Zo, Yo + (size_t)(TT-1)*BB*NOBS,
                             E_, Bb_, Cm, Ds_, 0, 1);
}

// round 4
// speedup vs baseline: 2.4049x; 2.4025x over previous
#include <cuda_runtime.h>
#include <cuda_bf16.h>
#include <math.h>
#include <stdint.h>

#define DD   512
#define BB   512
#define TT   256
#define UDIM 32
#define NOBS 50
#define NTAYLOR 8
#define NSQUARE 7

// ---------------- device scratch ----------------
__device__ float g_Y [DD*DD];
__device__ float g_E [DD*DD];
__device__ float g_P [DD*DD];
__device__ float g_T [DD*DD];
__device__ float g_T2[DD*DD];
__device__ float g_Bb[DD*UDIM];

__device__ __nv_bfloat16 g_Ehi [DD*DD];
__device__ __nv_bfloat16 g_Elo [DD*DD];
__device__ __nv_bfloat16 g_Chi [64*DD];
__device__ __nv_bfloat16 g_Clo [64*DD];
__device__ __nv_bfloat16 g_Bbhi[DD*64];
__device__ __nv_bfloat16 g_Bblo[DD*64];
__device__ __nv_bfloat16 g_Dshi[64*64];
__device__ __nv_bfloat16 g_Dslo[64*64];

// ---------------- helpers ----------------
__device__ __forceinline__ uint32_t smem_u32(const void* p) {
    uint32_t a;
    asm("{ .reg .u64 t; cvta.to.shared.u64 t, %1; cvt.u32.u64 %0, t; }" : "=r"(a) : "l"(p));
    return a;
}
#define SWZ(o) ((o) ^ (((o) >> 3) & 0x70))

__device__ __forceinline__ void ldmx4(uint32_t r[4], uint32_t addr) {
    asm volatile("ldmatrix.sync.aligned.m8n8.x4.shared.b16 {%0,%1,%2,%3}, [%4];"
        : "=r"(r[0]), "=r"(r[1]), "=r"(r[2]), "=r"(r[3]) : "r"(addr));
}
__device__ __forceinline__ void mma16816(float acc[4], const uint32_t a[4],
                                          uint32_t b0, uint32_t b1) {
    asm volatile("mma.sync.aligned.m16n8k16.row.col.f32.bf16.bf16.f32 "
        "{%0,%1,%2,%3},{%4,%5,%6,%7},{%8,%9},{%0,%1,%2,%3};"
        : "+f"(acc[0]), "+f"(acc[1]), "+f"(acc[2]), "+f"(acc[3])
        : "r"(a[0]), "r"(a[1]), "r"(a[2]), "r"(a[3]), "r"(b0), "r"(b1));
}
__device__ __forceinline__ void split4(float4 v, uint32_t hi_a, uint32_t lo_a) {
    __nv_bfloat162 h0 = __floats2bfloat162_rn(v.x, v.y);
    __nv_bfloat162 h1 = __floats2bfloat162_rn(v.z, v.w);
    __nv_bfloat162 l0 = __floats2bfloat162_rn(v.x - __bfloat162float(h0.x), v.y - __bfloat162float(h0.y));
    __nv_bfloat162 l1 = __floats2bfloat162_rn(v.z - __bfloat162float(h1.x), v.w - __bfloat162float(h1.y));
    uint32_t h0u = *(uint32_t*)&h0, h1u = *(uint32_t*)&h1;
    uint32_t l0u = *(uint32_t*)&l0, l1u = *(uint32_t*)&l1;
    asm volatile("st.shared.v2.b32 [%0], {%1,%2};" :: "r"(hi_a), "r"(h0u), "r"(h1u) : "memory");
    asm volatile("st.shared.v2.b32 [%0], {%1,%2};" :: "r"(lo_a), "r"(l0u), "r"(l1u) : "memory");
}

// ---------------- setup kernels (fp32) ----------------
__global__ void build_Y_kernel(const float* __restrict__ skew, const float* __restrict__ gamma,
                               const float* __restrict__ dtp, float* __restrict__ Y)
{
    int idx = blockIdx.x*256 + threadIdx.x;
    if (idx >= DD*DD) return;
    int i = idx >> 9, j = idx & (DD-1);
    float v;
    if (i < j)      v =  skew[i*(DD-1) - (i*(i-1))/2 + (j-i-1)];
    else if (i > j) v = -skew[j*(DD-1) - (j*(j-1))/2 + (i-j-1)];
    else { float g = gamma[i]; v = -(fmaxf(g,0.f) + log1pf(expf(-fabsf(g)))); }
    Y[idx] = v * (dtp[0] * (1.0f/(float)(1<<NSQUARE)));
}
__global__ void init_EPT(float* E, float* P, float* Tm) {
    int idx = blockIdx.x*256 + threadIdx.x;
    if (idx >= DD*DD) return;
    float v = ((idx>>9) == (idx&(DD-1))) ? 1.f : 0.f;
    E[idx]=v; P[idx]=v; Tm[idx]=v;
}
__global__ void taylor_accum(float* E, float* P, float* Tm, const float* T2, float invk1) {
    int idx = blockIdx.x*256 + threadIdx.x;
    if (idx >= DD*DD) return;
    float t = T2[idx]; Tm[idx]=t; E[idx]+=t; P[idx]+=t*invk1;
}
__global__ void phi_update(float* P, const float* T2) {
    int idx = blockIdx.x*256 + threadIdx.x;
    if (idx >= DD*DD) return;
    P[idx] = T2[idx] + 0.5f*P[idx];
}
__global__ void copy_kernel(float* dst, const float* src, int n) {
    int idx = blockIdx.x*256 + threadIdx.x;
    if (idx < n) dst[idx] = src[idx];
}
__global__ void scale_by_dt(float* x, const float* dtp, int n) {
    int idx = blockIdx.x*256 + threadIdx.x;
    if (idx < n) x[idx] *= dtp[0];
}
__global__ void gemm_nn(float* __restrict__ C, const float* __restrict__ A,
                        const float* __restrict__ Bm, int M, int N, int K, float alpha)
{
    __shared__ float As[32][33];
    __shared__ float Bs[32][33];
    int tx = threadIdx.x & 15, ty = threadIdx.x >> 4;
    int j0 = blockIdx.x*32, i0 = blockIdx.y*32;
    float a00=0,a01=0,a10=0,a11=0;
    for (int k0 = 0; k0 < K; k0 += 32) {
        for (int u = threadIdx.x; u < 32*32; u += 256) {
            int r = u>>5, c = u&31;
            As[r][c] = A[(size_t)(i0+r)*K + k0+c];
            Bs[r][c] = Bm[(size_t)(k0+r)*N + j0+c];
        }
        __syncthreads();
        #pragma unroll
        for (int k = 0; k < 32; k++) {
            float x0=As[ty*2][k], x1=As[ty*2+1][k];
            float y0=Bs[k][tx*2], y1=Bs[k][tx*2+1];
            a00+=x0*y0; a01+=x0*y1; a10+=x1*y0; a11+=x1*y1;
        }
        __syncthreads();
    }
    C[(size_t)(i0+ty*2+0)*N + j0+tx*2+0]=alpha*a00;
    C[(size_t)(i0+ty*2+0)*N + j0+tx*2+1]=alpha*a01;
    C[(size_t)(i0+ty*2+1)*N + j0+tx*2+0]=alpha*a10;
    C[(size_t)(i0+ty*2+1)*N + j0+tx*2+1]=alpha*a11;
}
// split src (rs x cs) into padded (rd x cd) bf16 hi/lo, optional *dt
__global__ void split_mat(const float* __restrict__ src, __nv_bfloat16* hi, __nv_bfloat16* lo,
                          int rs, int cs, int rd, int cd, const float* dtp, int usedt)
{
    int idx = blockIdx.x*256 + threadIdx.x;
    if (idx >= rd*cd) return;
    int r = idx / cd, c = idx % cd;
    float v = (r < rs && c < cs) ? src[(size_t)r*cs + c] : 0.f;
    if (usedt) v *= dtp[0];
    __nv_bfloat16 h = __float2bfloat16(v);
    hi[idx] = h;
    lo[idx] = __float2bfloat16(v - __bfloat162float(h));
}

// ---------------- mma.sync scan step ----------------
// CTA tile: 64 (batch) x 32 (out cols). 4 warps 2x2 (each 32x16). K = 512 + 64(u).
// smem: B hi (8 chunks x 4KB) | B lo | B2 hi 4KB | B2 lo 4KB | Z ring 2 x (hi 8KB + lo 8KB)
#define SM_BH   0u
#define SM_BL   32768u
#define SM_B2H  65536u
#define SM_B2L  69632u
#define SM_ZR   73728u
#define SM_TOT  106496u

__global__ void __launch_bounds__(128, 1) step_mma(
    const float* __restrict__ Zprev, const float* __restrict__ Ut,
    const float* __restrict__ Utm1,  float* __restrict__ Zout,
    float* __restrict__ Yout,
    const __nv_bfloat16* __restrict__ Ehi,  const __nv_bfloat16* __restrict__ Elo,
    const __nv_bfloat16* __restrict__ Bbhi, const __nv_bfloat16* __restrict__ Bblo,
    const __nv_bfloat16* __restrict__ Chi,  const __nv_bfloat16* __restrict__ Clo,
    const __nv_bfloat16* __restrict__ Dshi, const __nv_bfloat16* __restrict__ Dslo,
    int nZ, int writeY)
{
    extern __shared__ __align__(1024) char smem[];
    const int tid = threadIdx.x;
    const int lane = tid & 31;
    const int w = tid >> 5;
    const int wm = (w & 1) * 32;
    const int wn = (w >> 1) * 16;
    const int blk = blockIdx.x;
    const bool isZ = blk < nZ;
    if (!isZ && !writeY) return;

    int m0, n0;
    const __nv_bfloat16 *Bh_g, *Bl_g, *B2h_g, *B2l_g;
    if (isZ) {
        m0 = (blk >> 4) * 64; n0 = (blk & 15) * 32;
        Bh_g = Ehi; Bl_g = Elo; B2h_g = Bbhi; B2l_g = Bblo;
    } else {
        int local = blk - nZ;
        m0 = (local >> 1) * 64; n0 = (local & 1) * 32;
        Bh_g = Chi; Bl_g = Clo; B2h_g = Dshi; B2l_g = Dslo;
    }

    const uint32_t sb = smem_u32(smem);

    // ---- prologue: load B operand (32 rows x 512 k, hi+lo) into swizzled chunks ----
    #pragma unroll
    for (int i = 0; i < 16; i++) {
        int idx = i*128 + tid;
        int r = idx >> 6, g = idx & 63;             // 64 x 16B groups per row
        uint32_t soff = (uint32_t)((g >> 3)*4096) + SWZ((uint32_t)(r*128 + (g & 7)*16));
        *reinterpret_cast<uint4*>(smem + SM_BH + soff) =
            *reinterpret_cast<const uint4*>(Bh_g + (size_t)(n0 + r)*DD + g*8);
        *reinterpret_cast<uint4*>(smem + SM_BL + soff) =
            *reinterpret_cast<const uint4*>(Bl_g + (size_t)(n0 + r)*DD + g*8);
    }
    // ---- B2 (u operand, 32 rows x 64 k padded) ----
    #pragma unroll
    for (int i = 0; i < 2; i++) {
        int idx = i*128 + tid;
        int r = idx >> 3, g = idx & 7;
        uint32_t soff = SWZ((uint32_t)(r*128 + g*16));
        *reinterpret_cast<uint4*>(smem + SM_B2H + soff) =
            *reinterpret_cast<const uint4*>(B2h_g + (size_t)(n0 + r)*64 + g*8);
        *reinterpret_cast<uint4*>(smem + SM_B2L + soff) =
            *reinterpret_cast<const uint4*>(B2l_g + (size_t)(n0 + r)*64 + g*8);
    }

    // per-thread fragment offsets (within 128B-row tiles)
    const uint32_t aoff0 = (uint32_t)((wm + 0  + (lane & 15))*128 + ((lane >> 4) << 4));
    const uint32_t aoff1 = (uint32_t)((wm + 16 + (lane & 15))*128 + ((lane >> 4) << 4));
    const uint32_t boff  = (uint32_t)((wn + (lane & 7) + ((lane >> 4) & 1)*8)*128 + ((lane >> 3) & 1)*16);

    const int ldr = tid >> 4;      // load row (0..7 step handled by i)
    const int lfq = tid & 15;      // float4 index within 64-float row

    float4 pf[8];
    // prefetch chunk 0
    #pragma unroll
    for (int i = 0; i < 8; i++) {
        int r = i*8 + ldr;
        pf[i] = *reinterpret_cast<const float4*>(Zprev + (size_t)(m0 + r)*DD + lfq*4);
    }
    // store chunk 0 into buf 0
    {
        uint32_t zb = sb + SM_ZR;
        #pragma unroll
        for (int i = 0; i < 8; i++) {
            int r = i*8 + ldr;
            uint32_t off = SWZ((uint32_t)(r*128 + lfq*8));
            split4(pf[i], zb + off, zb + 8192u + off);
        }
    }
    __syncthreads();

    float acc[2][2][4];
    #pragma unroll
    for (int a = 0; a < 2; a++)
        #pragma unroll
        for (int b = 0; b < 2; b++)
            #pragma unroll
            for (int c = 0; c < 4; c++) acc[a][b][c] = 0.f;

    for (int s = 0; s < 9; s++) {
        // prefetch next chunk
        if (s < 8) {
            if (s + 1 < 8) {
                #pragma unroll
                for (int i = 0; i < 8; i++) {
                    int r = i*8 + ldr;
                    pf[i] = *reinterpret_cast<const float4*>(
                        Zprev + (size_t)(m0 + r)*DD + (s+1)*64 + lfq*4);
                }
            } else {
                const float* Us = isZ ? Ut : Utm1;
                #pragma unroll
                for (int i = 0; i < 8; i++) {
                    int r = i*8 + ldr;
                    pf[i] = (lfq < 8)
                        ? *reinterpret_cast<const float4*>(Us + (size_t)(m0 + r)*UDIM + lfq*4)
                        : make_float4(0.f, 0.f, 0.f, 0.f);
                }
            }
        }
        // compute chunk s
        {
            uint32_t zb  = sb + SM_ZR + (uint32_t)(s & 1)*16384u;
            uint32_t bb  = sb + ((s < 8) ? (SM_BH + (uint32_t)s*4096u) : SM_B2H);
            uint32_t gap = (s < 8) ? 32768u : 4096u;
            #pragma unroll
            for (int k16 = 0; k16 < 4; k16++) {
                uint32_t ah0[4], al0[4], ah1[4], al1[4], bh[4], bl[4];
                uint32_t ad0 = zb + SWZ(aoff0 + (uint32_t)k16*32);
                ldmx4(ah0, ad0); ldmx4(al0, ad0 + 8192u);
                uint32_t ad1 = zb + SWZ(aoff1 + (uint32_t)k16*32);
                ldmx4(ah1, ad1); ldmx4(al1, ad1 + 8192u);
                uint32_t bd = bb + SWZ(boff + (uint32_t)k16*32);
                ldmx4(bh, bd); ldmx4(bl, bd + gap);

                mma16816(acc[0][0], ah0, bh[0], bh[1]);
                mma16816(acc[0][1], ah0, bh[2], bh[3]);
                mma16816(acc[1][0], ah1, bh[0], bh[1]);
                mma16816(acc[1][1], ah1, bh[2], bh[3]);
                mma16816(acc[0][0], al0, bh[0], bh[1]);
                mma16816(acc[0][1], al0, bh[2], bh[3]);
                mma16816(acc[1][0], al1, bh[0], bh[1]);
                mma16816(acc[1][1], al1, bh[2], bh[3]);
                mma16816(acc[0][0], ah0, bl[0], bl[1]);
                mma16816(acc[0][1], ah0, bl[2], bl[3]);
                mma16816(acc[1][0], ah1, bl[0], bl[1]);
                mma16816(acc[1][1], ah1, bl[2], bl[3]);
            }
        }
        __syncthreads();
        if (s < 8) {
            uint32_t zb = sb + SM_ZR + (uint32_t)((s+1) & 1)*16384u;
            #pragma unroll
            for (int i = 0; i < 8; i++) {
                int r = i*8 + ldr;
                uint32_t off = SWZ((uint32_t)(r*128 + lfq*8));
                split4(pf[i], zb + off, zb + 8192u + off);
            }
            __syncthreads();
        }
    }

    // ---- epilogue ----
    int r0 = m0 + wm + (lane >> 2);
    int c0 = n0 + wn + (lane & 3)*2;
    if (isZ) {
        #pragma unroll
        for (int mi = 0; mi < 2; mi++)
            #pragma unroll
            for (int ni = 0; ni < 2; ni++) {
                int row = r0 + mi*16, col = c0 + ni*8;
                float2 v0 = make_float2(acc[mi][ni][0], acc[mi][ni][1]);
                float2 v1 = make_float2(acc[mi][ni][2], acc[mi][ni][3]);
                *reinterpret_cast<float2*>(Zout + (size_t)row*DD + col) = v0;
                *reinterpret_cast<float2*>(Zout + (size_t)(row + 8)*DD + col) = v1;
            }
    } else {
        #pragma unroll
        for (int mi = 0; mi < 2; mi++)
            #pragma unroll
            for (int ni = 0; ni < 2; ni++) {
                int row = r0 + mi*16, col = c0 + ni*8;
                if (col < NOBS)     Yout[(size_t)row*NOBS + col]       = acc[mi][ni][0];
                if (col + 1 < NOBS) Yout[(size_t)row*NOBS + col + 1]   = acc[mi][ni][1];
                if (col < NOBS)     Yout[(size_t)(row+8)*NOBS + col]   = acc[mi][ni][2];
                if (col + 1 < NOBS) Yout[(size_t)(row+8)*NOBS + col+1] = acc[mi][ni][3];
            }
    }
}

// ---------------- host orchestration ----------------
extern "C" void kernel_launch(void* const* d_in, const int* in_sizes, int n_in,
                              void* d_out, int out_size)
{
    const float* z_dyn = (const float*)d_in[0];
    const float* dtp   = (const float*)d_in[2];
    const float* U     = (const float*)d_in[3];
    const float* skew  = (const float*)d_in[4];
    const float* gamma = (const float*)d_in[5];
    const float* B_ct  = (const float*)d_in[6];
    const float* Cm    = (const float*)d_in[7];
    const float* Dm    = (const float*)d_in[8];

    float *Y_, *E_, *P_, *T_, *T2_, *Bb_;
    cudaGetSymbolAddress((void**)&Y_,  g_Y);
    cudaGetSymbolAddress((void**)&E_,  g_E);
    cudaGetSymbolAddress((void**)&P_,  g_P);
    cudaGetSymbolAddress((void**)&T_,  g_T);
    cudaGetSymbolAddress((void**)&T2_, g_T2);
    cudaGetSymbolAddress((void**)&Bb_, g_Bb);

    __nv_bfloat16 *Ehi, *Elo, *Chi, *Clo, *Bbhi, *Bblo, *Dshi, *Dslo;
    cudaGetSymbolAddress((void**)&Ehi,  g_Ehi);
    cudaGetSymbolAddress((void**)&Elo,  g_Elo);
    cudaGetSymbolAddress((void**)&Chi,  g_Chi);
    cudaGetSymbolAddress((void**)&Clo,  g_Clo);
    cudaGetSymbolAddress((void**)&Bbhi, g_Bbhi);
    cudaGetSymbolAddress((void**)&Bblo, g_Bblo);
    cudaGetSymbolAddress((void**)&Dshi, g_Dshi);
    cudaGetSymbolAddress((void**)&Dslo, g_Dslo);

    cudaFuncSetAttribute(step_mma, cudaFuncAttributeMaxDynamicSharedMemorySize, SM_TOT);

    const int n2 = DD*DD;
    const int g2 = (n2 + 255)/256;
    dim3 ggemm(DD/32, DD/32);

    // setup: E = expm(A dt), P = phi1 (scaling & squaring, Taylor-8)
    build_Y_kernel<<<g2, 256>>>(skew, gamma, dtp, Y_);
    init_EPT<<<g2, 256>>>(E_, P_, T_);
    for (int k = 1; k <= NTAYLOR; k++) {
        gemm_nn<<<ggemm, 256>>>(T2_, T_, Y_, DD, DD, DD, 1.0f/(float)k);
        taylor_accum<<<g2, 256>>>(E_, P_, T_, T2_, 1.0f/(float)(k+1));
    }
    for (int s = 0; s < NSQUARE; s++) {
        gemm_nn<<<ggemm, 256>>>(T2_, E_, P_, DD, DD, DD, 0.5f);
        phi_update<<<g2, 256>>>(P_, T2_);
        gemm_nn<<<ggemm, 256>>>(T_, E_, E_, DD, DD, DD, 1.0f);
        copy_kernel<<<g2, 256>>>(E_, T_, n2);
    }
    gemm_nn<<<dim3(UDIM/32, DD/32), 256>>>(Bb_, P_, B_ct, DD, UDIM, DD, 1.0f);
    scale_by_dt<<<(DD*UDIM + 255)/256, 256>>>(Bb_, dtp, DD*UDIM);

    // presplit bf16 hi/lo operands
    split_mat<<<g2, 256>>>(E_, Ehi, Elo, DD, DD, DD, DD, dtp, 0);
    split_mat<<<(64*DD + 255)/256, 256>>>(Cm, Chi, Clo, NOBS, DD, 64, DD, dtp, 0);
    split_mat<<<(DD*64 + 255)/256, 256>>>(Bb_, Bbhi, Bblo, DD, UDIM, DD, 64, dtp, 0);
    split_mat<<<(64*64 + 255)/256, 256>>>(Dm, Dshi, Dslo, NOBS, UDIM, 64, 64, dtp, 1);

    float* Zo = (float*)d_out;
    float* Yo = (float*)d_out + (size_t)TT*BB*DD;
    const int ZB = (BB/64) * (DD/32);   // 8*16 = 128
    const int YB = (BB/64) * 2;         // 16

    for (int t = 0; t < TT; t++) {
        const float* Zp   = (t == 0) ? z_dyn : Zo + (size_t)(t-1)*BB*DD;
        const float* ut   = U + (size_t)t*BB*UDIM;
        const float* utm1 = (t == 0) ? ut : U + (size_t)(t-1)*BB*UDIM;
        float* yout       = (t == 0) ? Yo : Yo + (size_t)(t-1)*BB*NOBS;
        step_mma<<<ZB + YB, 128, SM_TOT>>>(Zp, ut, utm1,
                                           Zo + (size_t)t*BB*DD, yout,
                                           Ehi, Elo, Bbhi, Bblo, Chi, Clo, Dshi, Dslo,
                                           ZB, (t > 0) ? 1 : 0);
    }
    step_mma<<<YB, 128, SM_TOT>>>(Zo + (size_t)(TT-1)*BB*DD, U,
                                  U + (size_t)(TT-1)*BB*UDIM,
                                  Zo, Yo + (size_t)(TT-1)*BB*NOBS,
                                  Ehi, Elo, Bbhi, Bblo, Chi, Clo, Dshi, Dslo,
                                  0, 1);
}

// round 5
// speedup vs baseline: 2.5249x; 1.0499x over previous
#include <cuda_runtime.h>
#include <cuda_bf16.h>
#include <math.h>
#include <stdint.h>

#define DD   512
#define BB   512
#define TT   256
#define UDIM 32
#define NOBS 50
#define NTAYLOR 8
#define NSQUARE 7
#define NCTA 144

// ---------------- device scratch ----------------
__device__ float g_Y [DD*DD];
__device__ float g_E [DD*DD];
__device__ float g_P [DD*DD];
__device__ float g_T [DD*DD];
__device__ float g_T2[DD*DD];
__device__ float g_Bb[DD*UDIM];

__device__ __nv_bfloat16 g_Ehi [DD*DD];
__device__ __nv_bfloat16 g_Elo [DD*DD];
__device__ __nv_bfloat16 g_Chi [64*DD];
__device__ __nv_bfloat16 g_Clo [64*DD];
__device__ __nv_bfloat16 g_Bbhi[DD*64];
__device__ __nv_bfloat16 g_Bblo[DD*64];
__device__ __nv_bfloat16 g_Dshi[64*64];
__device__ __nv_bfloat16 g_Dslo[64*64];

__device__ unsigned g_count;
__device__ unsigned g_release;

// ---------------- helpers ----------------
__device__ __forceinline__ uint32_t smem_u32(const void* p) {
    uint32_t a;
    asm("{ .reg .u64 t; cvta.to.shared.u64 t, %1; cvt.u32.u64 %0, t; }" : "=r"(a) : "l"(p));
    return a;
}
#define SWZ(o) ((o) ^ (((o) >> 3) & 0x70))

__device__ __forceinline__ void ldmx4(uint32_t r[4], uint32_t addr) {
    asm volatile("ldmatrix.sync.aligned.m8n8.x4.shared.b16 {%0,%1,%2,%3}, [%4];"
        : "=r"(r[0]), "=r"(r[1]), "=r"(r[2]), "=r"(r[3]) : "r"(addr));
}
__device__ __forceinline__ void mma16816(float acc[4], const uint32_t a[4],
                                          uint32_t b0, uint32_t b1) {
    asm volatile("mma.sync.aligned.m16n8k16.row.col.f32.bf16.bf16.f32 "
        "{%0,%1,%2,%3},{%4,%5,%6,%7},{%8,%9},{%0,%1,%2,%3};"
        : "+f"(acc[0]), "+f"(acc[1]), "+f"(acc[2]), "+f"(acc[3])
        : "r"(a[0]), "r"(a[1]), "r"(a[2]), "r"(a[3]), "r"(b0), "r"(b1));
}
__device__ __forceinline__ void split4(float4 v, uint32_t hi_a, uint32_t lo_a) {
    __nv_bfloat162 h0 = __floats2bfloat162_rn(v.x, v.y);
    __nv_bfloat162 h1 = __floats2bfloat162_rn(v.z, v.w);
    __nv_bfloat162 l0 = __floats2bfloat162_rn(v.x - __bfloat162float(h0.x), v.y - __bfloat162float(h0.y));
    __nv_bfloat162 l1 = __floats2bfloat162_rn(v.z - __bfloat162float(h1.x), v.w - __bfloat162float(h1.y));
    uint32_t h0u = *(uint32_t*)&h0, h1u = *(uint32_t*)&h1;
    uint32_t l0u = *(uint32_t*)&l0, l1u = *(uint32_t*)&l1;
    asm volatile("st.shared.v2.b32 [%0], {%1,%2};" :: "r"(hi_a), "r"(h0u), "r"(h1u) : "memory");
    asm volatile("st.shared.v2.b32 [%0], {%1,%2};" :: "r"(lo_a), "r"(l0u), "r"(l1u) : "memory");
}

// ---------------- setup kernels ----------------
__global__ void build_Y_kernel(const float* __restrict__ skew, const float* __restrict__ gamma,
                               const float* __restrict__ dtp, float* __restrict__ Y)
{
    int idx = blockIdx.x*256 + threadIdx.x;
    if (idx >= DD*DD) return;
    int i = idx >> 9, j = idx & (DD-1);
    float v;
    if (i < j)      v =  skew[i*(DD-1) - (i*(i-1))/2 + (j-i-1)];
    else if (i > j) v = -skew[j*(DD-1) - (j*(j-1))/2 + (i-j-1)];
    else { float g = gamma[i]; v = -(fmaxf(g,0.f) + log1pf(expf(-fabsf(g)))); }
    Y[idx] = v * (dtp[0] * (1.0f/(float)(1<<NSQUARE)));
}
__global__ void init_EPT(float* E, float* P, float* Tm) {
    int idx = blockIdx.x*256 + threadIdx.x;
    if (idx >= DD*DD) return;
    float v = ((idx>>9) == (idx&(DD-1))) ? 1.f : 0.f;
    E[idx]=v; P[idx]=v; Tm[idx]=v;
}
__global__ void reset_barrier() { g_count = 0; g_release = 0; }

// fused fp32 GEMM: 32x64 tile, BK=16, 128 threads, register-prefetch single-buffer
// mode 0: C = acc ; mode 1 (taylor): tv=acc*alpha; C=tv; E+=tv; P+=tv*invk1
// mode 2 (phi): C = 0.5*acc + 0.5*Pin[idx]
__global__ void __launch_bounds__(128) gemm_f32(
    const float* __restrict__ A, const float* __restrict__ Bm, float* __restrict__ C,
    float* __restrict__ Eacc, float* __restrict__ Pacc, const float* __restrict__ Pin,
    float alpha, float invk1, int mode)
{
    __shared__ float As[16][32];
    __shared__ float Bs[16][64];
    const int tid = threadIdx.x;
    const int i0 = blockIdx.y*32, j0 = blockIdx.x*64;
    const int tm = tid & 7, tn = tid >> 3;
    float acc[4][4] = {};
    const int ar = tid >> 2, akg = tid & 3;
    const int u0 = tid*2, u1 = tid*2 + 1;

    float4 pa, pb0, pb1;
    pa  = *reinterpret_cast<const float4*>(A + (size_t)(i0+ar)*DD + akg*4);
    pb0 = *reinterpret_cast<const float4*>(Bm + (size_t)(u0>>4)*DD + j0 + (u0&15)*4);
    pb1 = *reinterpret_cast<const float4*>(Bm + (size_t)(u1>>4)*DD + j0 + (u1&15)*4);

    for (int kt = 0; kt < DD/16; kt++) {
        As[akg*4+0][ar] = pa.x; As[akg*4+1][ar] = pa.y;
        As[akg*4+2][ar] = pa.z; As[akg*4+3][ar] = pa.w;
        *reinterpret_cast<float4*>(&Bs[u0>>4][(u0&15)*4]) = pb0;
        *reinterpret_cast<float4*>(&Bs[u1>>4][(u1&15)*4]) = pb1;
        __syncthreads();
        if (kt+1 < DD/16) {
            int k0 = (kt+1)*16;
            pa  = *reinterpret_cast<const float4*>(A + (size_t)(i0+ar)*DD + k0 + akg*4);
            pb0 = *reinterpret_cast<const float4*>(Bm + (size_t)(k0 + (u0>>4))*DD + j0 + (u0&15)*4);
            pb1 = *reinterpret_cast<const float4*>(Bm + (size_t)(k0 + (u1>>4))*DD + j0 + (u1&15)*4);
        }
        #pragma unroll
        for (int k = 0; k < 16; k++) {
            float4 a = *reinterpret_cast<const float4*>(&As[k][tm*4]);
            float4 b = *reinterpret_cast<const float4*>(&Bs[k][tn*4]);
            acc[0][0]+=a.x*b.x; acc[0][1]+=a.x*b.y; acc[0][2]+=a.x*b.z; acc[0][3]+=a.x*b.w;
            acc[1][0]+=a.y*b.x; acc[1][1]+=a.y*b.y; acc[1][2]+=a.y*b.z; acc[1][3]+=a.y*b.w;
            acc[2][0]+=a.z*b.x; acc[2][1]+=a.z*b.y; acc[2][2]+=a.z*b.z; acc[2][3]+=a.z*b.w;
            acc[3][0]+=a.w*b.x; acc[3][1]+=a.w*b.y; acc[3][2]+=a.w*b.z; acc[3][3]+=a.w*b.w;
        }
        __syncthreads();
    }
    #pragma unroll
    for (int i = 0; i < 4; i++) {
        int row = i0 + tm*4 + i;
        #pragma unroll
        for (int j = 0; j < 4; j++) {
            int idx = row*DD + j0 + tn*4 + j;
            float t = acc[i][j];
            if (mode == 0) C[idx] = t;
            else if (mode == 1) { float tv = t*alpha; C[idx] = tv; Eacc[idx] += tv; Pacc[idx] += tv*invk1; }
            else C[idx] = 0.5f*t + 0.5f*Pin[idx];
        }
    }
}

// small GEMM for B_bar = P @ B_ct  (M=512, N=32, K=512)
__global__ void gemm_small(float* __restrict__ C, const float* __restrict__ A,
                           const float* __restrict__ Bm)
{
    __shared__ float As[32][33];
    __shared__ float Bs[32][33];
    int tx = threadIdx.x & 15, ty = threadIdx.x >> 4;
    int i0 = blockIdx.x*32;
    float a00=0,a01=0,a10=0,a11=0;
    for (int k0 = 0; k0 < DD; k0 += 32) {
        for (int u = threadIdx.x; u < 32*32; u += 256) {
            int r = u>>5, c = u&31;
            As[r][c] = A[(size_t)(i0+r)*DD + k0+c];
            Bs[r][c] = Bm[(size_t)(k0+r)*UDIM + c];
        }
        __syncthreads();
        #pragma unroll
        for (int k = 0; k < 32; k++) {
            float x0=As[ty*2][k], x1=As[ty*2+1][k];
            float y0=Bs[k][tx*2], y1=Bs[k][tx*2+1];
            a00+=x0*y0; a01+=x0*y1; a10+=x1*y0; a11+=x1*y1;
        }
        __syncthreads();
    }
    C[(size_t)(i0+ty*2+0)*UDIM + tx*2+0]=a00;
    C[(size_t)(i0+ty*2+0)*UDIM + tx*2+1]=a01;
    C[(size_t)(i0+ty*2+1)*UDIM + tx*2+0]=a10;
    C[(size_t)(i0+ty*2+1)*UDIM + tx*2+1]=a11;
}

__global__ void split_mat(const float* __restrict__ src, __nv_bfloat16* hi, __nv_bfloat16* lo,
                          int rs, int cs, int rd, int cd, const float* dtp, int usedt)
{
    int idx = blockIdx.x*256 + threadIdx.x;
    if (idx >= rd*cd) return;
    int r = idx / cd, c = idx % cd;
    float v = (r < rs && c < cs) ? src[(size_t)r*cs + c] : 0.f;
    if (usedt) v *= dtp[0];
    __nv_bfloat16 h = __float2bfloat16(v);
    hi[idx] = h;
    lo[idx] = __float2bfloat16(v - __bfloat162float(h));
}

// ---------------- persistent mma scan ----------------
// smem: B hi 8x4KB | B lo 8x4KB | B2 hi 4KB | B2 lo 4KB | Z ring 2x16KB  = 104 KB
// padded to 118 KB to force 1 CTA/SM (co-residency for the grid barrier)
#define SM_BH   0u
#define SM_BL   32768u
#define SM_B2H  65536u
#define SM_B2L  69632u
#define SM_ZR   73728u
#define SM_TOT  120832u

__device__ __forceinline__ void grid_barrier(int step) {
    __syncthreads();
    if (threadIdx.x == 0) {
        __threadfence();
        unsigned arrived = atomicAdd(&g_count, 1u) + 1u;
        unsigned want = (unsigned)(step + 1);
        if (arrived == (unsigned)NCTA * want) {
            __threadfence();
            *(volatile unsigned*)&g_release = want;
        } else {
            while (*(volatile unsigned*)&g_release < want) { }
            __threadfence();
        }
    }
    __syncthreads();
}

__global__ void __launch_bounds__(128) scan_persist(
    const float* __restrict__ z_dyn, const float* __restrict__ U,
    float* __restrict__ Zo, float* __restrict__ Yo,
    const __nv_bfloat16* __restrict__ Ehi,  const __nv_bfloat16* __restrict__ Elo,
    const __nv_bfloat16* __restrict__ Bbhi, const __nv_bfloat16* __restrict__ Bblo,
    const __nv_bfloat16* __restrict__ Chi,  const __nv_bfloat16* __restrict__ Clo,
    const __nv_bfloat16* __restrict__ Dshi, const __nv_bfloat16* __restrict__ Dslo)
{
    extern __shared__ __align__(1024) char smem[];
    const int tid = threadIdx.x;
    const int lane = tid & 31;
    const int w = tid >> 5;
    const int wm = (w & 1) * 32;
    const int wn = (w >> 1) * 16;
    const int blk = blockIdx.x;
    const bool isZ = blk < 128;

    int m0, n0;
    const __nv_bfloat16 *Bh_g, *Bl_g, *B2h_g, *B2l_g;
    if (isZ) {
        m0 = (blk >> 4) * 64; n0 = (blk & 15) * 32;
        Bh_g = Ehi; Bl_g = Elo; B2h_g = Bbhi; B2l_g = Bblo;
    } else {
        int local = blk - 128;
        m0 = (local >> 1) * 64; n0 = (local & 1) * 32;
        Bh_g = Chi; Bl_g = Clo; B2h_g = Dshi; B2l_g = Dslo;
    }

    const uint32_t sb = smem_u32(smem);

    // ---- B operand resident for all steps ----
    #pragma unroll
    for (int i = 0; i < 16; i++) {
        int idx = i*128 + tid;
        int r = idx >> 6, g = idx & 63;
        uint32_t soff = (uint32_t)((g >> 3)*4096) + SWZ((uint32_t)(r*128 + (g & 7)*16));
        *reinterpret_cast<uint4*>(smem + SM_BH + soff) =
            *reinterpret_cast<const uint4*>(Bh_g + (size_t)(n0 + r)*DD + g*8);
        *reinterpret_cast<uint4*>(smem + SM_BL + soff) =
            *reinterpret_cast<const uint4*>(Bl_g + (size_t)(n0 + r)*DD + g*8);
    }
    #pragma unroll
    for (int i = 0; i < 2; i++) {
        int idx = i*128 + tid;
        int r = idx >> 3, g = idx & 7;
        uint32_t soff = SWZ((uint32_t)(r*128 + g*16));
        *reinterpret_cast<uint4*>(smem + SM_B2H + soff) =
            *reinterpret_cast<const uint4*>(B2h_g + (size_t)(n0 + r)*64 + g*8);
        *reinterpret_cast<uint4*>(smem + SM_B2L + soff) =
            *reinterpret_cast<const uint4*>(B2l_g + (size_t)(n0 + r)*64 + g*8);
    }
    __syncthreads();

    const uint32_t aoff0 = (uint32_t)((wm + 0  + (lane & 15))*128 + ((lane >> 4) << 4));
    const uint32_t aoff1 = (uint32_t)((wm + 16 + (lane & 15))*128 + ((lane >> 4) << 4));
    const uint32_t boff  = (uint32_t)((wn + (lane & 7) + ((lane >> 4) & 1)*8)*128 + ((lane >> 3) & 1)*16);
    const int ldr = tid >> 4;
    const int lfq = tid & 15;

    for (int t = 0; t <= TT; t++) {
        const bool active = isZ ? (t < TT) : (t >= 1);
        if (active) {
            const float* Zprev;
            const float* Us;
            if (isZ) {
                Zprev = (t == 0) ? z_dyn : Zo + (size_t)(t-1)*BB*DD;
                Us = U + (size_t)t*BB*UDIM;
            } else {
                Zprev = (t == 1) ? ((const float*)Zo) : Zo + (size_t)(t-1)*BB*DD;
                Us = U + (size_t)(t-1)*BB*UDIM;
            }

            float4 pf[8];
            #pragma unroll
            for (int i = 0; i < 8; i++) {
                int r = i*8 + ldr;
                pf[i] = *reinterpret_cast<const float4*>(Zprev + (size_t)(m0 + r)*DD + lfq*4);
            }
            {
                uint32_t zb = sb + SM_ZR;
                #pragma unroll
                for (int i = 0; i < 8; i++) {
                    int r = i*8 + ldr;
                    uint32_t off = SWZ((uint32_t)(r*128 + lfq*8));
                    split4(pf[i], zb + off, zb + 8192u + off);
                }
            }
            __syncthreads();

            float acc[2][2][4];
            #pragma unroll
            for (int a = 0; a < 2; a++)
                #pragma unroll
                for (int b = 0; b < 2; b++)
                    #pragma unroll
                    for (int c = 0; c < 4; c++) acc[a][b][c] = 0.f;

            for (int s = 0; s < 9; s++) {
                if (s < 8) {
                    if (s + 1 < 8) {
                        #pragma unroll
                        for (int i = 0; i < 8; i++) {
                            int r = i*8 + ldr;
                            pf[i] = *reinterpret_cast<const float4*>(
                                Zprev + (size_t)(m0 + r)*DD + (s+1)*64 + lfq*4);
                        }
                    } else {
                        #pragma unroll
                        for (int i = 0; i < 8; i++) {
                            int r = i*8 + ldr;
                            pf[i] = (lfq < 8)
                                ? *reinterpret_cast<const float4*>(Us + (size_t)(m0 + r)*UDIM + lfq*4)
                                : make_float4(0.f, 0.f, 0.f, 0.f);
                        }
                    }
                }
                {
                    uint32_t zb  = sb + SM_ZR + (uint32_t)(s & 1)*16384u;
                    uint32_t bb  = sb + ((s < 8) ? (SM_BH + (uint32_t)s*4096u) : SM_B2H);
                    uint32_t gap = (s < 8) ? 32768u : 4096u;
                    #pragma unroll
                    for (int k16 = 0; k16 < 4; k16++) {
                        uint32_t ah0[4], al0[4], ah1[4], al1[4], bh[4], bl[4];
                        uint32_t ad0 = zb + SWZ(aoff0 + (uint32_t)k16*32);
                        ldmx4(ah0, ad0); ldmx4(al0, ad0 + 8192u);
                        uint32_t ad1 = zb + SWZ(aoff1 + (uint32_t)k16*32);
                        ldmx4(ah1, ad1); ldmx4(al1, ad1 + 8192u);
                        uint32_t bd = bb + SWZ(boff + (uint32_t)k16*32);
                        ldmx4(bh, bd); ldmx4(bl, bd + gap);

                        mma16816(acc[0][0], ah0, bh[0], bh[1]);
                        mma16816(acc[0][1], ah0, bh[2], bh[3]);
                        mma16816(acc[1][0], ah1, bh[0], bh[1]);
                        mma16816(acc[1][1], ah1, bh[2], bh[3]);
                        mma16816(acc[0][0], al0, bh[0], bh[1]);
                        mma16816(acc[0][1], al0, bh[2], bh[3]);
                        mma16816(acc[1][0], al1, bh[0], bh[1]);
                        mma16816(acc[1][1], al1, bh[2], bh[3]);
                        mma16816(acc[0][0], ah0, bl[0], bl[1]);
                        mma16816(acc[0][1], ah0, bl[2], bl[3]);
                        mma16816(acc[1][0], ah1, bl[0], bl[1]);
                        mma16816(acc[1][1], ah1, bl[2], bl[3]);
                    }
                }
                __syncthreads();
                if (s < 8) {
                    uint32_t zb = sb + SM_ZR + (uint32_t)((s+1) & 1)*16384u;
                    #pragma unroll
                    for (int i = 0; i < 8; i++) {
                        int r = i*8 + ldr;
                        uint32_t off = SWZ((uint32_t)(r*128 + lfq*8));
                        split4(pf[i], zb + off, zb + 8192u + off);
                    }
                    __syncthreads();
                }
            }

            int r0 = m0 + wm + (lane >> 2);
            int c0 = n0 + wn + (lane & 3)*2;
            if (isZ) {
                float* Zout = Zo + (size_t)t*BB*DD;
                #pragma unroll
                for (int mi = 0; mi < 2; mi++)
                    #pragma unroll
                    for (int ni = 0; ni < 2; ni++) {
                        int row = r0 + mi*16, col = c0 + ni*8;
                        *reinterpret_cast<float2*>(Zout + (size_t)row*DD + col) =
                            make_float2(acc[mi][ni][0], acc[mi][ni][1]);
                        *reinterpret_cast<float2*>(Zout + (size_t)(row+8)*DD + col) =
                            make_float2(acc[mi][ni][2], acc[mi][ni][3]);
                    }
            } else {
                float* Yout = Yo + (size_t)(t-1)*BB*NOBS;
                #pragma unroll
                for (int mi = 0; mi < 2; mi++)
                    #pragma unroll
                    for (int ni = 0; ni < 2; ni++) {
                        int row = r0 + mi*16, col = c0 + ni*8;
                        if (col < NOBS)     Yout[(size_t)row*NOBS + col]       = acc[mi][ni][0];
                        if (col + 1 < NOBS) Yout[(size_t)row*NOBS + col + 1]   = acc[mi][ni][1];
                        if (col < NOBS)     Yout[(size_t)(row+8)*NOBS + col]   = acc[mi][ni][2];
                        if (col + 1 < NOBS) Yout[(size_t)(row+8)*NOBS + col+1] = acc[mi][ni][3];
                    }
            }
        }
        if (t < TT) grid_barrier(t);
    }
}

// ---------------- host orchestration ----------------
extern "C" void kernel_launch(void* const* d_in, const int* in_sizes, int n_in,
                              void* d_out, int out_size)
{
    const float* z_dyn = (const float*)d_in[0];
    const float* dtp   = (const float*)d_in[2];
    const float* U     = (const float*)d_in[3];
    const float* skew  = (const float*)d_in[4];
    const float* gamma = (const float*)d_in[5];
    const float* B_ct  = (const float*)d_in[6];
    const float* Cm    = (const float*)d_in[7];
    const float* Dm    = (const float*)d_in[8];

    float *Y_, *E_, *P_, *T_, *T2_, *Bb_;
    cudaGetSymbolAddress((void**)&Y_,  g_Y);
    cudaGetSymbolAddress((void**)&E_,  g_E);
    cudaGetSymbolAddress((void**)&P_,  g_P);
    cudaGetSymbolAddress((void**)&T_,  g_T);
    cudaGetSymbolAddress((void**)&T2_, g_T2);
    cudaGetSymbolAddress((void**)&Bb_, g_Bb);

    __nv_bfloat16 *Ehi, *Elo, *Chi, *Clo, *Bbhi, *Bblo, *Dshi, *Dslo;
    cudaGetSymbolAddress((void**)&Ehi,  g_Ehi);
    cudaGetSymbolAddress((void**)&Elo,  g_Elo);
    cudaGetSymbolAddress((void**)&Chi,  g_Chi);
    cudaGetSymbolAddress((void**)&Clo,  g_Clo);
    cudaGetSymbolAddress((void**)&Bbhi, g_Bbhi);
    cudaGetSymbolAddress((void**)&Bblo, g_Bblo);
    cudaGetSymbolAddress((void**)&Dshi, g_Dshi);
    cudaGetSymbolAddress((void**)&Dslo, g_Dslo);

    cudaFuncSetAttribute(scan_persist, cudaFuncAttributeMaxDynamicSharedMemorySize, SM_TOT);

    const int n2 = DD*DD;
    const int g2 = (n2 + 255)/256;
    dim3 gg(DD/64, DD/32);   // 8 x 16 = 128 CTAs

    build_Y_kernel<<<g2, 256>>>(skew, gamma, dtp, Y_);
    init_EPT<<<g2, 256>>>(E_, P_, T_);

    // Taylor: T_{k} = T_{k-1} @ Y / k ; E += T_k ; P += T_k/(k+1)   (T ping-pong)
    float* Tin = T_; float* Tout = T2_;
    for (int k = 1; k <= NTAYLOR; k++) {
        gemm_f32<<<gg, 128>>>(Tin, Y_, Tout, E_, P_, nullptr,
                              1.0f/(float)k, 1.0f/(float)(k+1), 1);
        float* tmp = Tin; Tin = Tout; Tout = tmp;
    }
    // Doubling: P <- 0.5*E@P + 0.5*P ; E <- E@E   (ping-pong, T buffers reused)
    float *Ecur = E_, *Eoth = T_, *Pcur = P_, *Poth = T2_;
    for (int s = 0; s < NSQUARE; s++) {
        gemm_f32<<<gg, 128>>>(Ecur, Pcur, Poth, nullptr, nullptr, Pcur, 1.f, 0.f, 2);
        gemm_f32<<<gg, 128>>>(Ecur, Ecur, Eoth, nullptr, nullptr, nullptr, 1.f, 0.f, 0);
        float* tp = Pcur; Pcur = Poth; Poth = tp;
        float* te = Ecur; Ecur = Eoth; Eoth = te;
    }
    // B_bar(unscaled) = P @ B_ct ; dt applied in split
    gemm_small<<<16, 256>>>(Bb_, Pcur, B_ct);

    split_mat<<<g2, 256>>>(Ecur, Ehi, Elo, DD, DD, DD, DD, dtp, 0);
    split_mat<<<(64*DD + 255)/256, 256>>>(Cm, Chi, Clo, NOBS, DD, 64, DD, dtp, 0);
    split_mat<<<(DD*64 + 255)/256, 256>>>(Bb_, Bbhi, Bblo, DD, UDIM, DD, 64, dtp, 1);
    split_mat<<<(64*64 + 255)/256, 256>>>(Dm, Dshi, Dslo, NOBS, UDIM, 64, 64, dtp, 1);

    reset_barrier<<<1, 1>>>();

    float* Zo = (float*)d_out;
    float* Yo = (float*)d_out + (size_t)TT*BB*DD;
    scan_persist<<<NCTA, 128, SM_TOT>>>(z_dyn, U, Zo, Yo,
                                        Ehi, Elo, Bbhi, Bblo, Chi, Clo, Dshi, Dslo);
}

// round 6
// speedup vs baseline: 2.7634x; 1.0944x over previous
#include <cuda_runtime.h>
#include <cuda_bf16.h>
#include <math.h>
#include <stdint.h>

#define DD   512
#define BB   512
#define TT   256
#define UDIM 32
#define NOBS 50
#define NTAYLOR 10
#define NSQUARE 2
#define NCTA 144

// ---------------- device scratch ----------------
__device__ float g_Y [DD*DD];
__device__ float g_E [DD*DD];
__device__ float g_P [DD*DD];
__device__ float g_T [DD*DD];
__device__ float g_T2[DD*DD];
__device__ float g_Bb[DD*UDIM];

__device__ __nv_bfloat16 g_Ehi [DD*DD];
__device__ __nv_bfloat16 g_Elo [DD*DD];
__device__ __nv_bfloat16 g_Chi [64*DD];
__device__ __nv_bfloat16 g_Clo [64*DD];
__device__ __nv_bfloat16 g_Bbhi[DD*64];
__device__ __nv_bfloat16 g_Bblo[DD*64];
__device__ __nv_bfloat16 g_Dshi[64*64];
__device__ __nv_bfloat16 g_Dslo[64*64];

__device__ __nv_bfloat16 g_Zh[2*BB*DD];
__device__ __nv_bfloat16 g_Zl[2*BB*DD];
__device__ __nv_bfloat16 g_Uh[(size_t)TT*BB*64];
__device__ __nv_bfloat16 g_Ul[(size_t)TT*BB*64];

__device__ unsigned g_count;

// ---------------- helpers ----------------
__device__ __forceinline__ uint32_t smem_u32(const void* p) {
    uint32_t a;
    asm("{ .reg .u64 t; cvta.to.shared.u64 t, %1; cvt.u32.u64 %0, t; }" : "=r"(a) : "l"(p));
    return a;
}
#define SWZ(o) ((o) ^ (((o) >> 3) & 0x70))

__device__ __forceinline__ void ldmx4(uint32_t r[4], uint32_t addr) {
    asm volatile("ldmatrix.sync.aligned.m8n8.x4.shared.b16 {%0,%1,%2,%3}, [%4];"
        : "=r"(r[0]), "=r"(r[1]), "=r"(r[2]), "=r"(r[3]) : "r"(addr));
}
__device__ __forceinline__ void mma16816(float acc[4], const uint32_t a[4],
                                          uint32_t b0, uint32_t b1) {
    asm volatile("mma.sync.aligned.m16n8k16.row.col.f32.bf16.bf16.f32 "
        "{%0,%1,%2,%3},{%4,%5,%6,%7},{%8,%9},{%0,%1,%2,%3};"
        : "+f"(acc[0]), "+f"(acc[1]), "+f"(acc[2]), "+f"(acc[3])
        : "r"(a[0]), "r"(a[1]), "r"(a[2]), "r"(a[3]), "r"(b0), "r"(b1));
}

// ---------------- setup kernels ----------------
__global__ void build_Y_kernel(const float* __restrict__ skew, const float* __restrict__ gamma,
                               const float* __restrict__ dtp, float* __restrict__ Y)
{
    int idx = blockIdx.x*256 + threadIdx.x;
    if (idx >= DD*DD) return;
    int i = idx >> 9, j = idx & (DD-1);
    float v;
    if (i < j)      v =  skew[i*(DD-1) - (i*(i-1))/2 + (j-i-1)];
    else if (i > j) v = -skew[j*(DD-1) - (j*(j-1))/2 + (i-j-1)];
    else { float g = gamma[i]; v = -(fmaxf(g,0.f) + log1pf(expf(-fabsf(g)))); }
    Y[idx] = v * (dtp[0] * (1.0f/(float)(1<<NSQUARE)));
}
__global__ void init_EPT(float* E, float* P, float* Tm) {
    int idx = blockIdx.x*256 + threadIdx.x;
    if (idx >= DD*DD) return;
    float v = ((idx>>9) == (idx&(DD-1))) ? 1.f : 0.f;
    E[idx]=v; P[idx]=v; Tm[idx]=v;
}
__global__ void reset_barrier() { g_count = 0; }

// fp32 GEMM 32x64 tile, 256 threads, smem double-buffered.
// mode 1 (taylor): tv=acc*alpha; C=tv; Eacc+=tv; Pacc+=tv*invk1
// mode 3 (double): z==0: C = 0.5*acc(E@P) + 0.5*Pin ; z==1: C2 = acc(E@E)
__global__ void __launch_bounds__(256) gemm_setup(
    const float* __restrict__ A, const float* __restrict__ Bm,
    float* __restrict__ C, float* __restrict__ C2,
    float* __restrict__ Eacc, float* __restrict__ Pacc,
    const float* __restrict__ Pin, float alpha, float invk1, int mode)
{
    __shared__ float As[2][16][32];
    __shared__ float Bs[2][16][64];
    const int tid = threadIdx.x;
    const int i0 = blockIdx.y*32, j0 = blockIdx.x*64;
    const int z = blockIdx.z;
    const float* Bp = (mode == 3 && z == 1) ? A : Bm;

    const int ar = tid >> 2, akg = tid & 3;   // A loader (tid<128)
    const int br = tid >> 4, bc = tid & 15;   // B loader
    const bool la = tid < 128;
    float4 pa = make_float4(0,0,0,0), pb;
    if (la) pa = *reinterpret_cast<const float4*>(A + (size_t)(i0+ar)*DD + akg*4);
    pb = *reinterpret_cast<const float4*>(Bp + (size_t)br*DD + j0 + bc*4);
    if (la) {
        As[0][akg*4+0][ar]=pa.x; As[0][akg*4+1][ar]=pa.y;
        As[0][akg*4+2][ar]=pa.z; As[0][akg*4+3][ar]=pa.w;
    }
    *reinterpret_cast<float4*>(&Bs[0][br][bc*4]) = pb;
    __syncthreads();

    const int tm = tid >> 4, tn = tid & 15;
    float acc[2][4] = {};
    for (int kt = 0; kt < DD/16; kt++) {
        int cur = kt & 1;
        if (kt + 1 < DD/16) {
            int k0 = (kt+1)*16;
            if (la) pa = *reinterpret_cast<const float4*>(A + (size_t)(i0+ar)*DD + k0 + akg*4);
            pb = *reinterpret_cast<const float4*>(Bp + (size_t)(k0+br)*DD + j0 + bc*4);
        }
        #pragma unroll
        for (int k = 0; k < 16; k++) {
            float2 a = *reinterpret_cast<const float2*>(&As[cur][k][tm*2]);
            float4 b = *reinterpret_cast<const float4*>(&Bs[cur][k][tn*4]);
            acc[0][0]+=a.x*b.x; acc[0][1]+=a.x*b.y; acc[0][2]+=a.x*b.z; acc[0][3]+=a.x*b.w;
            acc[1][0]+=a.y*b.x; acc[1][1]+=a.y*b.y; acc[1][2]+=a.y*b.z; acc[1][3]+=a.y*b.w;
        }
        if (kt + 1 < DD/16) {
            int nxt = cur ^ 1;
            if (la) {
                As[nxt][akg*4+0][ar]=pa.x; As[nxt][akg*4+1][ar]=pa.y;
                As[nxt][akg*4+2][ar]=pa.z; As[nxt][akg*4+3][ar]=pa.w;
            }
            *reinterpret_cast<float4*>(&Bs[nxt][br][bc*4]) = pb;
        }
        __syncthreads();
    }
    #pragma unroll
    for (int r = 0; r < 2; r++) {
        int row = i0 + tm*2 + r;
        #pragma unroll
        for (int j = 0; j < 4; j++) {
            int idx = row*DD + j0 + tn*4 + j;
            float t = acc[r][j];
            if (mode == 1) {
                float tv = t*alpha; C[idx] = tv; Eacc[idx] += tv; Pacc[idx] += tv*invk1;
            } else {
                if (z == 0) C[idx] = 0.5f*t + 0.5f*Pin[idx];
                else        C2[idx] = t;
            }
        }
    }
}

// B_bar = P @ B_ct  (512x32x512)
__global__ void gemm_small(float* __restrict__ C, const float* __restrict__ A,
                           const float* __restrict__ Bm)
{
    __shared__ float As[32][33];
    __shared__ float Bs[32][33];
    int tx = threadIdx.x & 15, ty = threadIdx.x >> 4;
    int i0 = blockIdx.x*32;
    float a00=0,a01=0,a10=0,a11=0;
    for (int k0 = 0; k0 < DD; k0 += 32) {
        for (int u = threadIdx.x; u < 32*32; u += 256) {
            int r = u>>5, c = u&31;
            As[r][c] = A[(size_t)(i0+r)*DD + k0+c];
            Bs[r][c] = Bm[(size_t)(k0+r)*UDIM + c];
        }
        __syncthreads();
        #pragma unroll
        for (int k = 0; k < 32; k++) {
            float x0=As[ty*2][k], x1=As[ty*2+1][k];
            float y0=Bs[k][tx*2], y1=Bs[k][tx*2+1];
            a00+=x0*y0; a01+=x0*y1; a10+=x1*y0; a11+=x1*y1;
        }
        __syncthreads();
    }
    C[(size_t)(i0+ty*2+0)*UDIM + tx*2+0]=a00;
    C[(size_t)(i0+ty*2+0)*UDIM + tx*2+1]=a01;
    C[(size_t)(i0+ty*2+1)*UDIM + tx*2+0]=a10;
    C[(size_t)(i0+ty*2+1)*UDIM + tx*2+1]=a11;
}

// split src (rs x cs) into padded (rd x cd) bf16 hi/lo, optional *dt
__global__ void split_mat(const float* __restrict__ src, __nv_bfloat16* hi, __nv_bfloat16* lo,
                          int rs, int cs, int rd, int cd, const float* dtp, int usedt)
{
    int idx = blockIdx.x*256 + threadIdx.x;
    if (idx >= rd*cd) return;
    int r = idx / cd, c = idx % cd;
    float v = (r < rs && c < cs) ? src[(size_t)r*cs + c] : 0.f;
    if (usedt) v *= dtp[0];
    __nv_bfloat16 h = __float2bfloat16(v);
    hi[idx] = h;
    lo[idx] = __float2bfloat16(v - __bfloat162float(h));
}

// ---------------- persistent mma scan ----------------
#define SM_BH   0u
#define SM_BL   32768u
#define SM_B2H  65536u
#define SM_B2L  69632u
#define SM_ZR   73728u
#define SM_TOT  120832u

__device__ __forceinline__ void gb_arrive() {
    __syncthreads();
    if (threadIdx.x == 0) { __threadfence(); atomicAdd(&g_count, 1u); }
}
__device__ __forceinline__ void gb_wait(unsigned want) {
    if (threadIdx.x == 0) {
        while (*(volatile unsigned*)&g_count < want) { }
        __threadfence();
    }
    __syncthreads();
}

__global__ void __launch_bounds__(128) scan_persist(
    float* __restrict__ Zo, float* __restrict__ Yo,
    const __nv_bfloat16* __restrict__ Ehi,  const __nv_bfloat16* __restrict__ Elo,
    const __nv_bfloat16* __restrict__ Bbhi, const __nv_bfloat16* __restrict__ Bblo,
    const __nv_bfloat16* __restrict__ Chi,  const __nv_bfloat16* __restrict__ Clo,
    const __nv_bfloat16* __restrict__ Dshi, const __nv_bfloat16* __restrict__ Dslo,
    __nv_bfloat16* __restrict__ Zh, __nv_bfloat16* __restrict__ Zl,
    const __nv_bfloat16* __restrict__ Uh, const __nv_bfloat16* __restrict__ Ul)
{
    extern __shared__ __align__(1024) char smem[];
    const int tid = threadIdx.x;
    const int lane = tid & 31;
    const int w = tid >> 5;
    const int wm = (w & 1) * 32;
    const int wn = (w >> 1) * 16;
    const int blk = blockIdx.x;
    const bool isZ = blk < 128;

    int m0, n0;
    const __nv_bfloat16 *Bh_g, *Bl_g, *B2h_g, *B2l_g;
    if (isZ) {
        m0 = (blk >> 4) * 64; n0 = (blk & 15) * 32;
        Bh_g = Ehi; Bl_g = Elo; B2h_g = Bbhi; B2l_g = Bblo;
    } else {
        int local = blk - 128;
        m0 = (local >> 1) * 64; n0 = (local & 1) * 32;
        Bh_g = Chi; Bl_g = Clo; B2h_g = Dshi; B2l_g = Dslo;
    }

    const uint32_t sb = smem_u32(smem);

    // resident B operand
    #pragma unroll
    for (int i = 0; i < 16; i++) {
        int idx = i*128 + tid;
        int r = idx >> 6, g = idx & 63;
        uint32_t soff = (uint32_t)((g >> 3)*4096) + SWZ((uint32_t)(r*128 + (g & 7)*16));
        *reinterpret_cast<uint4*>(smem + SM_BH + soff) =
            *reinterpret_cast<const uint4*>(Bh_g + (size_t)(n0 + r)*DD + g*8);
        *reinterpret_cast<uint4*>(smem + SM_BL + soff) =
            *reinterpret_cast<const uint4*>(Bl_g + (size_t)(n0 + r)*DD + g*8);
    }
    #pragma unroll
    for (int i = 0; i < 2; i++) {
        int idx = i*128 + tid;
        int r = idx >> 3, g = idx & 7;
        uint32_t soff = SWZ((uint32_t)(r*128 + g*16));
        *reinterpret_cast<uint4*>(smem + SM_B2H + soff) =
            *reinterpret_cast<const uint4*>(B2h_g + (size_t)(n0 + r)*64 + g*8);
        *reinterpret_cast<uint4*>(smem + SM_B2L + soff) =
            *reinterpret_cast<const uint4*>(B2l_g + (size_t)(n0 + r)*64 + g*8);
    }
    __syncthreads();

    const uint32_t aoff0 = (uint32_t)((wm + 0  + (lane & 15))*128 + ((lane >> 4) << 4));
    const uint32_t aoff1 = (uint32_t)((wm + 16 + (lane & 15))*128 + ((lane >> 4) << 4));
    const uint32_t boff  = (uint32_t)((wn + (lane & 7) + ((lane >> 4) & 1)*8)*128 + ((lane >> 3) & 1)*16);
    const int ldr = tid >> 3;     // 0..15  (row pair base: idx = i*128+tid → r=idx>>3)
    const int ldg = tid & 7;

    for (int t = 0; t <= TT; t++) {
        const bool active = isZ ? (t < TT) : (t >= 1);
        float acc[2][2][4];
        if (active) {
            #pragma unroll
            for (int a = 0; a < 2; a++)
                #pragma unroll
                for (int b = 0; b < 2; b++)
                    #pragma unroll
                    for (int c = 0; c < 4; c++) acc[a][b][c] = 0.f;

            // --- u slab (independent of Z[t-1]) into ring slot0 ---
            int tu = isZ ? t : (t-1);
            const __nv_bfloat16* uh = Uh + (size_t)tu*BB*64;
            const __nv_bfloat16* ul = Ul + (size_t)tu*BB*64;
            uint32_t slot0 = sb + SM_ZR;
            #pragma unroll
            for (int i = 0; i < 4; i++) {
                int r = i*16 + ldr;
                uint32_t off = SWZ((uint32_t)(r*128 + ldg*16));
                *reinterpret_cast<uint4*>(smem + SM_ZR + off) =
                    *reinterpret_cast<const uint4*>(uh + (size_t)(m0 + r)*64 + ldg*8);
                *reinterpret_cast<uint4*>(smem + SM_ZR + 8192u + off) =
                    *reinterpret_cast<const uint4*>(ul + (size_t)(m0 + r)*64 + ldg*8);
            }
            __syncthreads();
            {
                uint32_t bb = sb + SM_B2H;
                #pragma unroll
                for (int k16 = 0; k16 < 4; k16++) {
                    uint32_t ah0[4], al0[4], ah1[4], al1[4], bh[4], bl[4];
                    uint32_t ad0 = slot0 + SWZ(aoff0 + (uint32_t)k16*32);
                    ldmx4(ah0, ad0); ldmx4(al0, ad0 + 8192u);
                    uint32_t ad1 = slot0 + SWZ(aoff1 + (uint32_t)k16*32);
                    ldmx4(ah1, ad1); ldmx4(al1, ad1 + 8192u);
                    uint32_t bd = bb + SWZ(boff + (uint32_t)k16*32);
                    ldmx4(bh, bd); ldmx4(bl, bd + 4096u);
                    mma16816(acc[0][0], ah0, bh[0], bh[1]);
                    mma16816(acc[0][1], ah0, bh[2], bh[3]);
                    mma16816(acc[1][0], ah1, bh[0], bh[1]);
                    mma16816(acc[1][1], ah1, bh[2], bh[3]);
                    mma16816(acc[0][0], al0, bh[0], bh[1]);
                    mma16816(acc[0][1], al0, bh[2], bh[3]);
                    mma16816(acc[1][0], al1, bh[0], bh[1]);
                    mma16816(acc[1][1], al1, bh[2], bh[3]);
                    mma16816(acc[0][0], ah0, bl[0], bl[1]);
                    mma16816(acc[0][1], ah0, bl[2], bl[3]);
                    mma16816(acc[1][0], ah1, bl[0], bl[1]);
                    mma16816(acc[1][1], ah1, bl[2], bl[3]);
                }
            }
        }
        if (t > 0) gb_wait((unsigned)NCTA * (unsigned)t);

        if (active) {
            const __nv_bfloat16* zh = Zh + (size_t)(t & 1)*BB*DD;
            const __nv_bfloat16* zl = Zl + (size_t)(t & 1)*BB*DD;
            uint4 ph[4], pl[4];
            // prefetch slab 0
            #pragma unroll
            for (int i = 0; i < 4; i++) {
                int r = i*16 + ldr;
                ph[i] = *reinterpret_cast<const uint4*>(zh + (size_t)(m0 + r)*DD + ldg*8);
                pl[i] = *reinterpret_cast<const uint4*>(zl + (size_t)(m0 + r)*DD + ldg*8);
            }
            // store slab0 into slot1 (slot for slab s = (s+1)&1)
            {
                uint32_t zb = sb + SM_ZR + 16384u;
                #pragma unroll
                for (int i = 0; i < 4; i++) {
                    int r = i*16 + ldr;
                    uint32_t off = SWZ((uint32_t)(r*128 + ldg*16));
                    *reinterpret_cast<uint4*>(smem + (zb - sb) + off) = ph[i];
                    *reinterpret_cast<uint4*>(smem + (zb - sb) + 8192u + off) = pl[i];
                }
            }
            __syncthreads();

            for (int s = 0; s < 8; s++) {
                if (s + 1 < 8) {
                    #pragma unroll
                    for (int i = 0; i < 4; i++) {
                        int r = i*16 + ldr;
                        ph[i] = *reinterpret_cast<const uint4*>(zh + (size_t)(m0 + r)*DD + (s+1)*64 + ldg*8);
                        pl[i] = *reinterpret_cast<const uint4*>(zl + (size_t)(m0 + r)*DD + (s+1)*64 + ldg*8);
                    }
                }
                {
                    uint32_t zb = sb + SM_ZR + (uint32_t)((s+1) & 1)*16384u;
                    uint32_t bb = sb + SM_BH + (uint32_t)s*4096u;
                    #pragma unroll
                    for (int k16 = 0; k16 < 4; k16++) {
                        uint32_t ah0[4], al0[4], ah1[4], al1[4], bh[4], bl[4];
                        uint32_t ad0 = zb + SWZ(aoff0 + (uint32_t)k16*32);
                        ldmx4(ah0, ad0); ldmx4(al0, ad0 + 8192u);
                        uint32_t ad1 = zb + SWZ(aoff1 + (uint32_t)k16*32);
                        ldmx4(ah1, ad1); ldmx4(al1, ad1 + 8192u);
                        uint32_t bd = bb + SWZ(boff + (uint32_t)k16*32);
                        ldmx4(bh, bd); ldmx4(bl, bd + 32768u);
                        mma16816(acc[0][0], ah0, bh[0], bh[1]);
                        mma16816(acc[0][1], ah0, bh[2], bh[3]);
                        mma16816(acc[1][0], ah1, bh[0], bh[1]);
                        mma16816(acc[1][1], ah1, bh[2], bh[3]);
                        mma16816(acc[0][0], al0, bh[0], bh[1]);
                        mma16816(acc[0][1], al0, bh[2], bh[3]);
                        mma16816(acc[1][0], al1, bh[0], bh[1]);
                        mma16816(acc[1][1], al1, bh[2], bh[3]);
                        mma16816(acc[0][0], ah0, bl[0], bl[1]);
                        mma16816(acc[0][1], ah0, bl[2], bl[3]);
                        mma16816(acc[1][0], ah1, bl[0], bl[1]);
                        mma16816(acc[1][1], ah1, bl[2], bl[3]);
                    }
                }
                __syncthreads();
                if (s + 1 < 8) {
                    uint32_t zb = sb + SM_ZR + (uint32_t)(s & 1)*16384u;
                    #pragma unroll
                    for (int i = 0; i < 4; i++) {
                        int r = i*16 + ldr;
                        uint32_t off = SWZ((uint32_t)(r*128 + ldg*16));
                        *reinterpret_cast<uint4*>(smem + (zb - sb) + off) = ph[i];
                        *reinterpret_cast<uint4*>(smem + (zb - sb) + 8192u + off) = pl[i];
                    }
                    __syncthreads();
                }
            }

            // epilogue
            int r0 = m0 + wm + (lane >> 2);
            int c0 = n0 + wn + (lane & 3)*2;
            if (isZ) {
                float* Zout = Zo + (size_t)t*BB*DD;
                __nv_bfloat16* zhn = Zh + (size_t)((t+1) & 1)*BB*DD;
                __nv_bfloat16* zln = Zl + (size_t)((t+1) & 1)*BB*DD;
                #pragma unroll
                for (int mi = 0; mi < 2; mi++)
                    #pragma unroll
                    for (int ni = 0; ni < 2; ni++) {
                        int row = r0 + mi*16, col = c0 + ni*8;
                        float a0 = acc[mi][ni][0], a1 = acc[mi][ni][1];
                        float a2 = acc[mi][ni][2], a3 = acc[mi][ni][3];
                        *reinterpret_cast<float2*>(Zout + (size_t)row*DD + col)     = make_float2(a0, a1);
                        *reinterpret_cast<float2*>(Zout + (size_t)(row+8)*DD + col) = make_float2(a2, a3);
                        __nv_bfloat162 h0 = __floats2bfloat162_rn(a0, a1);
                        __nv_bfloat162 l0 = __floats2bfloat162_rn(a0 - __bfloat162float(h0.x),
                                                                  a1 - __bfloat162float(h0.y));
                        __nv_bfloat162 h1 = __floats2bfloat162_rn(a2, a3);
                        __nv_bfloat162 l1 = __floats2bfloat162_rn(a2 - __bfloat162float(h1.x),
                                                                  a3 - __bfloat162float(h1.y));
                        *reinterpret_cast<__nv_bfloat162*>(zhn + (size_t)row*DD + col)     = h0;
                        *reinterpret_cast<__nv_bfloat162*>(zln + (size_t)row*DD + col)     = l0;
                        *reinterpret_cast<__nv_bfloat162*>(zhn + (size_t)(row+8)*DD + col) = h1;
                        *reinterpret_cast<__nv_bfloat162*>(zln + (size_t)(row+8)*DD + col) = l1;
                    }
            } else {
                float* Yout = Yo + (size_t)(t-1)*BB*NOBS;
                #pragma unroll
                for (int mi = 0; mi < 2; mi++)
                    #pragma unroll
                    for (int ni = 0; ni < 2; ni++) {
                        int row = r0 + mi*16, col = c0 + ni*8;
                        if (col < NOBS)     Yout[(size_t)row*NOBS + col]       = acc[mi][ni][0];
                        if (col + 1 < NOBS) Yout[(size_t)row*NOBS + col + 1]   = acc[mi][ni][1];
                        if (col < NOBS)     Yout[(size_t)(row+8)*NOBS + col]   = acc[mi][ni][2];
                        if (col + 1 < NOBS) Yout[(size_t)(row+8)*NOBS + col+1] = acc[mi][ni][3];
                    }
            }
        }
        if (t < TT) gb_arrive();
    }
}

// ---------------- host orchestration ----------------
extern "C" void kernel_launch(void* const* d_in, const int* in_sizes, int n_in,
                              void* d_out, int out_size)
{
    const float* z_dyn = (const float*)d_in[0];
    const float* dtp   = (const float*)d_in[2];
    const float* U     = (const float*)d_in[3];
    const float* skew  = (const float*)d_in[4];
    const float* gamma = (const float*)d_in[5];
    const float* B_ct  = (const float*)d_in[6];
    const float* Cm    = (const float*)d_in[7];
    const float* Dm    = (const float*)d_in[8];

    float *Y_, *E_, *P_, *T_, *T2_, *Bb_;
    cudaGetSymbolAddress((void**)&Y_,  g_Y);
    cudaGetSymbolAddress((void**)&E_,  g_E);
    cudaGetSymbolAddress((void**)&P_,  g_P);
    cudaGetSymbolAddress((void**)&T_,  g_T);
    cudaGetSymbolAddress((void**)&T2_, g_T2);
    cudaGetSymbolAddress((void**)&Bb_, g_Bb);

    __nv_bfloat16 *Ehi, *Elo, *Chi, *Clo, *Bbhi, *Bblo, *Dshi, *Dslo, *Zh, *Zl, *Uh, *Ul;
    cudaGetSymbolAddress((void**)&Ehi,  g_Ehi);
    cudaGetSymbolAddress((void**)&Elo,  g_Elo);
    cudaGetSymbolAddress((void**)&Chi,  g_Chi);
    cudaGetSymbolAddress((void**)&Clo,  g_Clo);
    cudaGetSymbolAddress((void**)&Bbhi, g_Bbhi);
    cudaGetSymbolAddress((void**)&Bblo, g_Bblo);
    cudaGetSymbolAddress((void**)&Dshi, g_Dshi);
    cudaGetSymbolAddress((void**)&Dslo, g_Dslo);
    cudaGetSymbolAddress((void**)&Zh,   g_Zh);
    cudaGetSymbolAddress((void**)&Zl,   g_Zl);
    cudaGetSymbolAddress((void**)&Uh,   g_Uh);
    cudaGetSymbolAddress((void**)&Ul,   g_Ul);

    cudaFuncSetAttribute(scan_persist, cudaFuncAttributeMaxDynamicSharedMemorySize, SM_TOT);

    const int n2 = DD*DD;
    const int g2 = (n2 + 255)/256;
    dim3 gg(8, 16, 1);
    dim3 gg2(8, 16, 2);

    build_Y_kernel<<<g2, 256>>>(skew, gamma, dtp, Y_);
    init_EPT<<<g2, 256>>>(E_, P_, T_);

    float* Tin = T_; float* Tout = T2_;
    for (int k = 1; k <= NTAYLOR; k++) {
        gemm_setup<<<gg, 256>>>(Tin, Y_, Tout, nullptr, E_, P_, nullptr,
                                1.0f/(float)k, 1.0f/(float)(k+1), 1);
        float* tmp = Tin; Tin = Tout; Tout = tmp;
    }
    // doubling x2 (paired launches): P' = 0.5 E@P + 0.5 P ; E' = E@E
    gemm_setup<<<gg2, 256>>>(E_, P_, T2_, T_, nullptr, nullptr, P_, 1.f, 0.f, 3);
    gemm_setup<<<gg2, 256>>>(T_, T2_, P_, E_, nullptr, nullptr, T2_, 1.f, 0.f, 3);

    gemm_small<<<16, 256>>>(Bb_, P_, B_ct);

    split_mat<<<g2, 256>>>(E_, Ehi, Elo, DD, DD, DD, DD, dtp, 0);
    split_mat<<<(64*DD + 255)/256, 256>>>(Cm, Chi, Clo, NOBS, DD, 64, DD, dtp, 0);
    split_mat<<<(DD*64 + 255)/256, 256>>>(Bb_, Bbhi, Bblo, DD, UDIM, DD, 64, dtp, 1);
    split_mat<<<(64*64 + 255)/256, 256>>>(Dm, Dshi, Dslo, NOBS, UDIM, 64, 64, dtp, 1);
    split_mat<<<g2, 256>>>(z_dyn, Zh, Zl, BB, DD, BB, DD, dtp, 0);
    split_mat<<<(TT*BB*64 + 255)/256, 256>>>(U, Uh, Ul, TT*BB, UDIM, TT*BB, 64, dtp, 0);

    reset_barrier<<<1, 1>>>();

    float* Zo = (float*)d_out;
    float* Yo = (float*)d_out + (size_t)TT*BB*DD;
    scan_persist<<<NCTA, 128, SM_TOT>>>(Zo, Yo,
                                        Ehi, Elo, Bbhi, Bblo, Chi, Clo, Dshi, Dslo,
                                        Zh, Zl, Uh, Ul);
}

// round 7
// speedup vs baseline: 2.9871x; 1.0810x over previous
#include <cuda_runtime.h>
#include <cuda_bf16.h>
#include <math.h>
#include <stdint.h>

#define DD   512
#define BB   512
#define TT   256
#define UDIM 32
#define NOBS 50
#define NTAYLOR 10
#define NSQUARE 2
#define NCTA 144

// ---------------- device scratch ----------------
__device__ float g_Y [DD*DD];
__device__ float g_E [DD*DD];
__device__ float g_P [DD*DD];
__device__ float g_T [DD*DD];
__device__ float g_T2[DD*DD];
__device__ float g_Bb[DD*UDIM];

__device__ __nv_bfloat16 g_Ehi [DD*DD];
__device__ __nv_bfloat16 g_Elo [DD*DD];
__device__ __nv_bfloat16 g_Chi [64*DD];
__device__ __nv_bfloat16 g_Clo [64*DD];
__device__ __nv_bfloat16 g_Bbhi[DD*64];
__device__ __nv_bfloat16 g_Bblo[DD*64];
__device__ __nv_bfloat16 g_Dshi[64*64];
__device__ __nv_bfloat16 g_Dslo[64*64];

// transposed-split operands for setup GEMMs
__device__ __nv_bfloat16 g_Yht [DD*DD];
__device__ __nv_bfloat16 g_Ylt [DD*DD];
__device__ __nv_bfloat16 g_Eht [DD*DD];
__device__ __nv_bfloat16 g_Elt [DD*DD];
__device__ __nv_bfloat16 g_Pht [DD*DD];
__device__ __nv_bfloat16 g_Plt [DD*DD];
__device__ __nv_bfloat16 g_Pht2[DD*DD];
__device__ __nv_bfloat16 g_Plt2[DD*DD];

__device__ __nv_bfloat16 g_Zh[2*BB*DD];
__device__ __nv_bfloat16 g_Zl[2*BB*DD];
__device__ __nv_bfloat16 g_Uh[(size_t)TT*BB*64];
__device__ __nv_bfloat16 g_Ul[(size_t)TT*BB*64];

__device__ unsigned g_count;

// ---------------- helpers ----------------
__device__ __forceinline__ uint32_t smem_u32(const void* p) {
    uint32_t a;
    asm("{ .reg .u64 t; cvta.to.shared.u64 t, %1; cvt.u32.u64 %0, t; }" : "=r"(a) : "l"(p));
    return a;
}
#define SWZ(o) ((o) ^ (((o) >> 3) & 0x70))

__device__ __forceinline__ void ldmx4(uint32_t r[4], uint32_t addr) {
    asm volatile("ldmatrix.sync.aligned.m8n8.x4.shared.b16 {%0,%1,%2,%3}, [%4];"
        : "=r"(r[0]), "=r"(r[1]), "=r"(r[2]), "=r"(r[3]) : "r"(addr));
}
__device__ __forceinline__ void mma16816(float acc[4], const uint32_t a[4],
                                          uint32_t b0, uint32_t b1) {
    asm volatile("mma.sync.aligned.m16n8k16.row.col.f32.bf16.bf16.f32 "
        "{%0,%1,%2,%3},{%4,%5,%6,%7},{%8,%9},{%0,%1,%2,%3};"
        : "+f"(acc[0]), "+f"(acc[1]), "+f"(acc[2]), "+f"(acc[3])
        : "r"(a[0]), "r"(a[1]), "r"(a[2]), "r"(a[3]), "r"(b0), "r"(b1));
}
__device__ __forceinline__ void split4(float4 v, uint32_t hi_a, uint32_t lo_a) {
    __nv_bfloat162 h0 = __floats2bfloat162_rn(v.x, v.y);
    __nv_bfloat162 h1 = __floats2bfloat162_rn(v.z, v.w);
    __nv_bfloat162 l0 = __floats2bfloat162_rn(v.x - __bfloat162float(h0.x), v.y - __bfloat162float(h0.y));
    __nv_bfloat162 l1 = __floats2bfloat162_rn(v.z - __bfloat162float(h1.x), v.w - __bfloat162float(h1.y));
    uint32_t h0u = *(uint32_t*)&h0, h1u = *(uint32_t*)&h1;
    uint32_t l0u = *(uint32_t*)&l0, l1u = *(uint32_t*)&l1;
    asm volatile("st.shared.v2.b32 [%0], {%1,%2};" :: "r"(hi_a), "r"(h0u), "r"(h1u) : "memory");
    asm volatile("st.shared.v2.b32 [%0], {%1,%2};" :: "r"(lo_a), "r"(l0u), "r"(l1u) : "memory");
}

// ---------------- setup elementwise kernels ----------------
__global__ void build_Y_kernel(const float* __restrict__ skew, const float* __restrict__ gamma,
                               const float* __restrict__ dtp, float* __restrict__ Y)
{
    int idx = blockIdx.x*256 + threadIdx.x;
    if (idx >= DD*DD) return;
    int i = idx >> 9, j = idx & (DD-1);
    float v;
    if (i < j)      v =  skew[i*(DD-1) - (i*(i-1))/2 + (j-i-1)];
    else if (i > j) v = -skew[j*(DD-1) - (j*(j-1))/2 + (i-j-1)];
    else { float g = gamma[i]; v = -(fmaxf(g,0.f) + log1pf(expf(-fabsf(g)))); }
    Y[idx] = v * (dtp[0] * (1.0f/(float)(1<<NSQUARE)));
}
__global__ void init_EPT(float* E, float* P, float* Tm) {
    int idx = blockIdx.x*256 + threadIdx.x;
    if (idx >= DD*DD) return;
    float v = ((idx>>9) == (idx&(DD-1))) ? 1.f : 0.f;
    E[idx]=v; P[idx]=v; Tm[idx]=v;
}
__global__ void reset_barrier() { g_count = 0; }

// split + transpose: out[c*DD + r] = split(src[r*DD + c])
__global__ void split_T(const float* __restrict__ src,
                        __nv_bfloat16* __restrict__ h, __nv_bfloat16* __restrict__ l)
{
    int idx = blockIdx.x*256 + threadIdx.x;
    if (idx >= DD*DD) return;
    int r = idx >> 9, c = idx & (DD-1);
    float v = src[idx];
    __nv_bfloat16 hh = __float2bfloat16(v);
    h[(size_t)c*DD + r] = hh;
    l[(size_t)c*DD + r] = __float2bfloat16(v - __bfloat162float(hh));
}

// split src (rs x cs) into padded (rd x cd) bf16 hi/lo, optional *dt
__global__ void split_mat(const float* __restrict__ src, __nv_bfloat16* hi, __nv_bfloat16* lo,
                          int rs, int cs, int rd, int cd, const float* dtp, int usedt)
{
    int idx = blockIdx.x*256 + threadIdx.x;
    if (idx >= rd*cd) return;
    int r = idx / cd, c = idx % cd;
    float v = (r < rs && c < cs) ? src[(size_t)r*cs + c] : 0.f;
    if (usedt) v *= dtp[0];
    __nv_bfloat16 h = __float2bfloat16(v);
    hi[idx] = h;
    lo[idx] = __float2bfloat16(v - __bfloat162float(h));
}

// B_bar = P @ B_ct  (512x32x512), SIMT (tiny)
__global__ void gemm_small(float* __restrict__ C, const float* __restrict__ A,
                           const float* __restrict__ Bm)
{
    __shared__ float As[32][33];
    __shared__ float Bs[32][33];
    int tx = threadIdx.x & 15, ty = threadIdx.x >> 4;
    int i0 = blockIdx.x*32;
    float a00=0,a01=0,a10=0,a11=0;
    for (int k0 = 0; k0 < DD; k0 += 32) {
        for (int u = threadIdx.x; u < 32*32; u += 256) {
            int r = u>>5, c = u&31;
            As[r][c] = A[(size_t)(i0+r)*DD + k0+c];
            Bs[r][c] = Bm[(size_t)(k0+r)*UDIM + c];
        }
        __syncthreads();
        #pragma unroll
        for (int k = 0; k < 32; k++) {
            float x0=As[ty*2][k], x1=As[ty*2+1][k];
            float y0=Bs[k][tx*2], y1=Bs[k][tx*2+1];
            a00+=x0*y0; a01+=x0*y1; a10+=x1*y0; a11+=x1*y1;
        }
        __syncthreads();
    }
    C[(size_t)(i0+ty*2+0)*UDIM + tx*2+0]=a00;
    C[(size_t)(i0+ty*2+0)*UDIM + tx*2+1]=a01;
    C[(size_t)(i0+ty*2+1)*UDIM + tx*2+0]=a10;
    C[(size_t)(i0+ty*2+1)*UDIM + tx*2+1]=a11;
}

// ---------------- tensor-core setup GEMM ----------------
// C(MxN=512x512) = A(fp32) @ B, B given presplit-TRANSPOSED bf16 (Bop[n*DD+k]).
// CTA 64x32, 128 thr. mode 1: taylor (C0=acc*invk, E+=, P+=invk1*)
// mode 2: z0: C0 = 0.5 acc + 0.5 Pin, + transpose-split -> Th0/Tl0
//         z1: C1 = acc,               + transpose-split -> Th1/Tl1
// mode 3: same as 2 without transpose-split stores.
#define TC_BH  0u
#define TC_BL  32768u
#define TC_ZR  65536u
#define TC_TOT 98304u

__global__ void __launch_bounds__(128) gemm_tc(
    const float* __restrict__ A,
    const __nv_bfloat16* __restrict__ Bh0, const __nv_bfloat16* __restrict__ Bl0,
    const __nv_bfloat16* __restrict__ Bh1, const __nv_bfloat16* __restrict__ Bl1,
    float* __restrict__ C0, float* __restrict__ C1,
    float* __restrict__ Eacc, float* __restrict__ Pacc, const float* __restrict__ Pin,
    __nv_bfloat16* __restrict__ Th0, __nv_bfloat16* __restrict__ Tl0,
    __nv_bfloat16* __restrict__ Th1, __nv_bfloat16* __restrict__ Tl1,
    float invk, float invk1, int mode)
{
    extern __shared__ __align__(1024) char smem[];
    const int tid = threadIdx.x;
    const int lane = tid & 31;
    const int w = tid >> 5;
    const int wm = (w & 1) * 32;
    const int wn = (w >> 1) * 16;
    const int n0 = blockIdx.x * 32;
    const int m0 = blockIdx.y * 64;
    const int z  = blockIdx.z;

    const __nv_bfloat16* Bh = z ? Bh1 : Bh0;
    const __nv_bfloat16* Bl = z ? Bl1 : Bl0;

    const uint32_t sb = smem_u32(smem);

    // B prologue: 32 rows (n) x 512 (k) presplit bf16 -> 8 swizzled chunks
    #pragma unroll
    for (int i = 0; i < 16; i++) {
        int idx = i*128 + tid;
        int r = idx >> 6, g = idx & 63;
        uint32_t soff = (uint32_t)((g >> 3)*4096) + SWZ((uint32_t)(r*128 + (g & 7)*16));
        *reinterpret_cast<uint4*>(smem + TC_BH + soff) =
            *reinterpret_cast<const uint4*>(Bh + (size_t)(n0 + r)*DD + g*8);
        *reinterpret_cast<uint4*>(smem + TC_BL + soff) =
            *reinterpret_cast<const uint4*>(Bl + (size_t)(n0 + r)*DD + g*8);
    }

    const uint32_t aoff0 = (uint32_t)((wm + 0  + (lane & 15))*128 + ((lane >> 4) << 4));
    const uint32_t aoff1 = (uint32_t)((wm + 16 + (lane & 15))*128 + ((lane >> 4) << 4));
    const uint32_t boff  = (uint32_t)((wn + (lane & 7) + ((lane >> 4) & 1)*8)*128 + ((lane >> 3) & 1)*16);
    const int ldr = tid >> 4;      // 0..7
    const int lfq = tid & 15;      // 0..15

    float4 pf[8];
    #pragma unroll
    for (int i = 0; i < 8; i++) {
        int r = i*8 + ldr;
        pf[i] = *reinterpret_cast<const float4*>(A + (size_t)(m0 + r)*DD + lfq*4);
    }
    {
        uint32_t zb = sb + TC_ZR;
        #pragma unroll
        for (int i = 0; i < 8; i++) {
            int r = i*8 + ldr;
            uint32_t off = SWZ((uint32_t)(r*128 + lfq*8));
            split4(pf[i], zb + off, zb + 8192u + off);
        }
    }
    __syncthreads();

    float acc[2][2][4];
    #pragma unroll
    for (int a = 0; a < 2; a++)
        #pragma unroll
        for (int b = 0; b < 2; b++)
            #pragma unroll
            for (int c = 0; c < 4; c++) acc[a][b][c] = 0.f;

    for (int s = 0; s < 8; s++) {
        if (s + 1 < 8) {
            #pragma unroll
            for (int i = 0; i < 8; i++) {
                int r = i*8 + ldr;
                pf[i] = *reinterpret_cast<const float4*>(A + (size_t)(m0 + r)*DD + (s+1)*64 + lfq*4);
            }
        }
        {
            uint32_t zb = sb + TC_ZR + (uint32_t)(s & 1)*16384u;
            uint32_t bb = sb + TC_BH + (uint32_t)s*4096u;
            #pragma unroll
            for (int k16 = 0; k16 < 4; k16++) {
                uint32_t ah0[4], al0[4], ah1[4], al1[4], bh[4], bl[4];
                uint32_t ad0 = zb + SWZ(aoff0 + (uint32_t)k16*32);
                ldmx4(ah0, ad0); ldmx4(al0, ad0 + 8192u);
                uint32_t ad1 = zb + SWZ(aoff1 + (uint32_t)k16*32);
                ldmx4(ah1, ad1); ldmx4(al1, ad1 + 8192u);
                uint32_t bd = bb + SWZ(boff + (uint32_t)k16*32);
                ldmx4(bh, bd); ldmx4(bl, bd + 32768u);
                mma16816(acc[0][0], ah0, bh[0], bh[1]);
                mma16816(acc[0][1], ah0, bh[2], bh[3]);
                mma16816(acc[1][0], ah1, bh[0], bh[1]);
                mma16816(acc[1][1], ah1, bh[2], bh[3]);
                mma16816(acc[0][0], al0, bh[0], bh[1]);
                mma16816(acc[0][1], al0, bh[2], bh[3]);
                mma16816(acc[1][0], al1, bh[0], bh[1]);
                mma16816(acc[1][1], al1, bh[2], bh[3]);
                mma16816(acc[0][0], ah0, bl[0], bl[1]);
                mma16816(acc[0][1], ah0, bl[2], bl[3]);
                mma16816(acc[1][0], ah1, bl[0], bl[1]);
                mma16816(acc[1][1], ah1, bl[2], bl[3]);
            }
        }
        __syncthreads();
        if (s + 1 < 8) {
            uint32_t zb = sb + TC_ZR + (uint32_t)((s+1) & 1)*16384u;
            #pragma unroll
            for (int i = 0; i < 8; i++) {
                int r = i*8 + ldr;
                uint32_t off = SWZ((uint32_t)(r*128 + lfq*8));
                split4(pf[i], zb + off, zb + 8192u + off);
            }
            __syncthreads();
        }
    }

    // ---- epilogue ----
    int r0 = m0 + wm + (lane >> 2);
    int c0 = n0 + wn + (lane & 3)*2;
    float* Cw = z ? C1 : C0;
    __nv_bfloat16* Th = z ? Th1 : Th0;
    __nv_bfloat16* Tl = z ? Tl1 : Tl0;

    #pragma unroll
    for (int mi = 0; mi < 2; mi++) {
        #pragma unroll
        for (int ni = 0; ni < 2; ni++) {
            int row = r0 + mi*16, col = c0 + ni*8;
            #pragma unroll
            for (int h = 0; h < 2; h++) {      // h=0: row, h=1: row+8
                int rr = row + h*8;
                size_t idx = (size_t)rr*DD + col;
                float v0 = acc[mi][ni][h*2+0];
                float v1 = acc[mi][ni][h*2+1];
                if (mode == 1) {
                    v0 *= invk; v1 *= invk;
                    *reinterpret_cast<float2*>(Cw + idx) = make_float2(v0, v1);
                    float2 e = *reinterpret_cast<float2*>(Eacc + idx);
                    e.x += v0; e.y += v1;
                    *reinterpret_cast<float2*>(Eacc + idx) = e;
                    float2 p = *reinterpret_cast<float2*>(Pacc + idx);
                    p.x += v0*invk1; p.y += v1*invk1;
                    *reinterpret_cast<float2*>(Pacc + idx) = p;
                } else {
                    if (z == 0) {
                        float2 pin = *reinterpret_cast<const float2*>(Pin + idx);
                        v0 = 0.5f*v0 + 0.5f*pin.x;
                        v1 = 0.5f*v1 + 0.5f*pin.y;
                    }
                    *reinterpret_cast<float2*>(Cw + idx) = make_float2(v0, v1);
                    if (mode == 2) {
                        __nv_bfloat16 h0 = __float2bfloat16(v0);
                        __nv_bfloat16 h1 = __float2bfloat16(v1);
                        Th[(size_t)col*DD + rr]     = h0;
                        Tl[(size_t)col*DD + rr]     = __float2bfloat16(v0 - __bfloat162float(h0));
                        Th[(size_t)(col+1)*DD + rr] = h1;
                        Tl[(size_t)(col+1)*DD + rr] = __float2bfloat16(v1 - __bfloat162float(h1));
                    }
                }
            }
        }
    }
}

// ---------------- persistent mma scan (unchanged from R6) ----------------
#define SM_BH   0u
#define SM_BL   32768u
#define SM_B2H  65536u
#define SM_B2L  69632u
#define SM_ZR   73728u
#define SM_TOT  120832u

__device__ __forceinline__ void gb_arrive() {
    __syncthreads();
    if (threadIdx.x == 0) { __threadfence(); atomicAdd(&g_count, 1u); }
}
__device__ __forceinline__ void gb_wait(unsigned want) {
    if (threadIdx.x == 0) {
        while (*(volatile unsigned*)&g_count < want) { }
        __threadfence();
    }
    __syncthreads();
}

__global__ void __launch_bounds__(128) scan_persist(
    float* __restrict__ Zo, float* __restrict__ Yo,
    const __nv_bfloat16* __restrict__ Ehi,  const __nv_bfloat16* __restrict__ Elo,
    const __nv_bfloat16* __restrict__ Bbhi, const __nv_bfloat16* __restrict__ Bblo,
    const __nv_bfloat16* __restrict__ Chi,  const __nv_bfloat16* __restrict__ Clo,
    const __nv_bfloat16* __restrict__ Dshi, const __nv_bfloat16* __restrict__ Dslo,
    __nv_bfloat16* __restrict__ Zh, __nv_bfloat16* __restrict__ Zl,
    const __nv_bfloat16* __restrict__ Uh, const __nv_bfloat16* __restrict__ Ul)
{
    extern __shared__ __align__(1024) char smem[];
    const int tid = threadIdx.x;
    const int lane = tid & 31;
    const int w = tid >> 5;
    const int wm = (w & 1) * 32;
    const int wn = (w >> 1) * 16;
    const int blk = blockIdx.x;
    const bool isZ = blk < 128;

    int m0, n0;
    const __nv_bfloat16 *Bh_g, *Bl_g, *B2h_g, *B2l_g;
    if (isZ) {
        m0 = (blk >> 4) * 64; n0 = (blk & 15) * 32;
        Bh_g = Ehi; Bl_g = Elo; B2h_g = Bbhi; B2l_g = Bblo;
    } else {
        int local = blk - 128;
        m0 = (local >> 1) * 64; n0 = (local & 1) * 32;
        Bh_g = Chi; Bl_g = Clo; B2h_g = Dshi; B2l_g = Dslo;
    }

    const uint32_t sb = smem_u32(smem);

    #pragma unroll
    for (int i = 0; i < 16; i++) {
        int idx = i*128 + tid;
        int r = idx >> 6, g = idx & 63;
        uint32_t soff = (uint32_t)((g >> 3)*4096) + SWZ((uint32_t)(r*128 + (g & 7)*16));
        *reinterpret_cast<uint4*>(smem + SM_BH + soff) =
            *reinterpret_cast<const uint4*>(Bh_g + (size_t)(n0 + r)*DD + g*8);
        *reinterpret_cast<uint4*>(smem + SM_BL + soff) =
            *reinterpret_cast<const uint4*>(Bl_g + (size_t)(n0 + r)*DD + g*8);
    }
    #pragma unroll
    for (int i = 0; i < 2; i++) {
        int idx = i*128 + tid;
        int r = idx >> 3, g = idx & 7;
        uint32_t soff = SWZ((uint32_t)(r*128 + g*16));
        *reinterpret_cast<uint4*>(smem + SM_B2H + soff) =
            *reinterpret_cast<const uint4*>(B2h_g + (size_t)(n0 + r)*64 + g*8);
        *reinterpret_cast<uint4*>(smem + SM_B2L + soff) =
            *reinterpret_cast<const uint4*>(B2l_g + (size_t)(n0 + r)*64 + g*8);
    }
    __syncthreads();

    const uint32_t aoff0 = (uint32_t)((wm + 0  + (lane & 15))*128 + ((lane >> 4) << 4));
    const uint32_t aoff1 = (uint32_t)((wm + 16 + (lane & 15))*128 + ((lane >> 4) << 4));
    const uint32_t boff  = (uint32_t)((wn + (lane & 7) + ((lane >> 4) & 1)*8)*128 + ((lane >> 3) & 1)*16);
    const int ldr = tid >> 3;
    const int ldg = tid & 7;

    for (int t = 0; t <= TT; t++) {
        const bool active = isZ ? (t < TT) : (t >= 1);
        float acc[2][2][4];
        if (active) {
            #pragma unroll
            for (int a = 0; a < 2; a++)
                #pragma unroll
                for (int b = 0; b < 2; b++)
                    #pragma unroll
                    for (int c = 0; c < 4; c++) acc[a][b][c] = 0.f;

            int tu = isZ ? t : (t-1);
            const __nv_bfloat16* uh = Uh + (size_t)tu*BB*64;
            const __nv_bfloat16* ul = Ul + (size_t)tu*BB*64;
            uint32_t slot0 = sb + SM_ZR;
            #pragma unroll
            for (int i = 0; i < 4; i++) {
                int r = i*16 + ldr;
                uint32_t off = SWZ((uint32_t)(r*128 + ldg*16));
                *reinterpret_cast<uint4*>(smem + SM_ZR + off) =
                    *reinterpret_cast<const uint4*>(uh + (size_t)(m0 + r)*64 + ldg*8);
                *reinterpret_cast<uint4*>(smem + SM_ZR + 8192u + off) =
                    *reinterpret_cast<const uint4*>(ul + (size_t)(m0 + r)*64 + ldg*8);
            }
            __syncthreads();
            {
                uint32_t bb = sb + SM_B2H;
                #pragma unroll
                for (int k16 = 0; k16 < 4; k16++) {
                    uint32_t ah0[4], al0[4], ah1[4], al1[4], bh[4], bl[4];
                    uint32_t ad0 = slot0 + SWZ(aoff0 + (uint32_t)k16*32);
                    ldmx4(ah0, ad0); ldmx4(al0, ad0 + 8192u);
                    uint32_t ad1 = slot0 + SWZ(aoff1 + (uint32_t)k16*32);
                    ldmx4(ah1, ad1); ldmx4(al1, ad1 + 8192u);
                    uint32_t bd = bb + SWZ(boff + (uint32_t)k16*32);
                    ldmx4(bh, bd); ldmx4(bl, bd + 4096u);
                    mma16816(acc[0][0], ah0, bh[0], bh[1]);
                    mma16816(acc[0][1], ah0, bh[2], bh[3]);
                    mma16816(acc[1][0], ah1, bh[0], bh[1]);
                    mma16816(acc[1][1], ah1, bh[2], bh[3]);
                    mma16816(acc[0][0], al0, bh[0], bh[1]);
                    mma16816(acc[0][1], al0, bh[2], bh[3]);
                    mma16816(acc[1][0], al1, bh[0], bh[1]);
                    mma16816(acc[1][1], al1, bh[2], bh[3]);
                    mma16816(acc[0][0], ah0, bl[0], bl[1]);
                    mma16816(acc[0][1], ah0, bl[2], bl[3]);
                    mma16816(acc[1][0], ah1, bl[0], bl[1]);
                    mma16816(acc[1][1], ah1, bl[2], bl[3]);
                }
            }
        }
        if (t > 0) gb_wait((unsigned)NCTA * (unsigned)t);

        if (active) {
            const __nv_bfloat16* zh = Zh + (size_t)(t & 1)*BB*DD;
            const __nv_bfloat16* zl = Zl + (size_t)(t & 1)*BB*DD;
            uint4 ph[4], pl[4];
            #pragma unroll
            for (int i = 0; i < 4; i++) {
                int r = i*16 + ldr;
                ph[i] = *reinterpret_cast<const uint4*>(zh + (size_t)(m0 + r)*DD + ldg*8);
                pl[i] = *reinterpret_cast<const uint4*>(zl + (size_t)(m0 + r)*DD + ldg*8);
            }
            {
                uint32_t zboff = SM_ZR + 16384u;
                #pragma unroll
                for (int i = 0; i < 4; i++) {
                    int r = i*16 + ldr;
                    uint32_t off = SWZ((uint32_t)(r*128 + ldg*16));
                    *reinterpret_cast<uint4*>(smem + zboff + off) = ph[i];
                    *reinterpret_cast<uint4*>(smem + zboff + 8192u + off) = pl[i];
                }
            }
            __syncthreads();

            for (int s = 0; s < 8; s++) {
                if (s + 1 < 8) {
                    #pragma unroll
                    for (int i = 0; i < 4; i++) {
                        int r = i*16 + ldr;
                        ph[i] = *reinterpret_cast<const uint4*>(zh + (size_t)(m0 + r)*DD + (s+1)*64 + ldg*8);
                        pl[i] = *reinterpret_cast<const uint4*>(zl + (size_t)(m0 + r)*DD + (s+1)*64 + ldg*8);
                    }
                }
                {
                    uint32_t zb = sb + SM_ZR + (uint32_t)((s+1) & 1)*16384u;
                    uint32_t bb = sb + SM_BH + (uint32_t)s*4096u;
                    #pragma unroll
                    for (int k16 = 0; k16 < 4; k16++) {
                        uint32_t ah0[4], al0[4], ah1[4], al1[4], bh[4], bl[4];
                        uint32_t ad0 = zb + SWZ(aoff0 + (uint32_t)k16*32);
                        ldmx4(ah0, ad0); ldmx4(al0, ad0 + 8192u);
                        uint32_t ad1 = zb + SWZ(aoff1 + (uint32_t)k16*32);
                        ldmx4(ah1, ad1); ldmx4(al1, ad1 + 8192u);
                        uint32_t bd = bb + SWZ(boff + (uint32_t)k16*32);
                        ldmx4(bh, bd); ldmx4(bl, bd + 32768u);
                        mma16816(acc[0][0], ah0, bh[0], bh[1]);
                        mma16816(acc[0][1], ah0, bh[2], bh[3]);
                        mma16816(acc[1][0], ah1, bh[0], bh[1]);
                        mma16816(acc[1][1], ah1, bh[2], bh[3]);
                        mma16816(acc[0][0], al0, bh[0], bh[1]);
                        mma16816(acc[0][1], al0, bh[2], bh[3]);
                        mma16816(acc[1][0], al1, bh[0], bh[1]);
                        mma16816(acc[1][1], al1, bh[2], bh[3]);
                        mma16816(acc[0][0], ah0, bl[0], bl[1]);
                        mma16816(acc[0][1], ah0, bl[2], bl[3]);
                        mma16816(acc[1][0], ah1, bl[0], bl[1]);
                        mma16816(acc[1][1], ah1, bl[2], bl[3]);
                    }
                }
                __syncthreads();
                if (s + 1 < 8) {
                    uint32_t zboff = SM_ZR + (uint32_t)(s & 1)*16384u;
                    #pragma unroll
                    for (int i = 0; i < 4; i++) {
                        int r = i*16 + ldr;
                        uint32_t off = SWZ((uint32_t)(r*128 + ldg*16));
                        *reinterpret_cast<uint4*>(smem + zboff + off) = ph[i];
                        *reinterpret_cast<uint4*>(smem + zboff + 8192u + off) = pl[i];
                    }
                    __syncthreads();
                }
            }

            int r0 = m0 + wm + (lane >> 2);
            int c0 = n0 + wn + (lane & 3)*2;
            if (isZ) {
                float* Zout = Zo + (size_t)t*BB*DD;
                __nv_bfloat16* zhn = Zh + (size_t)((t+1) & 1)*BB*DD;
                __nv_bfloat16* zln = Zl + (size_t)((t+1) & 1)*BB*DD;
                #pragma unroll
                for (int mi = 0; mi < 2; mi++)
                    #pragma unroll
                    for (int ni = 0; ni < 2; ni++) {
                        int row = r0 + mi*16, col = c0 + ni*8;
                        float a0 = acc[mi][ni][0], a1 = acc[mi][ni][1];
                        float a2 = acc[mi][ni][2], a3 = acc[mi][ni][3];
                        *reinterpret_cast<float2*>(Zout + (size_t)row*DD + col)     = make_float2(a0, a1);
                        *reinterpret_cast<float2*>(Zout + (size_t)(row+8)*DD + col) = make_float2(a2, a3);
                        __nv_bfloat162 h0 = __floats2bfloat162_rn(a0, a1);
                        __nv_bfloat162 l0 = __floats2bfloat162_rn(a0 - __bfloat162float(h0.x),
                                                                  a1 - __bfloat162float(h0.y));
                        __nv_bfloat162 h1 = __floats2bfloat162_rn(a2, a3);
                        __nv_bfloat162 l1 = __floats2bfloat162_rn(a2 - __bfloat162float(h1.x),
                                                                  a3 - __bfloat162float(h1.y));
                        *reinterpret_cast<__nv_bfloat162*>(zhn + (size_t)row*DD + col)     = h0;
                        *reinterpret_cast<__nv_bfloat162*>(zln + (size_t)row*DD + col)     = l0;
                        *reinterpret_cast<__nv_bfloat162*>(zhn + (size_t)(row+8)*DD + col) = h1;
                        *reinterpret_cast<__nv_bfloat162*>(zln + (size_t)(row+8)*DD + col) = l1;
                    }
            } else {
                float* Yout = Yo + (size_t)(t-1)*BB*NOBS;
                #pragma unroll
                for (int mi = 0; mi < 2; mi++)
                    #pragma unroll
                    for (int ni = 0; ni < 2; ni++) {
                        int row = r0 + mi*16, col = c0 + ni*8;
                        if (col < NOBS)     Yout[(size_t)row*NOBS + col]       = acc[mi][ni][0];
                        if (col + 1 < NOBS) Yout[(size_t)row*NOBS + col + 1]   = acc[mi][ni][1];
                        if (col < NOBS)     Yout[(size_t)(row+8)*NOBS + col]   = acc[mi][ni][2];
                        if (col + 1 < NOBS) Yout[(size_t)(row+8)*NOBS + col+1] = acc[mi][ni][3];
                    }
            }
        }
        if (t < TT) gb_arrive();
    }
}

// ---------------- host orchestration ----------------
extern "C" void kernel_launch(void* const* d_in, const int* in_sizes, int n_in,
                              void* d_out, int out_size)
{
    const float* z_dyn = (const float*)d_in[0];
    const float* dtp   = (const float*)d_in[2];
    const float* U     = (const float*)d_in[3];
    const float* skew  = (const float*)d_in[4];
    const float* gamma = (const float*)d_in[5];
    const float* B_ct  = (const float*)d_in[6];
    const float* Cm    = (const float*)d_in[7];
    const float* Dm    = (const float*)d_in[8];

    float *Y_, *E_, *P_, *T_, *T2_, *Bb_;
    cudaGetSymbolAddress((void**)&Y_,  g_Y);
    cudaGetSymbolAddress((void**)&E_,  g_E);
    cudaGetSymbolAddress((void**)&P_,  g_P);
    cudaGetSymbolAddress((void**)&T_,  g_T);
    cudaGetSymbolAddress((void**)&T2_, g_T2);
    cudaGetSymbolAddress((void**)&Bb_, g_Bb);

    __nv_bfloat16 *Ehi, *Elo, *Chi, *Clo, *Bbhi, *Bblo, *Dshi, *Dslo, *Zh, *Zl, *Uh, *Ul;
    __nv_bfloat16 *Yht, *Ylt, *Eht, *Elt, *Pht, *Plt, *Pht2, *Plt2;
    cudaGetSymbolAddress((void**)&Ehi,  g_Ehi);
    cudaGetSymbolAddress((void**)&Elo,  g_Elo);
    cudaGetSymbolAddress((void**)&Chi,  g_Chi);
    cudaGetSymbolAddress((void**)&Clo,  g_Clo);
    cudaGetSymbolAddress((void**)&Bbhi, g_Bbhi);
    cudaGetSymbolAddress((void**)&Bblo, g_Bblo);
    cudaGetSymbolAddress((void**)&Dshi, g_Dshi);
    cudaGetSymbolAddress((void**)&Dslo, g_Dslo);
    cudaGetSymbolAddress((void**)&Zh,   g_Zh);
    cudaGetSymbolAddress((void**)&Zl,   g_Zl);
    cudaGetSymbolAddress((void**)&Uh,   g_Uh);
    cudaGetSymbolAddress((void**)&Ul,   g_Ul);
    cudaGetSymbolAddress((void**)&Yht,  g_Yht);
    cudaGetSymbolAddress((void**)&Ylt,  g_Ylt);
    cudaGetSymbolAddress((void**)&Eht,  g_Eht);
    cudaGetSymbolAddress((void**)&Elt,  g_Elt);
    cudaGetSymbolAddress((void**)&Pht,  g_Pht);
    cudaGetSymbolAddress((void**)&Plt,  g_Plt);
    cudaGetSymbolAddress((void**)&Pht2, g_Pht2);
    cudaGetSymbolAddress((void**)&Plt2, g_Plt2);

    cudaFuncSetAttribute(scan_persist, cudaFuncAttributeMaxDynamicSharedMemorySize, SM_TOT);
    cudaFuncSetAttribute(gemm_tc, cudaFuncAttributeMaxDynamicSharedMemorySize, TC_TOT);

    const int n2 = DD*DD;
    const int g2 = (n2 + 255)/256;
    dim3 gg1(16, 8, 1);
    dim3 gg2(16, 8, 2);

    build_Y_kernel<<<g2, 256>>>(skew, gamma, dtp, Y_);
    init_EPT<<<g2, 256>>>(E_, P_, T_);
    split_T<<<g2, 256>>>(Y_, Yht, Ylt);

    // Taylor: T_k = T_{k-1} @ Y / k ; E += T_k ; P += T_k/(k+1)
    float* Tin = T_; float* Tout = T2_;
    for (int k = 1; k <= NTAYLOR; k++) {
        gemm_tc<<<gg1, 128, TC_TOT>>>(Tin, Yht, Ylt, Yht, Ylt,
                                      Tout, Tout, E_, P_, nullptr,
                                      nullptr, nullptr, nullptr, nullptr,
                                      1.0f/(float)k, 1.0f/(float)(k+1), 1);
        float* tmp = Tin; Tin = Tout; Tout = tmp;
    }
    split_T<<<g2, 256>>>(E_, Eht, Elt);
    split_T<<<g2, 256>>>(P_, Pht, Plt);

    // DBL1: z0: P2(T2_) = 0.5 E@P + 0.5 P (+split->Pht2) ; z1: E2(T_) = E@E (+split->Yht reuse)
    gemm_tc<<<gg2, 128, TC_TOT>>>(E_, Pht, Plt, Eht, Elt,
                                  T2_, T_, nullptr, nullptr, P_,
                                  Pht2, Plt2, Yht, Ylt, 0.f, 0.f, 2);
    // DBL2: A=E2(T_); z0: P_final(P_) = 0.5 E2@P2 + 0.5 P2 ; z1: E_final(E_) = E2@E2
    gemm_tc<<<gg2, 128, TC_TOT>>>(T_, Pht2, Plt2, Yht, Ylt,
                                  P_, E_, nullptr, nullptr, T2_,
                                  nullptr, nullptr, nullptr, nullptr, 0.f, 0.f, 3);

    gemm_small<<<16, 256>>>(Bb_, P_, B_ct);

    split_mat<<<g2, 256>>>(E_, Ehi, Elo, DD, DD, DD, DD, dtp, 0);
    split_mat<<<(64*DD + 255)/256, 256>>>(Cm, Chi, Clo, NOBS, DD, 64, DD, dtp, 0);
    split_mat<<<(DD*64 + 255)/256, 256>>>(Bb_, Bbhi, Bblo, DD, UDIM, DD, 64, dtp, 1);
    split_mat<<<(64*64 + 255)/256, 256>>>(Dm, Dshi, Dslo, NOBS, UDIM, 64, 64, dtp, 1);
    split_mat<<<g2, 256>>>(z_dyn, Zh, Zl, BB, DD, BB, DD, dtp, 0);
    split_mat<<<(TT*BB*64 + 255)/256, 256>>>(U, Uh, Ul, TT*BB, UDIM, TT*BB, 64, dtp, 0);

    reset_barrier<<<1, 1>>>();

    float* Zo = (float*)d_out;
    float* Yo = (float*)d_out + (size_t)TT*BB*DD;
    scan_persist<<<NCTA, 128, SM_TOT>>>(Zo, Yo,
                                        Ehi, Elo, Bbhi, Bblo, Chi, Clo, Dshi, Dslo,
                                        Zh, Zl, Uh, Ul);
}

// round 10
// speedup vs baseline: 3.0325x; 1.0152x over previous
#include <cuda_runtime.h>
#include <cuda_bf16.h>
#include <math.h>
#include <stdint.h>

#define DD   512
#define BB   512
#define TT   256
#define UDIM 32
#define NOBS 50
#define NTAYLOR 7
#define NSQUARE 2
#define NCTA 144

// ---------------- device scratch ----------------
__device__ float g_Y [DD*DD];
__device__ float g_E [DD*DD];
__device__ float g_P [DD*DD];
__device__ float g_T [DD*DD];
__device__ float g_T2[DD*DD];
__device__ float g_Bb[DD*UDIM];

// transposed-split operands for setup GEMMs
__device__ __nv_bfloat16 g_Yht [DD*DD];
__device__ __nv_bfloat16 g_Ylt [DD*DD];
__device__ __nv_bfloat16 g_Eht [DD*DD];
__device__ __nv_bfloat16 g_Elt [DD*DD];
__device__ __nv_bfloat16 g_Pht [DD*DD];
__device__ __nv_bfloat16 g_Plt [DD*DD];
__device__ __nv_bfloat16 g_Pht2[DD*DD];
__device__ __nv_bfloat16 g_Plt2[DD*DD];

__device__ __nv_bfloat16 g_Ehi [DD*DD];
__device__ __nv_bfloat16 g_Elo [DD*DD];
__device__ __nv_bfloat16 g_Chi [64*DD];
__device__ __nv_bfloat16 g_Clo [64*DD];
__device__ __nv_bfloat16 g_Bbhi[DD*64];
__device__ __nv_bfloat16 g_Bblo[DD*64];
__device__ __nv_bfloat16 g_Dshi[64*64];
__device__ __nv_bfloat16 g_Dslo[64*64];

__device__ __nv_bfloat16 g_Zh[2*BB*DD];
__device__ __nv_bfloat16 g_Zl[2*BB*DD];
__device__ __nv_bfloat16 g_Uh[(size_t)TT*BB*64];
__device__ __nv_bfloat16 g_Ul[(size_t)TT*BB*64];

__device__ __align__(128) unsigned g_cnt[8*32];

// ---------------- helpers ----------------
__device__ __forceinline__ uint32_t smem_u32(const void* p) {
    uint32_t a;
    asm("{ .reg .u64 t; cvta.to.shared.u64 t, %1; cvt.u32.u64 %0, t; }" : "=r"(a) : "l"(p));
    return a;
}
#define SWZ(o) ((o) ^ (((o) >> 3) & 0x70))

__device__ __forceinline__ void ldmx4(uint32_t r[4], uint32_t addr) {
    asm volatile("ldmatrix.sync.aligned.m8n8.x4.shared.b16 {%0,%1,%2,%3}, [%4];"
        : "=r"(r[0]), "=r"(r[1]), "=r"(r[2]), "=r"(r[3]) : "r"(addr));
}
__device__ __forceinline__ void mma16816(float acc[4], const uint32_t a[4],
                                          uint32_t b0, uint32_t b1) {
    asm volatile("mma.sync.aligned.m16n8k16.row.col.f32.bf16.bf16.f32 "
        "{%0,%1,%2,%3},{%4,%5,%6,%7},{%8,%9},{%0,%1,%2,%3};"
        : "+f"(acc[0]), "+f"(acc[1]), "+f"(acc[2]), "+f"(acc[3])
        : "r"(a[0]), "r"(a[1]), "r"(a[2]), "r"(a[3]), "r"(b0), "r"(b1));
}
__device__ __forceinline__ void split4(float4 v, uint32_t hi_a, uint32_t lo_a) {
    __nv_bfloat162 h0 = __floats2bfloat162_rn(v.x, v.y);
    __nv_bfloat162 h1 = __floats2bfloat162_rn(v.z, v.w);
    __nv_bfloat162 l0 = __floats2bfloat162_rn(v.x - __bfloat162float(h0.x), v.y - __bfloat162float(h0.y));
    __nv_bfloat162 l1 = __floats2bfloat162_rn(v.z - __bfloat162float(h1.x), v.w - __bfloat162float(h1.y));
    uint32_t h0u = *(uint32_t*)&h0, h1u = *(uint32_t*)&h1;
    uint32_t l0u = *(uint32_t*)&l0, l1u = *(uint32_t*)&l1;
    asm volatile("st.shared.v2.b32 [%0], {%1,%2};" :: "r"(hi_a), "r"(h0u), "r"(h1u) : "memory");
    asm volatile("st.shared.v2.b32 [%0], {%1,%2};" :: "r"(lo_a), "r"(l0u), "r"(l1u) : "memory");
}
#define MMA_TRIPLE(accw, ahh, all, bhh, bll) \
    mma16816(accw[0][0], ahh##0, bhh[0], bhh[1]); \
    mma16816(accw[0][1], ahh##0, bhh[2], bhh[3]); \
    mma16816(accw[1][0], ahh##1, bhh[0], bhh[1]); \
    mma16816(accw[1][1], ahh##1, bhh[2], bhh[3]); \
    mma16816(accw[0][0], all##0, bhh[0], bhh[1]); \
    mma16816(accw[0][1], all##0, bhh[2], bhh[3]); \
    mma16816(accw[1][0], all##1, bhh[0], bhh[1]); \
    mma16816(accw[1][1], all##1, bhh[2], bhh[3]); \
    mma16816(accw[0][0], ahh##0, bll[0], bll[1]); \
    mma16816(accw[0][1], ahh##0, bll[2], bll[3]); \
    mma16816(accw[1][0], ahh##1, bll[0], bll[1]); \
    mma16816(accw[1][1], ahh##1, bll[2], bll[3]);

// ---------------- setup elementwise kernels ----------------
__global__ void build_Y_kernel(const float* __restrict__ skew, const float* __restrict__ gamma,
                               const float* __restrict__ dtp, float* __restrict__ Y)
{
    int idx = blockIdx.x*256 + threadIdx.x;
    if (idx >= DD*DD) return;
    int i = idx >> 9, j = idx & (DD-1);
    float v;
    if (i < j)      v =  skew[i*(DD-1) - (i*(i-1))/2 + (j-i-1)];
    else if (i > j) v = -skew[j*(DD-1) - (j*(j-1))/2 + (i-j-1)];
    else { float g = gamma[i]; v = -(fmaxf(g,0.f) + log1pf(expf(-fabsf(g)))); }
    Y[idx] = v * (dtp[0] * (1.0f/(float)(1<<NSQUARE)));
}
__global__ void init_EPT(float* E, float* P, float* Tm) {
    int idx = blockIdx.x*256 + threadIdx.x;
    if (idx >= DD*DD) return;
    float v = ((idx>>9) == (idx&(DD-1))) ? 1.f : 0.f;
    E[idx]=v; P[idx]=v; Tm[idx]=v;
}
__global__ void reset_barrier() { if (threadIdx.x < 8) g_cnt[threadIdx.x*32] = 0; }

__global__ void split_T(const float* __restrict__ src,
                        __nv_bfloat16* __restrict__ h, __nv_bfloat16* __restrict__ l)
{
    int idx = blockIdx.x*256 + threadIdx.x;
    if (idx >= DD*DD) return;
    int r = idx >> 9, c = idx & (DD-1);
    float v = src[idx];
    __nv_bfloat16 hh = __float2bfloat16(v);
    h[(size_t)c*DD + r] = hh;
    l[(size_t)c*DD + r] = __float2bfloat16(v - __bfloat162float(hh));
}
__global__ void split_mat(const float* __restrict__ src, __nv_bfloat16* hi, __nv_bfloat16* lo,
                          int rs, int cs, int rd, int cd, const float* dtp, int usedt)
{
    int idx = blockIdx.x*256 + threadIdx.x;
    if (idx >= rd*cd) return;
    int r = idx / cd, c = idx % cd;
    float v = (r < rs && c < cs) ? src[(size_t)r*cs + c] : 0.f;
    if (usedt) v *= dtp[0];
    __nv_bfloat16 h = __float2bfloat16(v);
    hi[idx] = h;
    lo[idx] = __float2bfloat16(v - __bfloat162float(h));
}

// B_bar = P @ B_ct  (512x32x512), SIMT (tiny, proven)
__global__ void gemm_small(float* __restrict__ C, const float* __restrict__ A,
                           const float* __restrict__ Bm)
{
    __shared__ float As[32][33];
    __shared__ float Bs[32][33];
    int tx = threadIdx.x & 15, ty = threadIdx.x >> 4;
    int i0 = blockIdx.x*32;
    float a00=0,a01=0,a10=0,a11=0;
    for (int k0 = 0; k0 < DD; k0 += 32) {
        for (int u = threadIdx.x; u < 32*32; u += 256) {
            int r = u>>5, c = u&31;
            As[r][c] = A[(size_t)(i0+r)*DD + k0+c];
            Bs[r][c] = Bm[(size_t)(k0+r)*UDIM + c];
        }
        __syncthreads();
        #pragma unroll
        for (int k = 0; k < 32; k++) {
            float x0=As[ty*2][k], x1=As[ty*2+1][k];
            float y0=Bs[k][tx*2], y1=Bs[k][tx*2+1];
            a00+=x0*y0; a01+=x0*y1; a10+=x1*y0; a11+=x1*y1;
        }
        __syncthreads();
    }
    C[(size_t)(i0+ty*2+0)*UDIM + tx*2+0]=a00;
    C[(size_t)(i0+ty*2+0)*UDIM + tx*2+1]=a01;
    C[(size_t)(i0+ty*2+1)*UDIM + tx*2+0]=a10;
    C[(size_t)(i0+ty*2+1)*UDIM + tx*2+1]=a11;
}

// ---------------- tensor-core setup GEMM (R7 proven version) ----------------
#define TC_BH  0u
#define TC_BL  32768u
#define TC_ZR  65536u
#define TC_TOT 98304u

__global__ void __launch_bounds__(128) gemm_tc(
    const float* __restrict__ A,
    const __nv_bfloat16* __restrict__ Bh0, const __nv_bfloat16* __restrict__ Bl0,
    const __nv_bfloat16* __restrict__ Bh1, const __nv_bfloat16* __restrict__ Bl1,
    float* __restrict__ C0, float* __restrict__ C1,
    float* __restrict__ Eacc, float* __restrict__ Pacc, const float* __restrict__ Pin,
    __nv_bfloat16* __restrict__ Th0, __nv_bfloat16* __restrict__ Tl0,
    __nv_bfloat16* __restrict__ Th1, __nv_bfloat16* __restrict__ Tl1,
    float invk, float invk1, int mode)
{
    extern __shared__ __align__(1024) char smem[];
    const int tid = threadIdx.x, lane = tid & 31, w = tid >> 5;
    const int wm = (w & 1)*32, wn = (w >> 1)*16;
    const int n0 = blockIdx.x*32, m0 = blockIdx.y*64;
    const int z = blockIdx.z;
    const __nv_bfloat16* Bh = z ? Bh1 : Bh0;
    const __nv_bfloat16* Bl = z ? Bl1 : Bl0;
    const uint32_t sb = smem_u32(smem);

    #pragma unroll
    for (int i = 0; i < 16; i++) {
        int idx = i*128 + tid;
        int r = idx >> 6, g = idx & 63;
        uint32_t soff = (uint32_t)((g>>3)*4096) + SWZ((uint32_t)(r*128 + (g&7)*16));
        *(uint4*)(smem + TC_BH + soff) = *(const uint4*)(Bh + (size_t)(n0+r)*DD + g*8);
        *(uint4*)(smem + TC_BL + soff) = *(const uint4*)(Bl + (size_t)(n0+r)*DD + g*8);
    }

    const uint32_t aoff0 = (uint32_t)((wm + 0  + (lane & 15))*128 + ((lane >> 4) << 4));
    const uint32_t aoff1 = (uint32_t)((wm + 16 + (lane & 15))*128 + ((lane >> 4) << 4));
    const uint32_t boff  = (uint32_t)((wn + (lane & 7) + ((lane >> 4) & 1)*8)*128 + ((lane >> 3) & 1)*16);
    const int ldr = tid >> 4, lfq = tid & 15;

    float4 pf[8];
    #pragma unroll
    for (int i = 0; i < 8; i++)
        pf[i] = *(const float4*)(A + (size_t)(m0 + i*8 + ldr)*DD + lfq*4);
    {
        uint32_t zb = sb + TC_ZR;
        #pragma unroll
        for (int i = 0; i < 8; i++) {
            uint32_t off = SWZ((uint32_t)((i*8+ldr)*128 + lfq*8));
            split4(pf[i], zb + off, zb + 8192u + off);
        }
    }
    __syncthreads();

    float acc[2][2][4];
    #pragma unroll
    for (int a = 0; a < 2; a++)
        #pragma unroll
        for (int b = 0; b < 2; b++)
            #pragma unroll
            for (int c = 0; c < 4; c++) acc[a][b][c] = 0.f;

    for (int s = 0; s < 8; s++) {
        if (s + 1 < 8) {
            #pragma unroll
            for (int i = 0; i < 8; i++)
                pf[i] = *(const float4*)(A + (size_t)(m0 + i*8 + ldr)*DD + (s+1)*64 + lfq*4);
        }
        {
            uint32_t zb = sb + TC_ZR + (uint32_t)(s & 1)*16384u;
            uint32_t bb = sb + TC_BH + (uint32_t)s*4096u;
            #pragma unroll
            for (int k16 = 0; k16 < 4; k16++) {
                uint32_t ah0[4], al0[4], ah1[4], al1[4], bh[4], bl[4];
                uint32_t ad0 = zb + SWZ(aoff0 + (uint32_t)k16*32);
                ldmx4(ah0, ad0); ldmx4(al0, ad0 + 8192u);
                uint32_t ad1 = zb + SWZ(aoff1 + (uint32_t)k16*32);
                ldmx4(ah1, ad1); ldmx4(al1, ad1 + 8192u);
                uint32_t bd = bb + SWZ(boff + (uint32_t)k16*32);
                ldmx4(bh, bd); ldmx4(bl, bd + 32768u);
                MMA_TRIPLE(acc, ah, al, bh, bl)
            }
        }
        __syncthreads();
        if (s + 1 < 8) {
            uint32_t zb = sb + TC_ZR + (uint32_t)((s+1)&1)*16384u;
            #pragma unroll
            for (int i = 0; i < 8; i++) {
                uint32_t off = SWZ((uint32_t)((i*8+ldr)*128 + lfq*8));
                split4(pf[i], zb + off, zb + 8192u + off);
            }
            __syncthreads();
        }
    }

    int r0 = m0 + wm + (lane >> 2);
    int c0 = n0 + wn + (lane & 3)*2;
    float* Cw = z ? C1 : C0;
    __nv_bfloat16* Th = z ? Th1 : Th0;
    __nv_bfloat16* Tl = z ? Tl1 : Tl0;

    #pragma unroll
    for (int mi = 0; mi < 2; mi++)
        #pragma unroll
        for (int ni = 0; ni < 2; ni++)
            #pragma unroll
            for (int h = 0; h < 2; h++) {
                int rr = r0 + mi*16 + h*8, cc = c0 + ni*8;
                size_t idx = (size_t)rr*DD + cc;
                float v0 = acc[mi][ni][h*2+0];
                float v1 = acc[mi][ni][h*2+1];
                if (mode == 1) {
                    v0 *= invk; v1 *= invk;
                    *(float2*)(Cw + idx) = make_float2(v0, v1);
                    float2 e = *(float2*)(Eacc + idx);
                    e.x += v0; e.y += v1;
                    *(float2*)(Eacc + idx) = e;
                    float2 p = *(float2*)(Pacc + idx);
                    p.x += v0*invk1; p.y += v1*invk1;
                    *(float2*)(Pacc + idx) = p;
                } else {
                    if (z == 0) {
                        float2 pin = *(const float2*)(Pin + idx);
                        v0 = 0.5f*v0 + 0.5f*pin.x;
                        v1 = 0.5f*v1 + 0.5f*pin.y;
                    }
                    *(float2*)(Cw + idx) = make_float2(v0, v1);
                    if (mode == 2) {
                        __nv_bfloat16 h0 = __float2bfloat16(v0);
                        __nv_bfloat16 h1 = __float2bfloat16(v1);
                        Th[(size_t)cc*DD + rr]     = h0;
                        Tl[(size_t)cc*DD + rr]     = __float2bfloat16(v0 - __bfloat162float(h0));
                        Th[(size_t)(cc+1)*DD + rr] = h1;
                        Tl[(size_t)(cc+1)*DD + rr] = __float2bfloat16(v1 - __bfloat162float(h1));
                    }
                }
            }
}

// ---------------- persistent mma scan (R7 verbatim, EXCEPT split barrier) ----------------
#define SM_BH   0u
#define SM_BL   32768u
#define SM_B2H  65536u
#define SM_B2L  69632u
#define SM_ZR   73728u
#define SM_TOT  120832u

__device__ __forceinline__ void gb_arrive(int blk) {
    __syncthreads();
    if (threadIdx.x == 0) {
        __threadfence();
        atomicAdd(&g_cnt[(blk & 7)*32], 1u);
    }
}
__device__ __forceinline__ void gb_wait(unsigned want) {
    if (threadIdx.x == 0) {
        unsigned s;
        do {
            s = 0;
            #pragma unroll
            for (int i = 0; i < 8; i++) s += *(volatile unsigned*)&g_cnt[i*32];
        } while (s < want);
        __threadfence();
    }
    __syncthreads();
}

__global__ void __launch_bounds__(128) scan_persist(
    float* __restrict__ Zo, float* __restrict__ Yo,
    const __nv_bfloat16* __restrict__ Ehi,  const __nv_bfloat16* __restrict__ Elo,
    const __nv_bfloat16* __restrict__ Bbhi, const __nv_bfloat16* __restrict__ Bblo,
    const __nv_bfloat16* __restrict__ Chi,  const __nv_bfloat16* __restrict__ Clo,
    const __nv_bfloat16* __restrict__ Dshi, const __nv_bfloat16* __restrict__ Dslo,
    __nv_bfloat16* __restrict__ Zh, __nv_bfloat16* __restrict__ Zl,
    const __nv_bfloat16* __restrict__ Uh, const __nv_bfloat16* __restrict__ Ul)
{
    extern __shared__ __align__(1024) char smem[];
    const int tid = threadIdx.x;
    const int lane = tid & 31;
    const int w = tid >> 5;
    const int wm = (w & 1) * 32;
    const int wn = (w >> 1) * 16;
    const int blk = blockIdx.x;
    const bool isZ = blk < 128;

    int m0, n0;
    const __nv_bfloat16 *Bh_g, *Bl_g, *B2h_g, *B2l_g;
    if (isZ) {
        m0 = (blk >> 4) * 64; n0 = (blk & 15) * 32;
        Bh_g = Ehi; Bl_g = Elo; B2h_g = Bbhi; B2l_g = Bblo;
    } else {
        int local = blk - 128;
        m0 = (local >> 1) * 64; n0 = (local & 1) * 32;
        Bh_g = Chi; Bl_g = Clo; B2h_g = Dshi; B2l_g = Dslo;
    }

    const uint32_t sb = smem_u32(smem);

    #pragma unroll
    for (int i = 0; i < 16; i++) {
        int idx = i*128 + tid;
        int r = idx >> 6, g = idx & 63;
        uint32_t soff = (uint32_t)((g >> 3)*4096) + SWZ((uint32_t)(r*128 + (g & 7)*16));
        *(uint4*)(smem + SM_BH + soff) = *(const uint4*)(Bh_g + (size_t)(n0 + r)*DD + g*8);
        *(uint4*)(smem + SM_BL + soff) = *(const uint4*)(Bl_g + (size_t)(n0 + r)*DD + g*8);
    }
    #pragma unroll
    for (int i = 0; i < 2; i++) {
        int idx = i*128 + tid;
        int r = idx >> 3, g = idx & 7;
        uint32_t soff = SWZ((uint32_t)(r*128 + g*16));
        *(uint4*)(smem + SM_B2H + soff) = *(const uint4*)(B2h_g + (size_t)(n0 + r)*64 + g*8);
        *(uint4*)(smem + SM_B2L + soff) = *(const uint4*)(B2l_g + (size_t)(n0 + r)*64 + g*8);
    }
    __syncthreads();

    const uint32_t aoff0 = (uint32_t)((wm + 0  + (lane & 15))*128 + ((lane >> 4) << 4));
    const uint32_t aoff1 = (uint32_t)((wm + 16 + (lane & 15))*128 + ((lane >> 4) << 4));
    const uint32_t boff  = (uint32_t)((wn + (lane & 7) + ((lane >> 4) & 1)*8)*128 + ((lane >> 3) & 1)*16);
    const int ldr = tid >> 3;
    const int ldg = tid & 7;

    for (int t = 0; t <= TT; t++) {
        const bool active = isZ ? (t < TT) : (t >= 1);
        float acc[2][2][4];
        if (active) {
            #pragma unroll
            for (int a = 0; a < 2; a++)
                #pragma unroll
                for (int b = 0; b < 2; b++)
                    #pragma unroll
                    for (int c = 0; c < 4; c++) acc[a][b][c] = 0.f;

            int tu = isZ ? t : (t-1);
            const __nv_bfloat16* uh = Uh + (size_t)tu*BB*64;
            const __nv_bfloat16* ul = Ul + (size_t)tu*BB*64;
            uint32_t slot0 = sb + SM_ZR;
            #pragma unroll
            for (int i = 0; i < 4; i++) {
                int r = i*16 + ldr;
                uint32_t off = SWZ((uint32_t)(r*128 + ldg*16));
                *(uint4*)(smem + SM_ZR + off) =
                    *(const uint4*)(uh + (size_t)(m0 + r)*64 + ldg*8);
                *(uint4*)(smem + SM_ZR + 8192u + off) =
                    *(const uint4*)(ul + (size_t)(m0 + r)*64 + ldg*8);
            }
            __syncthreads();
            {
                uint32_t bb = sb + SM_B2H;
                #pragma unroll
                for (int k16 = 0; k16 < 4; k16++) {
                    uint32_t ah0[4], al0[4], ah1[4], al1[4], bh[4], bl[4];
                    uint32_t ad0 = slot0 + SWZ(aoff0 + (uint32_t)k16*32);
                    ldmx4(ah0, ad0); ldmx4(al0, ad0 + 8192u);
                    uint32_t ad1 = slot0 + SWZ(aoff1 + (uint32_t)k16*32);
                    ldmx4(ah1, ad1); ldmx4(al1, ad1 + 8192u);
                    uint32_t bd = bb + SWZ(boff + (uint32_t)k16*32);
                    ldmx4(bh, bd); ldmx4(bl, bd + 4096u);
                    MMA_TRIPLE(acc, ah, al, bh, bl)
                }
            }
        }
        if (t > 0) gb_wait((unsigned)NCTA * (unsigned)t);

        if (active) {
            const __nv_bfloat16* zh = Zh + (size_t)(t & 1)*BB*DD;
            const __nv_bfloat16* zl = Zl + (size_t)(t & 1)*BB*DD;
            uint4 ph[4], pl[4];
            #pragma unroll
            for (int i = 0; i < 4; i++) {
                int r = i*16 + ldr;
                ph[i] = *(const uint4*)(zh + (size_t)(m0 + r)*DD + ldg*8);
                pl[i] = *(const uint4*)(zl + (size_t)(m0 + r)*DD + ldg*8);
            }
            {
                uint32_t zboff = SM_ZR + 16384u;
                #pragma unroll
                for (int i = 0; i < 4; i++) {
                    int r = i*16 + ldr;
                    uint32_t off = SWZ((uint32_t)(r*128 + ldg*16));
                    *(uint4*)(smem + zboff + off) = ph[i];
                    *(uint4*)(smem + zboff + 8192u + off) = pl[i];
                }
            }
            __syncthreads();

            for (int s = 0; s < 8; s++) {
                if (s + 1 < 8) {
                    #pragma unroll
                    for (int i = 0; i < 4; i++) {
                        int r = i*16 + ldr;
                        ph[i] = *(const uint4*)(zh + (size_t)(m0 + r)*DD + (s+1)*64 + ldg*8);
                        pl[i] = *(const uint4*)(zl + (size_t)(m0 + r)*DD + (s+1)*64 + ldg*8);
                    }
                }
                {
                    uint32_t zb = sb + SM_ZR + (uint32_t)((s+1) & 1)*16384u;
                    uint32_t bb = sb + SM_BH + (uint32_t)s*4096u;
                    #pragma unroll
                    for (int k16 = 0; k16 < 4; k16++) {
                        uint32_t ah0[4], al0[4], ah1[4], al1[4], bh[4], bl[4];
                        uint32_t ad0 = zb + SWZ(aoff0 + (uint32_t)k16*32);
                        ldmx4(ah0, ad0); ldmx4(al0, ad0 + 8192u);
                        uint32_t ad1 = zb + SWZ(aoff1 + (uint32_t)k16*32);
                        ldmx4(ah1, ad1); ldmx4(al1, ad1 + 8192u);
                        uint32_t bd = bb + SWZ(boff + (uint32_t)k16*32);
                        ldmx4(bh, bd); ldmx4(bl, bd + 32768u);
                        MMA_TRIPLE(acc, ah, al, bh, bl)
                    }
                }
                __syncthreads();
                if (s + 1 < 8) {
                    uint32_t zboff = SM_ZR + (uint32_t)(s & 1)*16384u;
                    #pragma unroll
                    for (int i = 0; i < 4; i++) {
                        int r = i*16 + ldr;
                        uint32_t off = SWZ((uint32_t)(r*128 + ldg*16));
                        *(uint4*)(smem + zboff + off) = ph[i];
                        *(uint4*)(smem + zboff + 8192u + off) = pl[i];
                    }
                    __syncthreads();
                }
            }

            int r0 = m0 + wm + (lane >> 2);
            int c0 = n0 + wn + (lane & 3)*2;
            if (isZ) {
                float* Zout = Zo + (size_t)t*BB*DD;
                __nv_bfloat16* zhn = Zh + (size_t)((t+1) & 1)*BB*DD;
                __nv_bfloat16* zln = Zl + (size_t)((t+1) & 1)*BB*DD;
                #pragma unroll
                for (int mi = 0; mi < 2; mi++)
                    #pragma unroll
                    for (int ni = 0; ni < 2; ni++) {
                        int row = r0 + mi*16, col = c0 + ni*8;
                        float a0 = acc[mi][ni][0], a1 = acc[mi][ni][1];
                        float a2 = acc[mi][ni][2], a3 = acc[mi][ni][3];
                        *(float2*)(Zout + (size_t)row*DD + col)     = make_float2(a0, a1);
                        *(float2*)(Zout + (size_t)(row+8)*DD + col) = make_float2(a2, a3);
                        __nv_bfloat162 h0 = __floats2bfloat162_rn(a0, a1);
                        __nv_bfloat162 l0 = __floats2bfloat162_rn(a0 - __bfloat162float(h0.x),
                                                                  a1 - __bfloat162float(h0.y));
                        __nv_bfloat162 h1 = __floats2bfloat162_rn(a2, a3);
                        __nv_bfloat162 l1 = __floats2bfloat162_rn(a2 - __bfloat162float(h1.x),
                                                                  a3 - __bfloat162float(h1.y));
                        *(__nv_bfloat162*)(zhn + (size_t)row*DD + col)     = h0;
                        *(__nv_bfloat162*)(zln + (size_t)row*DD + col)     = l0;
                        *(__nv_bfloat162*)(zhn + (size_t)(row+8)*DD + col) = h1;
                        *(__nv_bfloat162*)(zln + (size_t)(row+8)*DD + col) = l1;
                    }
            } else {
                float* Yout = Yo + (size_t)(t-1)*BB*NOBS;
                #pragma unroll
                for (int mi = 0; mi < 2; mi++)
                    #pragma unroll
                    for (int ni = 0; ni < 2; ni++) {
                        int row = r0 + mi*16, col = c0 + ni*8;
                        if (col < NOBS)     Yout[(size_t)row*NOBS + col]       = acc[mi][ni][0];
                        if (col + 1 < NOBS) Yout[(size_t)row*NOBS + col + 1]   = acc[mi][ni][1];
                        if (col < NOBS)     Yout[(size_t)(row+8)*NOBS + col]   = acc[mi][ni][2];
                        if (col + 1 < NOBS) Yout[(size_t)(row+8)*NOBS + col+1] = acc[mi][ni][3];
                    }
            }
        }
        if (t < TT) gb_arrive(blk);
    }
}

// ---------------- host orchestration ----------------
extern "C" void kernel_launch(void* const* d_in, const int* in_sizes, int n_in,
                              void* d_out, int out_size)
{
    const float* z_dyn = (const float*)d_in[0];
    const float* dtp   = (const float*)d_in[2];
    const float* U     = (const float*)d_in[3];
    const float* skew  = (const float*)d_in[4];
    const float* gamma = (const float*)d_in[5];
    const float* B_ct  = (const float*)d_in[6];
    const float* Cm    = (const float*)d_in[7];
    const float* Dm    = (const float*)d_in[8];

    float *Y_, *E_, *P_, *T_, *T2_, *Bb_;
    cudaGetSymbolAddress((void**)&Y_,  g_Y);
    cudaGetSymbolAddress((void**)&E_,  g_E);
    cudaGetSymbolAddress((void**)&P_,  g_P);
    cudaGetSymbolAddress((void**)&T_,  g_T);
    cudaGetSymbolAddress((void**)&T2_, g_T2);
    cudaGetSymbolAddress((void**)&Bb_, g_Bb);

    __nv_bfloat16 *Yht, *Ylt, *Eht, *Elt, *Pht, *Plt, *Pht2, *Plt2;
    __nv_bfloat16 *Ehi, *Elo, *Chi, *Clo, *Bbhi, *Bblo, *Dshi, *Dslo, *Zh, *Zl, *Uh, *Ul;
    cudaGetSymbolAddress((void**)&Yht,  g_Yht);
    cudaGetSymbolAddress((void**)&Ylt,  g_Ylt);
    cudaGetSymbolAddress((void**)&Eht,  g_Eht);
    cudaGetSymbolAddress((void**)&Elt,  g_Elt);
    cudaGetSymbolAddress((void**)&Pht,  g_Pht);
    cudaGetSymbolAddress((void**)&Plt,  g_Plt);
    cudaGetSymbolAddress((void**)&Pht2, g_Pht2);
    cudaGetSymbolAddress((void**)&Plt2, g_Plt2);
    cudaGetSymbolAddress((void**)&Ehi,  g_Ehi);
    cudaGetSymbolAddress((void**)&Elo,  g_Elo);
    cudaGetSymbolAddress((void**)&Chi,  g_Chi);
    cudaGetSymbolAddress((void**)&Clo,  g_Clo);
    cudaGetSymbolAddress((void**)&Bbhi, g_Bbhi);
    cudaGetSymbolAddress((void**)&Bblo, g_Bblo);
    cudaGetSymbolAddress((void**)&Dshi, g_Dshi);
    cudaGetSymbolAddress((void**)&Dslo, g_Dslo);
    cudaGetSymbolAddress((void**)&Zh,   g_Zh);
    cudaGetSymbolAddress((void**)&Zl,   g_Zl);
    cudaGetSymbolAddress((void**)&Uh,   g_Uh);
    cudaGetSymbolAddress((void**)&Ul,   g_Ul);

    cudaFuncSetAttribute(scan_persist, cudaFuncAttributeMaxDynamicSharedMemorySize, SM_TOT);
    cudaFuncSetAttribute(gemm_tc, cudaFuncAttributeMaxDynamicSharedMemorySize, TC_TOT);

    const int n2 = DD*DD;
    const int g2 = (n2 + 255)/256;
    dim3 gg1(16, 8, 1), gg2(16, 8, 2);

    build_Y_kernel<<<g2, 256>>>(skew, gamma, dtp, Y_);
    init_EPT<<<g2, 256>>>(E_, P_, T_);
    split_T<<<g2, 256>>>(Y_, Yht, Ylt);

    // Taylor: T_k = T_{k-1} @ Y / k ; E += T_k ; P += T_k/(k+1)
    float* Tin = T_; float* Tout = T2_;
    for (int k = 1; k <= NTAYLOR; k++) {
        gemm_tc<<<gg1, 128, TC_TOT>>>(Tin, Yht, Ylt, Yht, Ylt,
                                      Tout, Tout, E_, P_, nullptr,
                                      nullptr, nullptr, nullptr, nullptr,
                                      1.0f/(float)k, 1.0f/(float)(k+1), 1);
        float* tmp = Tin; Tin = Tout; Tout = tmp;
    }
    split_T<<<g2, 256>>>(E_, Eht, Elt);
    split_T<<<g2, 256>>>(P_, Pht, Plt);

    // DBL1: z0: P2(T2_) = 0.5 E@P + 0.5 P (+split->Pht2) ; z1: E2(T_) = E@E (+split->Yht)
    gemm_tc<<<gg2, 128, TC_TOT>>>(E_, Pht, Plt, Eht, Elt,
                                  T2_, T_, nullptr, nullptr, P_,
                                  Pht2, Plt2, Yht, Ylt, 0.f, 0.f, 2);
    // DBL2: A=E2(T_); z0: P_final(P_) = 0.5 E2@P2 + 0.5 P2 ; z1: E_final(E_) = E2@E2
    gemm_tc<<<gg2, 128, TC_TOT>>>(T_, Pht2, Plt2, Yht, Ylt,
                                  P_, E_, nullptr, nullptr, T2_,
                                  nullptr, nullptr, nullptr, nullptr, 0.f, 0.f, 3);

    gemm_small<<<16, 256>>>(Bb_, P_, B_ct);

    split_mat<<<g2, 256>>>(E_, Ehi, Elo, DD, DD, DD, DD, dtp, 0);
    split_mat<<<(64*DD + 255)/256, 256>>>(Cm, Chi, Clo, NOBS, DD, 64, DD, dtp, 0);
    split_mat<<<(DD*64 + 255)/256, 256>>>(Bb_, Bbhi, Bblo, DD, UDIM, DD, 64, dtp, 1);
    split_mat<<<(64*64 + 255)/256, 256>>>(Dm, Dshi, Dslo, NOBS, UDIM, 64, 64, dtp, 1);
    split_mat<<<g2, 256>>>(z_dyn, Zh, Zl, BB, DD, BB, DD, dtp, 0);
    split_mat<<<(TT*BB*64 + 255)/256, 256>>>(U, Uh, Ul, TT*BB, UDIM, TT*BB, 64, dtp, 0);

    reset_barrier<<<1, 32>>>();

    float* Zo = (float*)d_out;
    float* Yo = (float*)d_out + (size_t)TT*BB*DD;
    scan_persist<<<NCTA, 128, SM_TOT>>>(Zo, Yo,
                                        Ehi, Elo, Bbhi, Bblo, Chi, Clo, Dshi, Dslo,
                                        Zh, Zl, Uh, Ul);
}

// round 11
// speedup vs baseline: 3.4393x; 1.1341x over previous
#include <cuda_runtime.h>
#include <cuda_bf16.h>
#include <math.h>
#include <stdint.h>

#define DD   512
#define BB   512
#define TT   256
#define UDIM 32
#define NOBS 50
#define NTAYLOR 7
#define NSQUARE 2
#define NCTA 144

// ---------------- device scratch ----------------
__device__ float g_Y [DD*DD];
__device__ float g_E [DD*DD];
__device__ float g_P [DD*DD];
__device__ float g_T [DD*DD];
__device__ float g_T2[DD*DD];
__device__ float g_Bb[DD*UDIM];

__device__ __nv_bfloat16 g_Yht [DD*DD];
__device__ __nv_bfloat16 g_Ylt [DD*DD];
__device__ __nv_bfloat16 g_Eht [DD*DD];
__device__ __nv_bfloat16 g_Elt [DD*DD];
__device__ __nv_bfloat16 g_Pht [DD*DD];
__device__ __nv_bfloat16 g_Plt [DD*DD];
__device__ __nv_bfloat16 g_Pht2[DD*DD];
__device__ __nv_bfloat16 g_Plt2[DD*DD];

__device__ __nv_bfloat16 g_Ehi [DD*DD];
__device__ __nv_bfloat16 g_Elo [DD*DD];
__device__ __nv_bfloat16 g_Chi [64*DD];
__device__ __nv_bfloat16 g_Clo [64*DD];
__device__ __nv_bfloat16 g_Bbhi[DD*64];
__device__ __nv_bfloat16 g_Bblo[DD*64];
__device__ __nv_bfloat16 g_Dshi[64*64];
__device__ __nv_bfloat16 g_Dslo[64*64];

__device__ __nv_bfloat16 g_Zh[2*BB*DD];
__device__ __nv_bfloat16 g_Zl[2*BB*DD];
__device__ __nv_bfloat16 g_Uh[(size_t)TT*BB*64];
__device__ __nv_bfloat16 g_Ul[(size_t)TT*BB*64];

__device__ __align__(128) unsigned g_cnt[8*32];

// ---------------- helpers ----------------
__device__ __forceinline__ uint32_t smem_u32(const void* p) {
    uint32_t a;
    asm("{ .reg .u64 t; cvta.to.shared.u64 t, %1; cvt.u32.u64 %0, t; }" : "=r"(a) : "l"(p));
    return a;
}
#define SWZ(o) ((o) ^ (((o) >> 3) & 0x70))
#define BARH(id) asm volatile("bar.sync %0, 128;" :: "r"(id) : "memory")

__device__ __forceinline__ void ldmx4(uint32_t r[4], uint32_t addr) {
    asm volatile("ldmatrix.sync.aligned.m8n8.x4.shared.b16 {%0,%1,%2,%3}, [%4];"
        : "=r"(r[0]), "=r"(r[1]), "=r"(r[2]), "=r"(r[3]) : "r"(addr));
}
__device__ __forceinline__ void mma16816(float acc[4], const uint32_t a[4],
                                          uint32_t b0, uint32_t b1) {
    asm volatile("mma.sync.aligned.m16n8k16.row.col.f32.bf16.bf16.f32 "
        "{%0,%1,%2,%3},{%4,%5,%6,%7},{%8,%9},{%0,%1,%2,%3};"
        : "+f"(acc[0]), "+f"(acc[1]), "+f"(acc[2]), "+f"(acc[3])
        : "r"(a[0]), "r"(a[1]), "r"(a[2]), "r"(a[3]), "r"(b0), "r"(b1));
}
__device__ __forceinline__ void split4(float4 v, uint32_t hi_a, uint32_t lo_a) {
    __nv_bfloat162 h0 = __floats2bfloat162_rn(v.x, v.y);
    __nv_bfloat162 h1 = __floats2bfloat162_rn(v.z, v.w);
    __nv_bfloat162 l0 = __floats2bfloat162_rn(v.x - __bfloat162float(h0.x), v.y - __bfloat162float(h0.y));
    __nv_bfloat162 l1 = __floats2bfloat162_rn(v.z - __bfloat162float(h1.x), v.w - __bfloat162float(h1.y));
    uint32_t h0u = *(uint32_t*)&h0, h1u = *(uint32_t*)&h1;
    uint32_t l0u = *(uint32_t*)&l0, l1u = *(uint32_t*)&l1;
    asm volatile("st.shared.v2.b32 [%0], {%1,%2};" :: "r"(hi_a), "r"(h0u), "r"(h1u) : "memory");
    asm volatile("st.shared.v2.b32 [%0], {%1,%2};" :: "r"(lo_a), "r"(l0u), "r"(l1u) : "memory");
}
#define MMA_TRIPLE(accw, ahh, all, bhh, bll) \
    mma16816(accw[0][0], ahh##0, bhh[0], bhh[1]); \
    mma16816(accw[0][1], ahh##0, bhh[2], bhh[3]); \
    mma16816(accw[1][0], ahh##1, bhh[0], bhh[1]); \
    mma16816(accw[1][1], ahh##1, bhh[2], bhh[3]); \
    mma16816(accw[0][0], all##0, bhh[0], bhh[1]); \
    mma16816(accw[0][1], all##0, bhh[2], bhh[3]); \
    mma16816(accw[1][0], all##1, bhh[0], bhh[1]); \
    mma16816(accw[1][1], all##1, bhh[2], bhh[3]); \
    mma16816(accw[0][0], ahh##0, bll[0], bll[1]); \
    mma16816(accw[0][1], ahh##0, bll[2], bll[3]); \
    mma16816(accw[1][0], ahh##1, bll[0], bll[1]); \
    mma16816(accw[1][1], ahh##1, bll[2], bll[3]);

// ---------------- setup elementwise kernels (R10 verbatim) ----------------
__global__ void build_Y_kernel(const float* __restrict__ skew, const float* __restrict__ gamma,
                               const float* __restrict__ dtp, float* __restrict__ Y)
{
    int idx = blockIdx.x*256 + threadIdx.x;
    if (idx >= DD*DD) return;
    int i = idx >> 9, j = idx & (DD-1);
    float v;
    if (i < j)      v =  skew[i*(DD-1) - (i*(i-1))/2 + (j-i-1)];
    else if (i > j) v = -skew[j*(DD-1) - (j*(j-1))/2 + (i-j-1)];
    else { float g = gamma[i]; v = -(fmaxf(g,0.f) + log1pf(expf(-fabsf(g)))); }
    Y[idx] = v * (dtp[0] * (1.0f/(float)(1<<NSQUARE)));
}
__global__ void init_EPT(float* E, float* P, float* Tm) {
    int idx = blockIdx.x*256 + threadIdx.x;
    if (idx >= DD*DD) return;
    float v = ((idx>>9) == (idx&(DD-1))) ? 1.f : 0.f;
    E[idx]=v; P[idx]=v; Tm[idx]=v;
}
__global__ void reset_barrier() { if (threadIdx.x < 8) g_cnt[threadIdx.x*32] = 0; }

__global__ void split_T(const float* __restrict__ src,
                        __nv_bfloat16* __restrict__ h, __nv_bfloat16* __restrict__ l)
{
    int idx = blockIdx.x*256 + threadIdx.x;
    if (idx >= DD*DD) return;
    int r = idx >> 9, c = idx & (DD-1);
    float v = src[idx];
    __nv_bfloat16 hh = __float2bfloat16(v);
    h[(size_t)c*DD + r] = hh;
    l[(size_t)c*DD + r] = __float2bfloat16(v - __bfloat162float(hh));
}
__global__ void split_mat(const float* __restrict__ src, __nv_bfloat16* hi, __nv_bfloat16* lo,
                          int rs, int cs, int rd, int cd, const float* dtp, int usedt)
{
    int idx = blockIdx.x*256 + threadIdx.x;
    if (idx >= rd*cd) return;
    int r = idx / cd, c = idx % cd;
    float v = (r < rs && c < cs) ? src[(size_t)r*cs + c] : 0.f;
    if (usedt) v *= dtp[0];
    __nv_bfloat16 h = __float2bfloat16(v);
    hi[idx] = h;
    lo[idx] = __float2bfloat16(v - __bfloat162float(h));
}

__global__ void gemm_small(float* __restrict__ C, const float* __restrict__ A,
                           const float* __restrict__ Bm)
{
    __shared__ float As[32][33];
    __shared__ float Bs[32][33];
    int tx = threadIdx.x & 15, ty = threadIdx.x >> 4;
    int i0 = blockIdx.x*32;
    float a00=0,a01=0,a10=0,a11=0;
    for (int k0 = 0; k0 < DD; k0 += 32) {
        for (int u = threadIdx.x; u < 32*32; u += 256) {
            int r = u>>5, c = u&31;
            As[r][c] = A[(size_t)(i0+r)*DD + k0+c];
            Bs[r][c] = Bm[(size_t)(k0+r)*UDIM + c];
        }
        __syncthreads();
        #pragma unroll
        for (int k = 0; k < 32; k++) {
            float x0=As[ty*2][k], x1=As[ty*2+1][k];
            float y0=Bs[k][tx*2], y1=Bs[k][tx*2+1];
            a00+=x0*y0; a01+=x0*y1; a10+=x1*y0; a11+=x1*y1;
        }
        __syncthreads();
    }
    C[(size_t)(i0+ty*2+0)*UDIM + tx*2+0]=a00;
    C[(size_t)(i0+ty*2+0)*UDIM + tx*2+1]=a01;
    C[(size_t)(i0+ty*2+1)*UDIM + tx*2+0]=a10;
    C[(size_t)(i0+ty*2+1)*UDIM + tx*2+1]=a11;
}

// ---------------- tensor-core setup GEMM (R10 verbatim) ----------------
#define TC_BH  0u
#define TC_BL  32768u
#define TC_ZR  65536u
#define TC_TOT 98304u

__global__ void __launch_bounds__(128) gemm_tc(
    const float* __restrict__ A,
    const __nv_bfloat16* __restrict__ Bh0, const __nv_bfloat16* __restrict__ Bl0,
    const __nv_bfloat16* __restrict__ Bh1, const __nv_bfloat16* __restrict__ Bl1,
    float* __restrict__ C0, float* __restrict__ C1,
    float* __restrict__ Eacc, float* __restrict__ Pacc, const float* __restrict__ Pin,
    __nv_bfloat16* __restrict__ Th0, __nv_bfloat16* __restrict__ Tl0,
    __nv_bfloat16* __restrict__ Th1, __nv_bfloat16* __restrict__ Tl1,
    float invk, float invk1, int mode)
{
    extern __shared__ __align__(1024) char smem[];
    const int tid = threadIdx.x, lane = tid & 31, w = tid >> 5;
    const int wm = (w & 1)*32, wn = (w >> 1)*16;
    const int n0 = blockIdx.x*32, m0 = blockIdx.y*64;
    const int z = blockIdx.z;
    const __nv_bfloat16* Bh = z ? Bh1 : Bh0;
    const __nv_bfloat16* Bl = z ? Bl1 : Bl0;
    const uint32_t sb = smem_u32(smem);

    #pragma unroll
    for (int i = 0; i < 16; i++) {
        int idx = i*128 + tid;
        int r = idx >> 6, g = idx & 63;
        uint32_t soff = (uint32_t)((g>>3)*4096) + SWZ((uint32_t)(r*128 + (g&7)*16));
        *(uint4*)(smem + TC_BH + soff) = *(const uint4*)(Bh + (size_t)(n0+r)*DD + g*8);
        *(uint4*)(smem + TC_BL + soff) = *(const uint4*)(Bl + (size_t)(n0+r)*DD + g*8);
    }

    const uint32_t aoff0 = (uint32_t)((wm + 0  + (lane & 15))*128 + ((lane >> 4) << 4));
    const uint32_t aoff1 = (uint32_t)((wm + 16 + (lane & 15))*128 + ((lane >> 4) << 4));
    const uint32_t boff  = (uint32_t)((wn + (lane & 7) + ((lane >> 4) & 1)*8)*128 + ((lane >> 3) & 1)*16);
    const int ldr = tid >> 4, lfq = tid & 15;

    float4 pf[8];
    #pragma unroll
    for (int i = 0; i < 8; i++)
        pf[i] = *(const float4*)(A + (size_t)(m0 + i*8 + ldr)*DD + lfq*4);
    {
        uint32_t zb = sb + TC_ZR;
        #pragma unroll
        for (int i = 0; i < 8; i++) {
            uint32_t off = SWZ((uint32_t)((i*8+ldr)*128 + lfq*8));
            split4(pf[i], zb + off, zb + 8192u + off);
        }
    }
    __syncthreads();

    float acc[2][2][4];
    #pragma unroll
    for (int a = 0; a < 2; a++)
        #pragma unroll
        for (int b = 0; b < 2; b++)
            #pragma unroll
            for (int c = 0; c < 4; c++) acc[a][b][c] = 0.f;

    for (int s = 0; s < 8; s++) {
        if (s + 1 < 8) {
            #pragma unroll
            for (int i = 0; i < 8; i++)
                pf[i] = *(const float4*)(A + (size_t)(m0 + i*8 + ldr)*DD + (s+1)*64 + lfq*4);
        }
        {
            uint32_t zb = sb + TC_ZR + (uint32_t)(s & 1)*16384u;
            uint32_t bb = sb + TC_BH + (uint32_t)s*4096u;
            #pragma unroll
            for (int k16 = 0; k16 < 4; k16++) {
                uint32_t ah0[4], al0[4], ah1[4], al1[4], bh[4], bl[4];
                uint32_t ad0 = zb + SWZ(aoff0 + (uint32_t)k16*32);
                ldmx4(ah0, ad0); ldmx4(al0, ad0 + 8192u);
                uint32_t ad1 = zb + SWZ(aoff1 + (uint32_t)k16*32);
                ldmx4(ah1, ad1); ldmx4(al1, ad1 + 8192u);
                uint32_t bd = bb + SWZ(boff + (uint32_t)k16*32);
                ldmx4(bh, bd); ldmx4(bl, bd + 32768u);
                MMA_TRIPLE(acc, ah, al, bh, bl)
            }
        }
        __syncthreads();
        if (s + 1 < 8) {
            uint32_t zb = sb + TC_ZR + (uint32_t)((s+1)&1)*16384u;
            #pragma unroll
            for (int i = 0; i < 8; i++) {
                uint32_t off = SWZ((uint32_t)((i*8+ldr)*128 + lfq*8));
                split4(pf[i], zb + off, zb + 8192u + off);
            }
            __syncthreads();
        }
    }

    int r0 = m0 + wm + (lane >> 2);
    int c0 = n0 + wn + (lane & 3)*2;
    float* Cw = z ? C1 : C0;
    __nv_bfloat16* Th = z ? Th1 : Th0;
    __nv_bfloat16* Tl = z ? Tl1 : Tl0;

    #pragma unroll
    for (int mi = 0; mi < 2; mi++)
        #pragma unroll
        for (int ni = 0; ni < 2; ni++)
            #pragma unroll
            for (int h = 0; h < 2; h++) {
                int rr = r0 + mi*16 + h*8, cc = c0 + ni*8;
                size_t idx = (size_t)rr*DD + cc;
                float v0 = acc[mi][ni][h*2+0];
                float v1 = acc[mi][ni][h*2+1];
                if (mode == 1) {
                    v0 *= invk; v1 *= invk;
                    *(float2*)(Cw + idx) = make_float2(v0, v1);
                    float2 e = *(float2*)(Eacc + idx);
                    e.x += v0; e.y += v1;
                    *(float2*)(Eacc + idx) = e;
                    float2 p = *(float2*)(Pacc + idx);
                    p.x += v0*invk1; p.y += v1*invk1;
                    *(float2*)(Pacc + idx) = p;
                } else {
                    if (z == 0) {
                        float2 pin = *(const float2*)(Pin + idx);
                        v0 = 0.5f*v0 + 0.5f*pin.x;
                        v1 = 0.5f*v1 + 0.5f*pin.y;
                    }
                    *(float2*)(Cw + idx) = make_float2(v0, v1);
                    if (mode == 2) {
                        __nv_bfloat16 h0 = __float2bfloat16(v0);
                        __nv_bfloat16 h1 = __float2bfloat16(v1);
                        Th[(size_t)cc*DD + rr]     = h0;
                        Tl[(size_t)cc*DD + rr]     = __float2bfloat16(v0 - __bfloat162float(h0));
                        Th[(size_t)(cc+1)*DD + rr] = h1;
                        Tl[(size_t)(cc+1)*DD + rr] = __float2bfloat16(v1 - __bfloat162float(h1));
                    }
                }
            }
}

// ---------------- persistent mma scan: 8 warps, K-split halves ----------------
// smem: B hi 32KB | B lo 32KB | B2 hi 4KB | B2 lo 4KB | ring 4 x 16KB = 136 KB
#define SM_BH   0u
#define SM_BL   32768u
#define SM_B2H  65536u
#define SM_B2L  69632u
#define SM_ZR   73728u
#define SM_RED  73728u            /* reduction buffer reuses half0 ring */
#define SM_TOT  139264u

__device__ __forceinline__ void gb_arrive(int blk) {
    __syncthreads();
    if (threadIdx.x == 0) {
        __threadfence();
        atomicAdd(&g_cnt[(blk & 7)*32], 1u);
    }
}
__device__ __forceinline__ void gb_wait(unsigned want) {
    if (threadIdx.x == 0) {
        unsigned s;
        do {
            s = 0;
            #pragma unroll
            for (int i = 0; i < 8; i++) s += *(volatile unsigned*)&g_cnt[i*32];
        } while (s < want);
        __threadfence();
    }
    __syncthreads();
}

__global__ void __launch_bounds__(256) scan_persist(
    float* __restrict__ Zo, float* __restrict__ Yo,
    const __nv_bfloat16* __restrict__ Ehi,  const __nv_bfloat16* __restrict__ Elo,
    const __nv_bfloat16* __restrict__ Bbhi, const __nv_bfloat16* __restrict__ Bblo,
    const __nv_bfloat16* __restrict__ Chi,  const __nv_bfloat16* __restrict__ Clo,
    const __nv_bfloat16* __restrict__ Dshi, const __nv_bfloat16* __restrict__ Dslo,
    __nv_bfloat16* __restrict__ Zh, __nv_bfloat16* __restrict__ Zl,
    const __nv_bfloat16* __restrict__ Uh, const __nv_bfloat16* __restrict__ Ul)
{
    extern __shared__ __align__(1024) char smem[];
    const int tid  = threadIdx.x;
    const int lane = tid & 31;
    const int w    = tid >> 5;              // 0..7
    const int half = w >> 2;                // 0 or 1
    const int wsub = w & 3;
    const int wm = (wsub & 1) * 32;
    const int wn = (wsub >> 1) * 16;
    const int htid = tid & 127;
    const int barid = 1 + half;
    const int blk = blockIdx.x;
    const bool isZ = blk < 128;

    int m0, n0;
    const __nv_bfloat16 *Bh_g, *Bl_g, *B2h_g, *B2l_g;
    if (isZ) {
        m0 = (blk >> 4) * 64; n0 = (blk & 15) * 32;
        Bh_g = Ehi; Bl_g = Elo; B2h_g = Bbhi; B2l_g = Bblo;
    } else {
        int local = blk - 128;
        m0 = (local >> 1) * 64; n0 = (local & 1) * 32;
        Bh_g = Chi; Bl_g = Clo; B2h_g = Dshi; B2l_g = Dslo;
    }

    const uint32_t sb = smem_u32(smem);

    // resident B operand (256 threads)
    #pragma unroll
    for (int i = 0; i < 8; i++) {
        int idx = i*256 + tid;
        int r = idx >> 6, g = idx & 63;
        uint32_t soff = (uint32_t)((g >> 3)*4096) + SWZ((uint32_t)(r*128 + (g & 7)*16));
        *(uint4*)(smem + SM_BH + soff) = *(const uint4*)(Bh_g + (size_t)(n0 + r)*DD + g*8);
        *(uint4*)(smem + SM_BL + soff) = *(const uint4*)(Bl_g + (size_t)(n0 + r)*DD + g*8);
    }
    {
        int r = tid >> 3, g = tid & 7;
        uint32_t soff = SWZ((uint32_t)(r*128 + g*16));
        *(uint4*)(smem + SM_B2H + soff) = *(const uint4*)(B2h_g + (size_t)(n0 + r)*64 + g*8);
        *(uint4*)(smem + SM_B2L + soff) = *(const uint4*)(B2l_g + (size_t)(n0 + r)*64 + g*8);
    }
    __syncthreads();

    const uint32_t aoff0 = (uint32_t)((wm + 0  + (lane & 15))*128 + ((lane >> 4) << 4));
    const uint32_t aoff1 = (uint32_t)((wm + 16 + (lane & 15))*128 + ((lane >> 4) << 4));
    const uint32_t boff  = (uint32_t)((wn + (lane & 7) + ((lane >> 4) & 1)*8)*128 + ((lane >> 3) & 1)*16);
    const int ldr = htid >> 3;
    const int ldg = htid & 7;
    const uint32_t ringb = SM_ZR + (uint32_t)half*32768u;   // this half's 2-slot ring
    const int gs0 = half*4;                                  // first global slab

    for (int t = 0; t <= TT; t++) {
        const bool active = isZ ? (t < TT) : (t >= 1);
        float acc[2][2][4];
        if (active) {
            #pragma unroll
            for (int a = 0; a < 2; a++)
                #pragma unroll
                for (int b = 0; b < 2; b++)
                    #pragma unroll
                    for (int c = 0; c < 4; c++) acc[a][b][c] = 0.f;

            // ---- u phase: half 0 only (Z-independent) ----
            if (half == 0) {
                int tu = isZ ? t : (t-1);
                const __nv_bfloat16* uh = Uh + (size_t)tu*BB*64;
                const __nv_bfloat16* ul = Ul + (size_t)tu*BB*64;
                #pragma unroll
                for (int i = 0; i < 4; i++) {
                    int r = i*16 + ldr;
                    uint32_t off = SWZ((uint32_t)(r*128 + ldg*16));
                    *(uint4*)(smem + ringb + off)         = *(const uint4*)(uh + (size_t)(m0 + r)*64 + ldg*8);
                    *(uint4*)(smem + ringb + 8192u + off) = *(const uint4*)(ul + (size_t)(m0 + r)*64 + ldg*8);
                }
                BARH(barid);
                uint32_t slot0 = sb + ringb;
                uint32_t bb = sb + SM_B2H;
                #pragma unroll
                for (int k16 = 0; k16 < 4; k16++) {
                    uint32_t ah0[4], al0[4], ah1[4], al1[4], bh[4], bl[4];
                    uint32_t ad0 = slot0 + SWZ(aoff0 + (uint32_t)k16*32);
                    ldmx4(ah0, ad0); ldmx4(al0, ad0 + 8192u);
                    uint32_t ad1 = slot0 + SWZ(aoff1 + (uint32_t)k16*32);
                    ldmx4(ah1, ad1); ldmx4(al1, ad1 + 8192u);
                    uint32_t bd = bb + SWZ(boff + (uint32_t)k16*32);
                    ldmx4(bh, bd); ldmx4(bl, bd + 4096u);
                    MMA_TRIPLE(acc, ah, al, bh, bl)
                }
            }
        }
        if (t > 0) gb_wait((unsigned)NCTA * (unsigned)t);

        if (active) {
            const __nv_bfloat16* zh = Zh + (size_t)(t & 1)*BB*DD;
            const __nv_bfloat16* zl = Zl + (size_t)(t & 1)*BB*DD;
            uint4 ph[4], pl[4];
            // prologue: load local slab 0 (global gs0), store -> slot1
            #pragma unroll
            for (int i = 0; i < 4; i++) {
                int r = i*16 + ldr;
                ph[i] = *(const uint4*)(zh + (size_t)(m0 + r)*DD + gs0*64 + ldg*8);
                pl[i] = *(const uint4*)(zl + (size_t)(m0 + r)*DD + gs0*64 + ldg*8);
            }
            {
                uint32_t zboff = ringb + 16384u;
                #pragma unroll
                for (int i = 0; i < 4; i++) {
                    int r = i*16 + ldr;
                    uint32_t off = SWZ((uint32_t)(r*128 + ldg*16));
                    *(uint4*)(smem + zboff + off) = ph[i];
                    *(uint4*)(smem + zboff + 8192u + off) = pl[i];
                }
            }
            BARH(barid);

            for (int s = 0; s < 4; s++) {
                int gs = gs0 + s;
                if (s + 1 < 4) {
                    #pragma unroll
                    for (int i = 0; i < 4; i++) {
                        int r = i*16 + ldr;
                        ph[i] = *(const uint4*)(zh + (size_t)(m0 + r)*DD + (gs+1)*64 + ldg*8);
                        pl[i] = *(const uint4*)(zl + (size_t)(m0 + r)*DD + (gs+1)*64 + ldg*8);
                    }
                }
                {
                    uint32_t zb = sb + ringb + (uint32_t)((s+1) & 1)*16384u;
                    uint32_t bb = sb + SM_BH + (uint32_t)gs*4096u;
                    #pragma unroll
                    for (int k16 = 0; k16 < 4; k16++) {
                        uint32_t ah0[4], al0[4], ah1[4], al1[4], bh[4], bl[4];
                        uint32_t ad0 = zb + SWZ(aoff0 + (uint32_t)k16*32);
                        ldmx4(ah0, ad0); ldmx4(al0, ad0 + 8192u);
                        uint32_t ad1 = zb + SWZ(aoff1 + (uint32_t)k16*32);
                        ldmx4(ah1, ad1); ldmx4(al1, ad1 + 8192u);
                        uint32_t bd = bb + SWZ(boff + (uint32_t)k16*32);
                        ldmx4(bh, bd); ldmx4(bl, bd + 32768u);
                        MMA_TRIPLE(acc, ah, al, bh, bl)
                    }
                }
                BARH(barid);
                if (s + 1 < 4) {
                    uint32_t zboff = ringb + (uint32_t)(s & 1)*16384u;
                    #pragma unroll
                    for (int i = 0; i < 4; i++) {
                        int r = i*16 + ldr;
                        uint32_t off = SWZ((uint32_t)(r*128 + ldg*16));
                        *(uint4*)(smem + zboff + off) = ph[i];
                        *(uint4*)(smem + zboff + 8192u + off) = pl[i];
                    }
                    BARH(barid);
                }
            }

            // ---- cross-half reduction: half1 -> smem -> half0 adds ----
            __syncthreads();
            if (half == 1) {
                uint32_t ra = sb + SM_RED + (uint32_t)htid*64u;
                #pragma unroll
                for (int mi = 0; mi < 2; mi++)
                    #pragma unroll
                    for (int ni = 0; ni < 2; ni++) {
                        float4 v = make_float4(acc[mi][ni][0], acc[mi][ni][1],
                                               acc[mi][ni][2], acc[mi][ni][3]);
                        asm volatile("st.shared.v4.b32 [%0], {%1,%2,%3,%4};"
                            :: "r"(ra + (uint32_t)(mi*2+ni)*16u),
                               "r"(__float_as_uint(v.x)), "r"(__float_as_uint(v.y)),
                               "r"(__float_as_uint(v.z)), "r"(__float_as_uint(v.w)) : "memory");
                    }
            }
            __syncthreads();
            if (half == 0) {
                const float* red = (const float*)(smem + SM_RED) + htid*16;
                #pragma unroll
                for (int mi = 0; mi < 2; mi++)
                    #pragma unroll
                    for (int ni = 0; ni < 2; ni++)
                        #pragma unroll
                        for (int c = 0; c < 4; c++)
                            acc[mi][ni][c] += red[(mi*2+ni)*4 + c];

                int r0 = m0 + wm + (lane >> 2);
                int c0 = n0 + wn + (lane & 3)*2;
                if (isZ) {
                    float* Zout = Zo + (size_t)t*BB*DD;
                    __nv_bfloat16* zhn = Zh + (size_t)((t+1) & 1)*BB*DD;
                    __nv_bfloat16* zln = Zl + (size_t)((t+1) & 1)*BB*DD;
                    #pragma unroll
                    for (int mi = 0; mi < 2; mi++)
                        #pragma unroll
                        for (int ni = 0; ni < 2; ni++) {
                            int row = r0 + mi*16, col = c0 + ni*8;
                            float a0 = acc[mi][ni][0], a1 = acc[mi][ni][1];
                            float a2 = acc[mi][ni][2], a3 = acc[mi][ni][3];
                            *(float2*)(Zout + (size_t)row*DD + col)     = make_float2(a0, a1);
                            *(float2*)(Zout + (size_t)(row+8)*DD + col) = make_float2(a2, a3);
                            __nv_bfloat162 h0 = __floats2bfloat162_rn(a0, a1);
                            __nv_bfloat162 l0 = __floats2bfloat162_rn(a0 - __bfloat162float(h0.x),
                                                                      a1 - __bfloat162float(h0.y));
                            __nv_bfloat162 h1 = __floats2bfloat162_rn(a2, a3);
                            __nv_bfloat162 l1 = __floats2bfloat162_rn(a2 - __bfloat162float(h1.x),
                                                                      a3 - __bfloat162float(h1.y));
                            *(__nv_bfloat162*)(zhn + (size_t)row*DD + col)     = h0;
                            *(__nv_bfloat162*)(zln + (size_t)row*DD + col)     = l0;
                            *(__nv_bfloat162*)(zhn + (size_t)(row+8)*DD + col) = h1;
                            *(__nv_bfloat162*)(zln + (size_t)(row+8)*DD + col) = l1;
                        }
                } else {
                    float* Yout = Yo + (size_t)(t-1)*BB*NOBS;
                    #pragma unroll
                    for (int mi = 0; mi < 2; mi++)
                        #pragma unroll
                        for (int ni = 0; ni < 2; ni++) {
                            int row = r0 + mi*16, col = c0 + ni*8;
                            if (col < NOBS)     Yout[(size_t)row*NOBS + col]       = acc[mi][ni][0];
                            if (col + 1 < NOBS) Yout[(size_t)row*NOBS + col + 1]   = acc[mi][ni][1];
                            if (col < NOBS)     Yout[(size_t)(row+8)*NOBS + col]   = acc[mi][ni][2];
                            if (col + 1 < NOBS) Yout[(size_t)(row+8)*NOBS + col+1] = acc[mi][ni][3];
                        }
                }
            }
        }
        if (t < TT) gb_arrive(blk);
    }
}

// ---------------- host orchestration ----------------
extern "C" void kernel_launch(void* const* d_in, const int* in_sizes, int n_in,
                              void* d_out, int out_size)
{
    const float* z_dyn = (const float*)d_in[0];
    const float* dtp   = (const float*)d_in[2];
    const float* U     = (const float*)d_in[3];
    const float* skew  = (const float*)d_in[4];
    const float* gamma = (const float*)d_in[5];
    const float* B_ct  = (const float*)d_in[6];
    const float* Cm    = (const float*)d_in[7];
    const float* Dm    = (const float*)d_in[8];

    float *Y_, *E_, *P_, *T_, *T2_, *Bb_;
    cudaGetSymbolAddress((void**)&Y_,  g_Y);
    cudaGetSymbolAddress((void**)&E_,  g_E);
    cudaGetSymbolAddress((void**)&P_,  g_P);
    cudaGetSymbolAddress((void**)&T_,  g_T);
    cudaGetSymbolAddress((void**)&T2_, g_T2);
    cudaGetSymbolAddress((void**)&Bb_, g_Bb);

    __nv_bfloat16 *Yht, *Ylt, *Eht, *Elt, *Pht, *Plt, *Pht2, *Plt2;
    __nv_bfloat16 *Ehi, *Elo, *Chi, *Clo, *Bbhi, *Bblo, *Dshi, *Dslo, *Zh, *Zl, *Uh, *Ul;
    cudaGetSymbolAddress((void**)&Yht,  g_Yht);
    cudaGetSymbolAddress((void**)&Ylt,  g_Ylt);
    cudaGetSymbolAddress((void**)&Eht,  g_Eht);
    cudaGetSymbolAddress((void**)&Elt,  g_Elt);
    cudaGetSymbolAddress((void**)&Pht,  g_Pht);
    cudaGetSymbolAddress((void**)&Plt,  g_Plt);
    cudaGetSymbolAddress((void**)&Pht2, g_Pht2);
    cudaGetSymbolAddress((void**)&Plt2, g_Plt2);
    cudaGetSymbolAddress((void**)&Ehi,  g_Ehi);
    cudaGetSymbolAddress((void**)&Elo,  g_Elo);
    cudaGetSymbolAddress((void**)&Chi,  g_Chi);
    cudaGetSymbolAddress((void**)&Clo,  g_Clo);
    cudaGetSymbolAddress((void**)&Bbhi, g_Bbhi);
    cudaGetSymbolAddress((void**)&Bblo, g_Bblo);
    cudaGetSymbolAddress((void**)&Dshi, g_Dshi);
    cudaGetSymbolAddress((void**)&Dslo, g_Dslo);
    cudaGetSymbolAddress((void**)&Zh,   g_Zh);
    cudaGetSymbolAddress((void**)&Zl,   g_Zl);
    cudaGetSymbolAddress((void**)&Uh,   g_Uh);
    cudaGetSymbolAddress((void**)&Ul,   g_Ul);

    cudaFuncSetAttribute(scan_persist, cudaFuncAttributeMaxDynamicSharedMemorySize, SM_TOT);
    cudaFuncSetAttribute(gemm_tc, cudaFuncAttributeMaxDynamicSharedMemorySize, TC_TOT);

    const int n2 = DD*DD;
    const int g2 = (n2 + 255)/256;
    dim3 gg1(16, 8, 1), gg2(16, 8, 2);

    build_Y_kernel<<<g2, 256>>>(skew, gamma, dtp, Y_);
    init_EPT<<<g2, 256>>>(E_, P_, T_);
    split_T<<<g2, 256>>>(Y_, Yht, Ylt);

    float* Tin = T_; float* Tout = T2_;
    for (int k = 1; k <= NTAYLOR; k++) {
        gemm_tc<<<gg1, 128, TC_TOT>>>(Tin, Yht, Ylt, Yht, Ylt,
                                      Tout, Tout, E_, P_, nullptr,
                                      nullptr, nullptr, nullptr, nullptr,
                                      1.0f/(float)k, 1.0f/(float)(k+1), 1);
        float* tmp = Tin; Tin = Tout; Tout = tmp;
    }
    split_T<<<g2, 256>>>(E_, Eht, Elt);
    split_T<<<g2, 256>>>(P_, Pht, Plt);

    gemm_tc<<<gg2, 128, TC_TOT>>>(E_, Pht, Plt, Eht, Elt,
                                  T2_, T_, nullptr, nullptr, P_,
                                  Pht2, Plt2, Yht, Ylt, 0.f, 0.f, 2);
    gemm_tc<<<gg2, 128, TC_TOT>>>(T_, Pht2, Plt2, Yht, Ylt,
                                  P_, E_, nullptr, nullptr, T2_,
                                  nullptr, nullptr, nullptr, nullptr, 0.f, 0.f, 3);

    gemm_small<<<16, 256>>>(Bb_, P_, B_ct);

    split_mat<<<g2, 256>>>(E_, Ehi, Elo, DD, DD, DD, DD, dtp, 0);
    split_mat<<<(64*DD + 255)/256, 256>>>(Cm, Chi, Clo, NOBS, DD, 64, DD, dtp, 0);
    split_mat<<<(DD*64 + 255)/256, 256>>>(Bb_, Bbhi, Bblo, DD, UDIM, DD, 64, dtp, 1);
    split_mat<<<(64*64 + 255)/256, 256>>>(Dm, Dshi, Dslo, NOBS, UDIM, 64, 64, dtp, 1);
    split_mat<<<g2, 256>>>(z_dyn, Zh, Zl, BB, DD, BB, DD, dtp, 0);
    split_mat<<<(TT*BB*64 + 255)/256, 256>>>(U, Uh, Ul, TT*BB, UDIM, TT*BB, 64, dtp, 0);

    reset_barrier<<<1, 32>>>();

    float* Zo = (float*)d_out;
    float* Yo = (float*)d_out + (size_t)TT*BB*DD;
    scan_persist<<<NCTA, 256, SM_TOT>>>(Zo, Yo,
                                        Ehi, Elo, Bbhi, Bblo, Chi, Clo, Dshi, Dslo,
                                        Zh, Zl, Uh, Ul);
}